// round 1
// baseline (speedup 1.0000x reference)
#include <cuda_runtime.h>
#include <math.h>

#define N_P   50000
#define N_HE  5000
#define D_IN  128
#define D_HID 256
#define N_HEADS 4
#define HEAD_DIM 64

// ---- scratch (no allocation allowed) ----
__device__ float g_he_feat[N_HE * D_IN];    // segment_sum result per hyperedge
__device__ float g_he_w[N_HE * D_IN];       // he_feat * he_attn
__device__ float g_cluster[N_P * D_IN];     // second segment_sum result

// ---------------------------------------------------------------------------
// zero scratch accumulators (float4 stores)
// ---------------------------------------------------------------------------
__global__ void zero_kernel() {
    int i = blockIdx.x * blockDim.x + threadIdx.x;
    float4 z = make_float4(0.f, 0.f, 0.f, 0.f);
    if (i < N_HE * D_IN / 4) ((float4*)g_he_feat)[i] = z;
    if (i < N_P * D_IN / 4)  ((float4*)g_cluster)[i] = z;
}

// ---------------------------------------------------------------------------
// pass 1: he_feat[hid] += feat[pid] * ew    (warp per edge, v4 reductions)
// ---------------------------------------------------------------------------
__device__ __forceinline__ void red_add_v4(float* dst, float a, float b, float c, float d) {
    asm volatile("red.global.add.v4.f32 [%0], {%1,%2,%3,%4};"
                 :: "l"(dst), "f"(a), "f"(b), "f"(c), "f"(d) : "memory");
}

__global__ void scatter1_kernel(const float* __restrict__ feat,
                                const float* __restrict__ ew,
                                const int* __restrict__ pid,
                                const int* __restrict__ hid, int nE) {
    int e    = (blockIdx.x * blockDim.x + threadIdx.x) >> 5;
    int lane = threadIdx.x & 31;
    if (e >= nE) return;
    int p = pid[e];
    int h = hid[e];
    float w = ew[e];
    float4 v = reinterpret_cast<const float4*>(feat + (size_t)p * D_IN)[lane];
    red_add_v4(g_he_feat + (size_t)h * D_IN + lane * 4,
               v.x * w, v.y * w, v.z * w, v.w * w);
}

// ---------------------------------------------------------------------------
// attention over hyperedges: one block (256 thr) per hyperedge
//   h = relu(he_feat @ Wh1[head] + bh1); logit = h . Wh2[head] + bh2
//   he_attn = sum_head sigmoid(logit) * Wfuse[head]
//   g_he_w = he_feat * he_attn
// ---------------------------------------------------------------------------
__global__ __launch_bounds__(256) void attn_kernel(
    const float* __restrict__ Wh1, const float* __restrict__ bh1,
    const float* __restrict__ Wh2, const float* __restrict__ bh2,
    const float* __restrict__ Wfuse) {
    __shared__ float s_he[D_IN];
    __shared__ float s_part[8];
    __shared__ float s_attn;

    int n = blockIdx.x;
    int t = threadIdx.x;
    if (t < D_IN) s_he[t] = g_he_feat[(size_t)n * D_IN + t];
    __syncthreads();

    int h = t >> 6;         // head 0..3
    int k = t & 63;         // dim within head
    const float* w = Wh1 + ((size_t)h * D_IN) * HEAD_DIM + k;
    float acc = 0.f;
#pragma unroll 4
    for (int d = 0; d < D_IN; d++) acc += s_he[d] * w[(size_t)d * HEAD_DIM];
    float v = fmaxf(acc + bh1[h * HEAD_DIM + k], 0.f) * Wh2[h * HEAD_DIM + k];
#pragma unroll
    for (int o = 16; o; o >>= 1) v += __shfl_down_sync(0xffffffffu, v, o);
    if ((t & 31) == 0) s_part[t >> 5] = v;
    __syncthreads();
    if (t == 0) {
        float a = 0.f;
        for (int hh = 0; hh < N_HEADS; hh++) {
            float logit = s_part[2 * hh] + s_part[2 * hh + 1] + bh2[hh];
            float sg = 1.f / (1.f + expf(-logit));
            a += sg * Wfuse[hh];
        }
        s_attn = a;
    }
    __syncthreads();
    if (t < D_IN) g_he_w[(size_t)n * D_IN + t] = s_he[t] * s_attn;
}

// ---------------------------------------------------------------------------
// pass 2: cluster[pid] += he_w[hid] * ew
// ---------------------------------------------------------------------------
__global__ void scatter2_kernel(const float* __restrict__ ew,
                                const int* __restrict__ pid,
                                const int* __restrict__ hid, int nE) {
    int e    = (blockIdx.x * blockDim.x + threadIdx.x) >> 5;
    int lane = threadIdx.x & 31;
    if (e >= nE) return;
    int p = pid[e];
    int h = hid[e];
    float w = ew[e];
    float4 v = reinterpret_cast<const float4*>(g_he_w + (size_t)h * D_IN)[lane];
    red_add_v4(g_cluster + (size_t)p * D_IN + lane * 4,
               v.x * w, v.y * w, v.z * w, v.w * w);
}

// ---------------------------------------------------------------------------
// fused per-row MLP: self_f, clu_f, 3-layer gate MLP, softmax fuse, relu
// Block = 256 threads, 16 rows/block. All weights read from L2 (512 KB total,
// reused 16x per load within block).
// ---------------------------------------------------------------------------
#define TM 16
__global__ __launch_bounds__(256) void mlp_kernel(
    const float* __restrict__ feat,
    const float* __restrict__ Wself, const float* __restrict__ bself,
    const float* __restrict__ Wclu,  const float* __restrict__ bclu,
    const float* __restrict__ Wf1,   const float* __restrict__ bf1,
    const float* __restrict__ Wf2,   const float* __restrict__ bf2,
    const float* __restrict__ Wf3,   const float* __restrict__ bf3,
    float* __restrict__ out, int nP) {
    __shared__ float s_feat[TM][D_IN];
    __shared__ float s_self[TM][D_IN];
    __shared__ float s_clu[TM][D_IN];     // holds cluster input, then clu_f
    __shared__ float s_x1[TM][D_HID];     // x1, then x2 in first 128 cols
    __shared__ float s_fw[TM][2];

    int row0 = blockIdx.x * TM;
    int t = threadIdx.x;

    for (int i = t; i < TM * D_IN; i += 256) {
        int r = i >> 7, c = i & 127;
        int gr = row0 + r;
        float f = 0.f, cl = 0.f;
        if (gr < nP) {
            f  = feat[(size_t)gr * D_IN + c];
            cl = g_cluster[(size_t)gr * D_IN + c];
        }
        s_feat[r][c] = f;
        s_clu[r][c]  = cl;
    }
    __syncthreads();

    int j = t & 127;
    int half = t >> 7;

    // ---- stage A: self_f (half 0) / clu_f (half 1), GEMV per column ----
    float acc[TM];
#pragma unroll
    for (int r = 0; r < TM; r++) acc[r] = 0.f;
    {
        const float* W = half ? Wclu : Wself;
        float (*in)[D_IN] = half ? s_clu : s_feat;
#pragma unroll 4
        for (int k = 0; k < D_IN; k++) {
            float w = W[k * D_IN + j];
#pragma unroll
            for (int r = 0; r < TM; r++) acc[r] += in[r][k] * w;
        }
    }
    __syncthreads();
    {
        float b = half ? bclu[j] : bself[j];
        float (*o)[D_IN] = half ? s_clu : s_self;
#pragma unroll
        for (int r = 0; r < TM; r++) o[r][j] = acc[r] + b;
    }
    __syncthreads();

    // ---- stage B: x1 = relu(cat @ Wf1 + bf1), thread t = column t ----
#pragma unroll
    for (int r = 0; r < TM; r++) acc[r] = 0.f;
#pragma unroll 2
    for (int k = 0; k < D_IN; k++) {
        float w = Wf1[k * D_HID + t];
#pragma unroll
        for (int r = 0; r < TM; r++) acc[r] += s_self[r][k] * w;
    }
#pragma unroll 2
    for (int k = 0; k < D_IN; k++) {
        float w = Wf1[(D_IN + k) * D_HID + t];
#pragma unroll
        for (int r = 0; r < TM; r++) acc[r] += s_clu[r][k] * w;
    }
    {
        float b = bf1[t];
#pragma unroll
        for (int r = 0; r < TM; r++) s_x1[r][t] = fmaxf(acc[r] + b, 0.f);
    }
    __syncthreads();

    // ---- stage C: x2 = relu(x1 @ Wf2 + bf2); 128 cols, rows split by half --
    float acc2[TM / 2];
#pragma unroll
    for (int r = 0; r < TM / 2; r++) acc2[r] = 0.f;
    int rbase = half * (TM / 2);
#pragma unroll 2
    for (int k = 0; k < D_HID; k++) {
        float w = Wf2[k * D_IN + j];
#pragma unroll
        for (int r = 0; r < TM / 2; r++) acc2[r] += s_x1[rbase + r][k] * w;
    }
    __syncthreads();   // all reads of s_x1 done before overwrite
    {
        float b = bf2[j];
#pragma unroll
        for (int r = 0; r < TM / 2; r++) s_x1[rbase + r][j] = fmaxf(acc2[r] + b, 0.f);
    }
    __syncthreads();

    // ---- stage D: logits + softmax gates ----
    if (t < 2 * TM) {
        int r = t >> 1, l = t & 1;
        float a = bf3[l];
        for (int k = 0; k < D_IN; k++) a += s_x1[r][k] * Wf3[k * 2 + l];
        s_fw[r][l] = a;
    }
    __syncthreads();
    if (t < TM) {
        float a = s_fw[t][0], b = s_fw[t][1];
        float m = fmaxf(a, b);
        float e0 = expf(a - m), e1 = expf(b - m);
        float inv = 1.f / (e0 + e1);
        s_fw[t][0] = e0 * inv;
        s_fw[t][1] = e1 * inv;
    }
    __syncthreads();

    // ---- stage E: out = relu(self*fw0 + clu*fw1 + feat) ----
    for (int i = t; i < TM * D_IN; i += 256) {
        int r = i >> 7, c = i & 127;
        int gr = row0 + r;
        if (gr < nP) {
            float v = s_self[r][c] * s_fw[r][0] + s_clu[r][c] * s_fw[r][1] + s_feat[r][c];
            out[(size_t)gr * D_IN + c] = fmaxf(v, 0.f);
        }
    }
}

// ---------------------------------------------------------------------------
extern "C" void kernel_launch(void* const* d_in, const int* in_sizes, int n_in,
                              void* d_out, int out_size) {
    const float* feat   = (const float*)d_in[0];
    const float* edge_w = (const float*)d_in[1];
    const float* Wself  = (const float*)d_in[2];
    const float* bself  = (const float*)d_in[3];
    const float* Wclu   = (const float*)d_in[4];
    const float* bclu   = (const float*)d_in[5];
    const float* Wh1    = (const float*)d_in[6];
    const float* bh1    = (const float*)d_in[7];
    const float* Wh2    = (const float*)d_in[8];
    const float* bh2    = (const float*)d_in[9];
    const float* Wfuse  = (const float*)d_in[10];
    const float* Wf1    = (const float*)d_in[11];
    const float* bf1    = (const float*)d_in[12];
    const float* Wf2    = (const float*)d_in[13];
    const float* bf2    = (const float*)d_in[14];
    const float* Wf3    = (const float*)d_in[15];
    const float* bf3    = (const float*)d_in[16];
    const int*   e_pid  = (const int*)d_in[17];
    const int*   e_hid  = (const int*)d_in[18];

    int nE = in_sizes[17];
    int nP = in_sizes[0] / D_IN;
    float* out = (float*)d_out;

    int zeroN = (N_P * D_IN) / 4;   // covers cluster (bigger) and he_feat
    zero_kernel<<<(zeroN + 255) / 256, 256>>>();

    scatter1_kernel<<<(nE * 32 + 255) / 256, 256>>>(feat, edge_w, e_pid, e_hid, nE);

    attn_kernel<<<N_HE, 256>>>(Wh1, bh1, Wh2, bh2, Wfuse);

    scatter2_kernel<<<(nE * 32 + 255) / 256, 256>>>(edge_w, e_pid, e_hid, nE);

    mlp_kernel<<<(nP + TM - 1) / TM, 256>>>(feat, Wself, bself, Wclu, bclu,
                                            Wf1, bf1, Wf2, bf2, Wf3, bf3,
                                            out, nP);
}

// round 3
// speedup vs baseline: 1.4824x; 1.4824x over previous
#include <cuda_runtime.h>
#include <math.h>

#define N_P   50000
#define N_HE  5000
#define D_IN  128
#define D_HID 256
#define N_HEADS 4
#define HEAD_DIM 64

#define PAD128 132   // 132 % 32 == 4 -> conflict-free ldmatrix rows
#define PAD256 260   // 260 % 32 == 4

// ---- scratch (no allocation allowed) ----
__device__ float g_he_feat[N_HE * D_IN];
__device__ float g_he_w[N_HE * D_IN];
__device__ float g_cluster[N_P * D_IN];

// ---------------------------------------------------------------------------
__global__ void zero_kernel() {
    int i = blockIdx.x * blockDim.x + threadIdx.x;
    float4 z = make_float4(0.f, 0.f, 0.f, 0.f);
    if (i < N_HE * D_IN / 4) ((float4*)g_he_feat)[i] = z;
    if (i < N_P * D_IN / 4)  ((float4*)g_cluster)[i] = z;
}

// ---------------------------------------------------------------------------
__device__ __forceinline__ void red_add_v4(float* dst, float a, float b, float c, float d) {
    asm volatile("red.global.add.v4.f32 [%0], {%1,%2,%3,%4};"
                 :: "l"(dst), "f"(a), "f"(b), "f"(c), "f"(d) : "memory");
}

__global__ void scatter1_kernel(const float* __restrict__ feat,
                                const float* __restrict__ ew,
                                const int* __restrict__ pid,
                                const int* __restrict__ hid, int nE) {
    int e    = (blockIdx.x * blockDim.x + threadIdx.x) >> 5;
    int lane = threadIdx.x & 31;
    if (e >= nE) return;
    int p = pid[e];
    int h = hid[e];
    float w = ew[e];
    float4 v = reinterpret_cast<const float4*>(feat + (size_t)p * D_IN)[lane];
    red_add_v4(g_he_feat + (size_t)h * D_IN + lane * 4,
               v.x * w, v.y * w, v.z * w, v.w * w);
}

// ---------------------------------------------------------------------------
__global__ __launch_bounds__(256) void attn_kernel(
    const float* __restrict__ Wh1, const float* __restrict__ bh1,
    const float* __restrict__ Wh2, const float* __restrict__ bh2,
    const float* __restrict__ Wfuse) {
    __shared__ float s_he[D_IN];
    __shared__ float s_part[8];
    __shared__ float s_attn;

    int n = blockIdx.x;
    int t = threadIdx.x;
    if (t < D_IN) s_he[t] = g_he_feat[(size_t)n * D_IN + t];
    __syncthreads();

    int h = t >> 6;
    int k = t & 63;
    const float* w = Wh1 + ((size_t)h * D_IN) * HEAD_DIM + k;
    float acc = 0.f;
#pragma unroll 4
    for (int d = 0; d < D_IN; d++) acc += s_he[d] * w[(size_t)d * HEAD_DIM];
    float v = fmaxf(acc + bh1[h * HEAD_DIM + k], 0.f) * Wh2[h * HEAD_DIM + k];
#pragma unroll
    for (int o = 16; o; o >>= 1) v += __shfl_down_sync(0xffffffffu, v, o);
    if ((t & 31) == 0) s_part[t >> 5] = v;
    __syncthreads();
    if (t == 0) {
        float a = 0.f;
        for (int hh = 0; hh < N_HEADS; hh++) {
            float logit = s_part[2 * hh] + s_part[2 * hh + 1] + bh2[hh];
            float sg = 1.f / (1.f + expf(-logit));
            a += sg * Wfuse[hh];
        }
        s_attn = a;
    }
    __syncthreads();
    if (t < D_IN) g_he_w[(size_t)n * D_IN + t] = s_he[t] * s_attn;
}

// ---------------------------------------------------------------------------
__global__ void scatter2_kernel(const float* __restrict__ ew,
                                const int* __restrict__ pid,
                                const int* __restrict__ hid, int nE) {
    int e    = (blockIdx.x * blockDim.x + threadIdx.x) >> 5;
    int lane = threadIdx.x & 31;
    if (e >= nE) return;
    int p = pid[e];
    int h = hid[e];
    float w = ew[e];
    float4 v = reinterpret_cast<const float4*>(g_he_w + (size_t)h * D_IN)[lane];
    red_add_v4(g_cluster + (size_t)p * D_IN + lane * 4,
               v.x * w, v.y * w, v.z * w, v.w * w);
}

// ---------------------------------------------------------------------------
// 3xTF32 tensor-core fused MLP. 64 rows per block, 256 threads = 8 warps.
// Each operand is split exactly: hi = bits & 0xFFFFE000 (tf32-exact),
// lo = x - hi. acc += a_hi*b_hi + a_lo*b_hi + a_hi*b_lo  ->  ~fp32 accuracy.
// ---------------------------------------------------------------------------
__device__ __forceinline__ void mma_tf32(float (&c)[4], const unsigned (&a)[4],
                                         unsigned b0, unsigned b1) {
    asm volatile(
        "mma.sync.aligned.m16n8k8.row.col.f32.tf32.tf32.f32 "
        "{%0,%1,%2,%3},{%4,%5,%6,%7},{%8,%9},{%0,%1,%2,%3};\n"
        : "+f"(c[0]), "+f"(c[1]), "+f"(c[2]), "+f"(c[3])
        : "r"(a[0]), "r"(a[1]), "r"(a[2]), "r"(a[3]), "r"(b0), "r"(b1));
}

#define LDSM4(R, ADDR) \
    asm volatile("ldmatrix.sync.aligned.m8n8.x4.shared.b16 {%0,%1,%2,%3},[%4];" \
                 : "=r"((R)[0]), "=r"((R)[1]), "=r"((R)[2]), "=r"((R)[3]) : "r"(ADDR))

__device__ __forceinline__ unsigned smem_u32(const void* p) {
    return (unsigned)__cvta_generic_to_shared(p);
}

__device__ __forceinline__ void split_bits(unsigned x, unsigned& hi, unsigned& lo) {
    hi = x & 0xffffe000u;
    lo = __float_as_uint(__uint_as_float(x) - __uint_as_float(hi));
}

// KT k-tiles (K = KT*8), NT n-tiles of 8 cols (warp covers NT*8 cols)
template <int KT, int NT>
__device__ __forceinline__ void gemm_stage(const unsigned (&aAddr)[4],
                                           const float* __restrict__ Wp, int N,
                                           float (&acc)[4][NT][4]) {
    unsigned a0[4][4];
    unsigned bb0[NT][2];
#pragma unroll
    for (int mt = 0; mt < 4; mt++) LDSM4(a0[mt], aAddr[mt]);
#pragma unroll
    for (int nt = 0; nt < NT; nt++) {
        bb0[nt][0] = __float_as_uint(__ldg(Wp + nt * 8));
        bb0[nt][1] = __float_as_uint(__ldg(Wp + 4 * N + nt * 8));
    }
#pragma unroll
    for (int kt = 0; kt < KT; kt++) {
        unsigned a1[4][4];
        unsigned bb1[NT][2];
        if (kt + 1 < KT) {
#pragma unroll
            for (int mt = 0; mt < 4; mt++) LDSM4(a1[mt], aAddr[mt] + (kt + 1) * 32u);
            const float* Wk = Wp + (size_t)(kt + 1) * 8 * N;
#pragma unroll
            for (int nt = 0; nt < NT; nt++) {
                bb1[nt][0] = __float_as_uint(__ldg(Wk + nt * 8));
                bb1[nt][1] = __float_as_uint(__ldg(Wk + 4 * N + nt * 8));
            }
        }
        // exact splits: a0 becomes a_hi in place, alo holds the residual
        unsigned alo[4][4];
#pragma unroll
        for (int mt = 0; mt < 4; mt++)
#pragma unroll
            for (int i = 0; i < 4; i++) split_bits(a0[mt][i], a0[mt][i], alo[mt][i]);
        unsigned blo[NT][2];
#pragma unroll
        for (int nt = 0; nt < NT; nt++) {
            split_bits(bb0[nt][0], bb0[nt][0], blo[nt][0]);
            split_bits(bb0[nt][1], bb0[nt][1], blo[nt][1]);
        }
        // correction terms first, dominant term last
#pragma unroll
        for (int nt = 0; nt < NT; nt++)
#pragma unroll
            for (int mt = 0; mt < 4; mt++) {
                mma_tf32(acc[mt][nt], alo[mt], bb0[nt][0], bb0[nt][1]);
                mma_tf32(acc[mt][nt], a0[mt],  blo[nt][0], blo[nt][1]);
                mma_tf32(acc[mt][nt], a0[mt],  bb0[nt][0], bb0[nt][1]);
            }
#pragma unroll
        for (int mt = 0; mt < 4; mt++)
#pragma unroll
            for (int i = 0; i < 4; i++) a0[mt][i] = a1[mt][i];
#pragma unroll
        for (int nt = 0; nt < NT; nt++) {
            bb0[nt][0] = bb1[nt][0];
            bb0[nt][1] = bb1[nt][1];
        }
    }
}

// write accumulators (+bias, optional relu) to smem dst
template <int NT, bool RELU>
__device__ __forceinline__ void epilogue(float* dst, int dstride, int col0,
                                         const float* __restrict__ bias,
                                         float (&acc)[4][NT][4], int lane) {
    int gid = lane >> 2, tig = lane & 3;
#pragma unroll
    for (int nt = 0; nt < NT; nt++) {
        int c = nt * 8 + tig * 2;
        float bA = __ldg(bias + c), bB = __ldg(bias + c + 1);
#pragma unroll
        for (int mt = 0; mt < 4; mt++) {
            int r = mt * 16 + gid;
            float v0 = acc[mt][nt][0] + bA, v1 = acc[mt][nt][1] + bB;
            float v2 = acc[mt][nt][2] + bA, v3 = acc[mt][nt][3] + bB;
            if (RELU) {
                v0 = fmaxf(v0, 0.f); v1 = fmaxf(v1, 0.f);
                v2 = fmaxf(v2, 0.f); v3 = fmaxf(v3, 0.f);
            }
            dst[(size_t)r * dstride + col0 + c]           = v0;
            dst[(size_t)r * dstride + col0 + c + 1]       = v1;
            dst[(size_t)(r + 8) * dstride + col0 + c]     = v2;
            dst[(size_t)(r + 8) * dstride + col0 + c + 1] = v3;
        }
    }
}

__global__ __launch_bounds__(256, 1) void mlp2_kernel(
    const float* __restrict__ feat,
    const float* __restrict__ Wself, const float* __restrict__ bself,
    const float* __restrict__ Wclu,  const float* __restrict__ bclu,
    const float* __restrict__ Wf1,   const float* __restrict__ bf1,
    const float* __restrict__ Wf2,   const float* __restrict__ bf2,
    const float* __restrict__ Wf3,   const float* __restrict__ bf3,
    float* __restrict__ out, int nP) {
    extern __shared__ float sm[];
    float* s_feat = sm;                            // 64 x PAD128 (later: x2)
    float* s_cat  = s_feat + 64 * PAD128;          // 64 x PAD256 (self|clu)
    float* s_u1   = s_cat + 64 * PAD256;           // 64 x PAD256 (cluin, later x1)
    float (*s_gate)[2] = (float (*)[2])(s_u1 + 64 * PAD256);

    int row0 = blockIdx.x * 64;
    int t = threadIdx.x;
    int wid = t >> 5, lane = t & 31;

    // ---- load feat + cluster tiles (float4 coalesced) ----
    const float4* feat4 = (const float4*)feat;
    const float4* clu4  = (const float4*)g_cluster;
    for (int i = t; i < 64 * 32; i += 256) {
        int r = i >> 5, c4 = i & 31;
        int gr = row0 + r;
        float4 f = make_float4(0.f, 0.f, 0.f, 0.f), cl = f;
        if (gr < nP) {
            f  = feat4[(size_t)gr * 32 + c4];
            cl = clu4[(size_t)gr * 32 + c4];
        }
        *(float4*)&s_feat[(size_t)r * PAD128 + c4 * 4] = f;
        *(float4*)&s_u1[(size_t)r * PAD256 + c4 * 4]   = cl;
    }
    __syncthreads();

    // ---- ldmatrix base addresses for this lane ----
    int m8  = lane >> 3;           // which 8x8 b16 matrix (0..3)
    int rIn = lane & 7;
    int rowoff = (m8 & 1) * 8 + rIn;
    int coloff = (m8 >> 1) * 4;

    int gid = lane >> 2, tig = lane & 3;

    // ================= stage A: self_f | clu_f ===================
    {
        float acc[4][4][4];
#pragma unroll
        for (int a = 0; a < 4; a++)
#pragma unroll
            for (int b = 0; b < 4; b++)
#pragma unroll
                for (int c = 0; c < 4; c++) acc[a][b][c] = 0.f;

        const float* aBuf   = (wid < 4) ? s_feat : s_u1;
        int          aStr   = (wid < 4) ? PAD128 : PAD256;
        const float* W      = (wid < 4) ? Wself : Wclu;
        const float* bias   = (wid < 4) ? bself : bclu;
        int ncol0           = (wid & 3) * 32;
        int outcol0         = (wid < 4) ? ncol0 : (128 + ncol0);

        unsigned aAddr[4];
#pragma unroll
        for (int mt = 0; mt < 4; mt++)
            aAddr[mt] = smem_u32(aBuf + (size_t)(mt * 16 + rowoff) * aStr + coloff);

        const float* Wp = W + (size_t)tig * 128 + ncol0 + gid;
        gemm_stage<16, 4>(aAddr, Wp, 128, acc);
        __syncthreads();
        epilogue<4, false>(s_cat, PAD256, outcol0, bias + ncol0, acc, lane);
    }
    __syncthreads();

    // ================= stage B: x1 = relu(cat @ Wf1 + bf1) =======
    {
        float acc[4][4][4];
#pragma unroll
        for (int a = 0; a < 4; a++)
#pragma unroll
            for (int b = 0; b < 4; b++)
#pragma unroll
                for (int c = 0; c < 4; c++) acc[a][b][c] = 0.f;

        int ncol0 = wid * 32;
        unsigned aAddr[4];
#pragma unroll
        for (int mt = 0; mt < 4; mt++)
            aAddr[mt] = smem_u32(s_cat + (size_t)(mt * 16 + rowoff) * PAD256 + coloff);
        const float* Wp = Wf1 + (size_t)tig * 256 + ncol0 + gid;
        gemm_stage<32, 4>(aAddr, Wp, 256, acc);
        __syncthreads();   // all reads of s_u1 (cluin) finished in stage A
        epilogue<4, true>(s_u1, PAD256, ncol0, bf1 + ncol0, acc, lane);
    }
    __syncthreads();

    // ================= stage C: x2 = relu(x1 @ Wf2 + bf2) ========
    {
        float acc[4][2][4];
#pragma unroll
        for (int a = 0; a < 4; a++)
#pragma unroll
            for (int b = 0; b < 2; b++)
#pragma unroll
                for (int c = 0; c < 4; c++) acc[a][b][c] = 0.f;

        int ncol0 = wid * 16;
        unsigned aAddr[4];
#pragma unroll
        for (int mt = 0; mt < 4; mt++)
            aAddr[mt] = smem_u32(s_u1 + (size_t)(mt * 16 + rowoff) * PAD256 + coloff);
        const float* Wp = Wf2 + (size_t)tig * 128 + ncol0 + gid;
        gemm_stage<32, 2>(aAddr, Wp, 128, acc);
        __syncthreads();   // stage A reads of s_feat done; safe to overwrite
        epilogue<2, true>(s_feat, PAD128, ncol0, bf2 + ncol0, acc, lane);
    }
    __syncthreads();

    // ================= stage D: gates = softmax(x2 @ Wf3 + bf3) ==
    if (t < 64) {
        float a0 = __ldg(bf3 + 0), a1 = __ldg(bf3 + 1);
        const float* x = s_feat + (size_t)t * PAD128;
#pragma unroll 4
        for (int k = 0; k < 128; k++) {
            float xv = x[k];
            a0 += xv * __ldg(Wf3 + 2 * k);
            a1 += xv * __ldg(Wf3 + 2 * k + 1);
        }
        float m = fmaxf(a0, a1);
        float e0 = expf(a0 - m), e1 = expf(a1 - m);
        float inv = 1.f / (e0 + e1);
        s_gate[t][0] = e0 * inv;
        s_gate[t][1] = e1 * inv;
    }
    __syncthreads();

    // ================= stage E: out = relu(self*g0 + clu*g1 + feat)
    for (int i = t; i < 64 * 32; i += 256) {
        int r = i >> 5, c4 = i & 31;
        int gr = row0 + r;
        if (gr < nP) {
            float4 f = feat4[(size_t)gr * 32 + c4];
            float g0 = s_gate[r][0], g1 = s_gate[r][1];
            const float* sf = s_cat + (size_t)r * PAD256 + c4 * 4;
            const float* sc = sf + 128;
            float4 o;
            o.x = fmaxf(sf[0] * g0 + sc[0] * g1 + f.x, 0.f);
            o.y = fmaxf(sf[1] * g0 + sc[1] * g1 + f.y, 0.f);
            o.z = fmaxf(sf[2] * g0 + sc[2] * g1 + f.z, 0.f);
            o.w = fmaxf(sf[3] * g0 + sc[3] * g1 + f.w, 0.f);
            ((float4*)out)[(size_t)gr * 32 + c4] = o;
        }
    }
}

// ---------------------------------------------------------------------------
extern "C" void kernel_launch(void* const* d_in, const int* in_sizes, int n_in,
                              void* d_out, int out_size) {
    const float* feat   = (const float*)d_in[0];
    const float* edge_w = (const float*)d_in[1];
    const float* Wself  = (const float*)d_in[2];
    const float* bself  = (const float*)d_in[3];
    const float* Wclu   = (const float*)d_in[4];
    const float* bclu   = (const float*)d_in[5];
    const float* Wh1    = (const float*)d_in[6];
    const float* bh1    = (const float*)d_in[7];
    const float* Wh2    = (const float*)d_in[8];
    const float* bh2    = (const float*)d_in[9];
    const float* Wfuse  = (const float*)d_in[10];
    const float* Wf1    = (const float*)d_in[11];
    const float* bf1    = (const float*)d_in[12];
    const float* Wf2    = (const float*)d_in[13];
    const float* bf2    = (const float*)d_in[14];
    const float* Wf3    = (const float*)d_in[15];
    const float* bf3    = (const float*)d_in[16];
    const int*   e_pid  = (const int*)d_in[17];
    const int*   e_hid  = (const int*)d_in[18];

    int nE = in_sizes[17];
    int nP = in_sizes[0] / D_IN;
    float* out = (float*)d_out;

    int zeroN = (N_P * D_IN) / 4;
    zero_kernel<<<(zeroN + 255) / 256, 256>>>();

    scatter1_kernel<<<(nE * 32 + 255) / 256, 256>>>(feat, edge_w, e_pid, e_hid, nE);

    attn_kernel<<<N_HE, 256>>>(Wh1, bh1, Wh2, bh2, Wfuse);

    scatter2_kernel<<<(nE * 32 + 255) / 256, 256>>>(edge_w, e_pid, e_hid, nE);

    size_t smemBytes = (size_t)(64 * PAD128 + 2 * 64 * PAD256) * 4 + 64 * 2 * 4;
    cudaFuncSetAttribute(mlp2_kernel, cudaFuncAttributeMaxDynamicSharedMemorySize,
                         (int)smemBytes);
    int nBlocks = (nP + 63) / 64;
    mlp2_kernel<<<nBlocks, 256, smemBytes>>>(feat, Wself, bself, Wclu, bclu,
                                             Wf1, bf1, Wf2, bf2, Wf3, bf3,
                                             out, nP);
}

// round 4
// speedup vs baseline: 1.6379x; 1.1049x over previous
#include <cuda_runtime.h>
#include <math.h>

#define N_P   50000
#define N_HE  5000
#define D_IN  128
#define D_HID 256
#define N_HEADS 4
#define HEAD_DIM 64

#define HE_CAP 256
#define P_CAP  64
#define OVF_CAP 65536

#define PAD128 132
#define PAD256 260

// ---- scratch (no allocation allowed) ----
__device__ float g_he_feat[N_HE * D_IN];
__device__ float g_he_w[N_HE * D_IN];
__device__ float g_cluster[N_P * D_IN];
__device__ int   g_cnt_he[N_HE];
__device__ int   g_cnt_p[N_P];
__device__ float2 g_list_he[N_HE * HE_CAP];   // (pid bits, w) per hyperedge
__device__ float2 g_list_p[N_P * P_CAP];      // (hid bits, w) per protein
__device__ float4 g_ovf[OVF_CAP];             // (pid, hid, w, -) overflow
__device__ int   g_novf;

// ---------------------------------------------------------------------------
__device__ __forceinline__ void red_add_v4(float* dst, float a, float b, float c, float d) {
    asm volatile("red.global.add.v4.f32 [%0], {%1,%2,%3,%4};"
                 :: "l"(dst), "f"(a), "f"(b), "f"(c), "f"(d) : "memory");
}

// ---------------------------------------------------------------------------
// zero: cluster + he_feat (fallback bases), counters, overflow count
// ---------------------------------------------------------------------------
__global__ void zero_kernel() {
    int i = blockIdx.x * blockDim.x + threadIdx.x;
    float4 z = make_float4(0.f, 0.f, 0.f, 0.f);
    if (i < N_P * (D_IN / 4))  ((float4*)g_cluster)[i] = z;
    if (i < N_HE * (D_IN / 4)) ((float4*)g_he_feat)[i] = z;
    if (i < N_HE)              g_cnt_he[i] = 0;
    if (i < N_P)               g_cnt_p[i] = 0;
    if (i == 0)                g_novf = 0;
}

// ---------------------------------------------------------------------------
// fill: bucket every edge into he-list and p-list (atomic tickets)
// ---------------------------------------------------------------------------
__global__ void fill_kernel(const float* __restrict__ ew,
                            const int* __restrict__ pid,
                            const int* __restrict__ hid,
                            const float* __restrict__ feat, int nE) {
    int e = blockIdx.x * blockDim.x + threadIdx.x;
    if (e >= nE) return;
    int p = pid[e];
    int h = hid[e];
    float w = ew[e];

    int pos = atomicAdd(&g_cnt_he[h], 1);
    if (pos < HE_CAP) {
        g_list_he[(size_t)h * HE_CAP + pos] = make_float2(__int_as_float(p), w);
    } else {
        // rare fallback: direct reduction into he_feat base
        const float4* fr = (const float4*)(feat + (size_t)p * D_IN);
        for (int i = 0; i < D_IN / 4; i++) {
            float4 v = fr[i];
            red_add_v4(g_he_feat + (size_t)h * D_IN + i * 4,
                       v.x * w, v.y * w, v.z * w, v.w * w);
        }
    }

    int pos2 = atomicAdd(&g_cnt_p[p], 1);
    if (pos2 < P_CAP) {
        g_list_p[(size_t)p * P_CAP + pos2] = make_float2(__int_as_float(h), w);
    } else {
        int o = atomicAdd(&g_novf, 1);
        if (o < OVF_CAP)
            g_ovf[o] = make_float4(__int_as_float(p), __int_as_float(h), w, 0.f);
    }
}

// ---------------------------------------------------------------------------
// he_acc: block per hyperedge, 128 threads = one he_feat row in registers
// ---------------------------------------------------------------------------
__global__ __launch_bounds__(128) void he_acc_kernel(const float* __restrict__ feat) {
    __shared__ float2 s_list[HE_CAP];
    int b = blockIdx.x, t = threadIdx.x;
    int n = g_cnt_he[b];
    if (n > HE_CAP) n = HE_CAP;
    for (int i = t; i < n; i += 128) s_list[i] = g_list_he[(size_t)b * HE_CAP + i];
    __syncthreads();

    float acc = g_he_feat[(size_t)b * D_IN + t];   // fallback base (usually 0)
    int i = 0;
    for (; i + 4 <= n; i += 4) {
        float2 e0 = s_list[i], e1 = s_list[i + 1], e2 = s_list[i + 2], e3 = s_list[i + 3];
        float f0 = feat[(size_t)__float_as_int(e0.x) * D_IN + t];
        float f1 = feat[(size_t)__float_as_int(e1.x) * D_IN + t];
        float f2 = feat[(size_t)__float_as_int(e2.x) * D_IN + t];
        float f3 = feat[(size_t)__float_as_int(e3.x) * D_IN + t];
        acc += e0.y * f0;
        acc += e1.y * f1;
        acc += e2.y * f2;
        acc += e3.y * f3;
    }
    for (; i < n; i++) {
        float2 e0 = s_list[i];
        acc += e0.y * feat[(size_t)__float_as_int(e0.x) * D_IN + t];
    }
    g_he_feat[(size_t)b * D_IN + t] = acc;
}

// ---------------------------------------------------------------------------
// attention over hyperedges (unchanged)
// ---------------------------------------------------------------------------
__global__ __launch_bounds__(256) void attn_kernel(
    const float* __restrict__ Wh1, const float* __restrict__ bh1,
    const float* __restrict__ Wh2, const float* __restrict__ bh2,
    const float* __restrict__ Wfuse) {
    __shared__ float s_he[D_IN];
    __shared__ float s_part[8];
    __shared__ float s_attn;

    int n = blockIdx.x;
    int t = threadIdx.x;
    if (t < D_IN) s_he[t] = g_he_feat[(size_t)n * D_IN + t];
    __syncthreads();

    int h = t >> 6;
    int k = t & 63;
    const float* w = Wh1 + ((size_t)h * D_IN) * HEAD_DIM + k;
    float acc = 0.f;
#pragma unroll 4
    for (int d = 0; d < D_IN; d++) acc += s_he[d] * w[(size_t)d * HEAD_DIM];
    float v = fmaxf(acc + bh1[h * HEAD_DIM + k], 0.f) * Wh2[h * HEAD_DIM + k];
#pragma unroll
    for (int o = 16; o; o >>= 1) v += __shfl_down_sync(0xffffffffu, v, o);
    if ((t & 31) == 0) s_part[t >> 5] = v;
    __syncthreads();
    if (t == 0) {
        float a = 0.f;
        for (int hh = 0; hh < N_HEADS; hh++) {
            float logit = s_part[2 * hh] + s_part[2 * hh + 1] + bh2[hh];
            float sg = 1.f / (1.f + expf(-logit));
            a += sg * Wfuse[hh];
        }
        s_attn = a;
    }
    __syncthreads();
    if (t < D_IN) g_he_w[(size_t)n * D_IN + t] = s_he[t] * s_attn;
}

// ---------------------------------------------------------------------------
// ovf: rare overflow edges -> direct reduction into cluster (before p_acc)
// ---------------------------------------------------------------------------
__global__ void ovf_kernel() {
    int novf = g_novf;
    if (novf > OVF_CAP) novf = OVF_CAP;
    int widg = (blockIdx.x * blockDim.x + threadIdx.x) >> 5;
    int lane = threadIdx.x & 31;
    int nw = (gridDim.x * blockDim.x) >> 5;
    for (int e = widg; e < novf; e += nw) {
        float4 o = g_ovf[e];
        int p = __float_as_int(o.x);
        int h = __float_as_int(o.y);
        float w = o.z;
        float4 v = ((const float4*)(g_he_w + (size_t)h * D_IN))[lane];
        red_add_v4(g_cluster + (size_t)p * D_IN + lane * 4,
                   v.x * w, v.y * w, v.z * w, v.w * w);
    }
}

// ---------------------------------------------------------------------------
// p_acc: warp per protein, float4 accumulation from L2-hot he_w
// ---------------------------------------------------------------------------
__global__ __launch_bounds__(256) void p_acc_kernel(int nP) {
    __shared__ float2 s_list[8][P_CAP];
    int wid = threadIdx.x >> 5, lane = threadIdx.x & 31;
    int p = blockIdx.x * 8 + wid;
    if (p >= nP) return;
    int n = g_cnt_p[p];
    if (n > P_CAP) n = P_CAP;
    for (int i = lane; i < n; i += 32) s_list[wid][i] = g_list_p[(size_t)p * P_CAP + i];
    __syncwarp();

    float4 acc = ((const float4*)(g_cluster + (size_t)p * D_IN))[lane]; // ovf base
    int i = 0;
    for (; i + 2 <= n; i += 2) {
        float2 e0 = s_list[wid][i], e1 = s_list[wid][i + 1];
        float4 v0 = ((const float4*)(g_he_w + (size_t)__float_as_int(e0.x) * D_IN))[lane];
        float4 v1 = ((const float4*)(g_he_w + (size_t)__float_as_int(e1.x) * D_IN))[lane];
        acc.x += e0.y * v0.x; acc.y += e0.y * v0.y;
        acc.z += e0.y * v0.z; acc.w += e0.y * v0.w;
        acc.x += e1.y * v1.x; acc.y += e1.y * v1.y;
        acc.z += e1.y * v1.z; acc.w += e1.y * v1.w;
    }
    if (i < n) {
        float2 e0 = s_list[wid][i];
        float4 v0 = ((const float4*)(g_he_w + (size_t)__float_as_int(e0.x) * D_IN))[lane];
        acc.x += e0.y * v0.x; acc.y += e0.y * v0.y;
        acc.z += e0.y * v0.z; acc.w += e0.y * v0.w;
    }
    ((float4*)(g_cluster + (size_t)p * D_IN))[lane] = acc;
}

// ---------------------------------------------------------------------------
// 3xTF32 tensor-core fused MLP (unchanged from round 2)
// ---------------------------------------------------------------------------
__device__ __forceinline__ void mma_tf32(float (&c)[4], const unsigned (&a)[4],
                                         unsigned b0, unsigned b1) {
    asm volatile(
        "mma.sync.aligned.m16n8k8.row.col.f32.tf32.tf32.f32 "
        "{%0,%1,%2,%3},{%4,%5,%6,%7},{%8,%9},{%0,%1,%2,%3};\n"
        : "+f"(c[0]), "+f"(c[1]), "+f"(c[2]), "+f"(c[3])
        : "r"(a[0]), "r"(a[1]), "r"(a[2]), "r"(a[3]), "r"(b0), "r"(b1));
}

#define LDSM4(R, ADDR) \
    asm volatile("ldmatrix.sync.aligned.m8n8.x4.shared.b16 {%0,%1,%2,%3},[%4];" \
                 : "=r"((R)[0]), "=r"((R)[1]), "=r"((R)[2]), "=r"((R)[3]) : "r"(ADDR))

__device__ __forceinline__ unsigned smem_u32(const void* p) {
    return (unsigned)__cvta_generic_to_shared(p);
}

__device__ __forceinline__ void split_bits(unsigned x, unsigned& hi, unsigned& lo) {
    hi = x & 0xffffe000u;
    lo = __float_as_uint(__uint_as_float(x) - __uint_as_float(hi));
}

template <int KT, int NT>
__device__ __forceinline__ void gemm_stage(const unsigned (&aAddr)[4],
                                           const float* __restrict__ Wp, int N,
                                           float (&acc)[4][NT][4]) {
    unsigned a0[4][4];
    unsigned bb0[NT][2];
#pragma unroll
    for (int mt = 0; mt < 4; mt++) LDSM4(a0[mt], aAddr[mt]);
#pragma unroll
    for (int nt = 0; nt < NT; nt++) {
        bb0[nt][0] = __float_as_uint(__ldg(Wp + nt * 8));
        bb0[nt][1] = __float_as_uint(__ldg(Wp + 4 * N + nt * 8));
    }
#pragma unroll
    for (int kt = 0; kt < KT; kt++) {
        unsigned a1[4][4];
        unsigned bb1[NT][2];
        if (kt + 1 < KT) {
#pragma unroll
            for (int mt = 0; mt < 4; mt++) LDSM4(a1[mt], aAddr[mt] + (kt + 1) * 32u);
            const float* Wk = Wp + (size_t)(kt + 1) * 8 * N;
#pragma unroll
            for (int nt = 0; nt < NT; nt++) {
                bb1[nt][0] = __float_as_uint(__ldg(Wk + nt * 8));
                bb1[nt][1] = __float_as_uint(__ldg(Wk + 4 * N + nt * 8));
            }
        }
        unsigned alo[4][4];
#pragma unroll
        for (int mt = 0; mt < 4; mt++)
#pragma unroll
            for (int i = 0; i < 4; i++) split_bits(a0[mt][i], a0[mt][i], alo[mt][i]);
        unsigned blo[NT][2];
#pragma unroll
        for (int nt = 0; nt < NT; nt++) {
            split_bits(bb0[nt][0], bb0[nt][0], blo[nt][0]);
            split_bits(bb0[nt][1], bb0[nt][1], blo[nt][1]);
        }
#pragma unroll
        for (int nt = 0; nt < NT; nt++)
#pragma unroll
            for (int mt = 0; mt < 4; mt++) {
                mma_tf32(acc[mt][nt], alo[mt], bb0[nt][0], bb0[nt][1]);
                mma_tf32(acc[mt][nt], a0[mt],  blo[nt][0], blo[nt][1]);
                mma_tf32(acc[mt][nt], a0[mt],  bb0[nt][0], bb0[nt][1]);
            }
#pragma unroll
        for (int mt = 0; mt < 4; mt++)
#pragma unroll
            for (int i = 0; i < 4; i++) a0[mt][i] = a1[mt][i];
#pragma unroll
        for (int nt = 0; nt < NT; nt++) {
            bb0[nt][0] = bb1[nt][0];
            bb0[nt][1] = bb1[nt][1];
        }
    }
}

template <int NT, bool RELU>
__device__ __forceinline__ void epilogue(float* dst, int dstride, int col0,
                                         const float* __restrict__ bias,
                                         float (&acc)[4][NT][4], int lane) {
    int gid = lane >> 2, tig = lane & 3;
#pragma unroll
    for (int nt = 0; nt < NT; nt++) {
        int c = nt * 8 + tig * 2;
        float bA = __ldg(bias + c), bB = __ldg(bias + c + 1);
#pragma unroll
        for (int mt = 0; mt < 4; mt++) {
            int r = mt * 16 + gid;
            float v0 = acc[mt][nt][0] + bA, v1 = acc[mt][nt][1] + bB;
            float v2 = acc[mt][nt][2] + bA, v3 = acc[mt][nt][3] + bB;
            if (RELU) {
                v0 = fmaxf(v0, 0.f); v1 = fmaxf(v1, 0.f);
                v2 = fmaxf(v2, 0.f); v3 = fmaxf(v3, 0.f);
            }
            dst[(size_t)r * dstride + col0 + c]           = v0;
            dst[(size_t)r * dstride + col0 + c + 1]       = v1;
            dst[(size_t)(r + 8) * dstride + col0 + c]     = v2;
            dst[(size_t)(r + 8) * dstride + col0 + c + 1] = v3;
        }
    }
}

__global__ __launch_bounds__(256, 1) void mlp2_kernel(
    const float* __restrict__ feat,
    const float* __restrict__ Wself, const float* __restrict__ bself,
    const float* __restrict__ Wclu,  const float* __restrict__ bclu,
    const float* __restrict__ Wf1,   const float* __restrict__ bf1,
    const float* __restrict__ Wf2,   const float* __restrict__ bf2,
    const float* __restrict__ Wf3,   const float* __restrict__ bf3,
    float* __restrict__ out, int nP) {
    extern __shared__ float sm[];
    float* s_feat = sm;
    float* s_cat  = s_feat + 64 * PAD128;
    float* s_u1   = s_cat + 64 * PAD256;
    float (*s_gate)[2] = (float (*)[2])(s_u1 + 64 * PAD256);

    int row0 = blockIdx.x * 64;
    int t = threadIdx.x;
    int wid = t >> 5, lane = t & 31;

    const float4* feat4 = (const float4*)feat;
    const float4* clu4  = (const float4*)g_cluster;
    for (int i = t; i < 64 * 32; i += 256) {
        int r = i >> 5, c4 = i & 31;
        int gr = row0 + r;
        float4 f = make_float4(0.f, 0.f, 0.f, 0.f), cl = f;
        if (gr < nP) {
            f  = feat4[(size_t)gr * 32 + c4];
            cl = clu4[(size_t)gr * 32 + c4];
        }
        *(float4*)&s_feat[(size_t)r * PAD128 + c4 * 4] = f;
        *(float4*)&s_u1[(size_t)r * PAD256 + c4 * 4]   = cl;
    }
    __syncthreads();

    int m8  = lane >> 3;
    int rIn = lane & 7;
    int rowoff = (m8 & 1) * 8 + rIn;
    int coloff = (m8 >> 1) * 4;
    int gid = lane >> 2, tig = lane & 3;

    // stage A: self_f | clu_f
    {
        float acc[4][4][4];
#pragma unroll
        for (int a = 0; a < 4; a++)
#pragma unroll
            for (int b = 0; b < 4; b++)
#pragma unroll
                for (int c = 0; c < 4; c++) acc[a][b][c] = 0.f;

        const float* aBuf   = (wid < 4) ? s_feat : s_u1;
        int          aStr   = (wid < 4) ? PAD128 : PAD256;
        const float* W      = (wid < 4) ? Wself : Wclu;
        const float* bias   = (wid < 4) ? bself : bclu;
        int ncol0           = (wid & 3) * 32;
        int outcol0         = (wid < 4) ? ncol0 : (128 + ncol0);

        unsigned aAddr[4];
#pragma unroll
        for (int mt = 0; mt < 4; mt++)
            aAddr[mt] = smem_u32(aBuf + (size_t)(mt * 16 + rowoff) * aStr + coloff);

        const float* Wp = W + (size_t)tig * 128 + ncol0 + gid;
        gemm_stage<16, 4>(aAddr, Wp, 128, acc);
        __syncthreads();
        epilogue<4, false>(s_cat, PAD256, outcol0, bias + ncol0, acc, lane);
    }
    __syncthreads();

    // stage B: x1 = relu(cat @ Wf1 + bf1)
    {
        float acc[4][4][4];
#pragma unroll
        for (int a = 0; a < 4; a++)
#pragma unroll
            for (int b = 0; b < 4; b++)
#pragma unroll
                for (int c = 0; c < 4; c++) acc[a][b][c] = 0.f;

        int ncol0 = wid * 32;
        unsigned aAddr[4];
#pragma unroll
        for (int mt = 0; mt < 4; mt++)
            aAddr[mt] = smem_u32(s_cat + (size_t)(mt * 16 + rowoff) * PAD256 + coloff);
        const float* Wp = Wf1 + (size_t)tig * 256 + ncol0 + gid;
        gemm_stage<32, 4>(aAddr, Wp, 256, acc);
        __syncthreads();
        epilogue<4, true>(s_u1, PAD256, ncol0, bf1 + ncol0, acc, lane);
    }
    __syncthreads();

    // stage C: x2 = relu(x1 @ Wf2 + bf2)
    {
        float acc[4][2][4];
#pragma unroll
        for (int a = 0; a < 4; a++)
#pragma unroll
            for (int b = 0; b < 2; b++)
#pragma unroll
                for (int c = 0; c < 4; c++) acc[a][b][c] = 0.f;

        int ncol0 = wid * 16;
        unsigned aAddr[4];
#pragma unroll
        for (int mt = 0; mt < 4; mt++)
            aAddr[mt] = smem_u32(s_u1 + (size_t)(mt * 16 + rowoff) * PAD256 + coloff);
        const float* Wp = Wf2 + (size_t)tig * 128 + ncol0 + gid;
        gemm_stage<32, 2>(aAddr, Wp, 128, acc);
        __syncthreads();
        epilogue<2, true>(s_feat, PAD128, ncol0, bf2 + ncol0, acc, lane);
    }
    __syncthreads();

    // stage D: softmax gates
    if (t < 64) {
        float a0 = __ldg(bf3 + 0), a1 = __ldg(bf3 + 1);
        const float* x = s_feat + (size_t)t * PAD128;
#pragma unroll 4
        for (int k = 0; k < 128; k++) {
            float xv = x[k];
            a0 += xv * __ldg(Wf3 + 2 * k);
            a1 += xv * __ldg(Wf3 + 2 * k + 1);
        }
        float m = fmaxf(a0, a1);
        float e0 = expf(a0 - m), e1 = expf(a1 - m);
        float inv = 1.f / (e0 + e1);
        s_gate[t][0] = e0 * inv;
        s_gate[t][1] = e1 * inv;
    }
    __syncthreads();

    // stage E: out = relu(self*g0 + clu*g1 + feat)
    for (int i = t; i < 64 * 32; i += 256) {
        int r = i >> 5, c4 = i & 31;
        int gr = row0 + r;
        if (gr < nP) {
            float4 f = feat4[(size_t)gr * 32 + c4];
            float g0 = s_gate[r][0], g1 = s_gate[r][1];
            const float* sf = s_cat + (size_t)r * PAD256 + c4 * 4;
            const float* sc = sf + 128;
            float4 o;
            o.x = fmaxf(sf[0] * g0 + sc[0] * g1 + f.x, 0.f);
            o.y = fmaxf(sf[1] * g0 + sc[1] * g1 + f.y, 0.f);
            o.z = fmaxf(sf[2] * g0 + sc[2] * g1 + f.z, 0.f);
            o.w = fmaxf(sf[3] * g0 + sc[3] * g1 + f.w, 0.f);
            ((float4*)out)[(size_t)gr * 32 + c4] = o;
        }
    }
}

// ---------------------------------------------------------------------------
extern "C" void kernel_launch(void* const* d_in, const int* in_sizes, int n_in,
                              void* d_out, int out_size) {
    const float* feat   = (const float*)d_in[0];
    const float* edge_w = (const float*)d_in[1];
    const float* Wself  = (const float*)d_in[2];
    const float* bself  = (const float*)d_in[3];
    const float* Wclu   = (const float*)d_in[4];
    const float* bclu   = (const float*)d_in[5];
    const float* Wh1    = (const float*)d_in[6];
    const float* bh1    = (const float*)d_in[7];
    const float* Wh2    = (const float*)d_in[8];
    const float* bh2    = (const float*)d_in[9];
    const float* Wfuse  = (const float*)d_in[10];
    const float* Wf1    = (const float*)d_in[11];
    const float* bf1    = (const float*)d_in[12];
    const float* Wf2    = (const float*)d_in[13];
    const float* bf2    = (const float*)d_in[14];
    const float* Wf3    = (const float*)d_in[15];
    const float* bf3    = (const float*)d_in[16];
    const int*   e_pid  = (const int*)d_in[17];
    const int*   e_hid  = (const int*)d_in[18];

    int nE = in_sizes[17];
    int nP = in_sizes[0] / D_IN;
    float* out = (float*)d_out;

    int zeroN = N_P * (D_IN / 4);
    zero_kernel<<<(zeroN + 255) / 256, 256>>>();

    fill_kernel<<<(nE + 255) / 256, 256>>>(edge_w, e_pid, e_hid, feat, nE);

    he_acc_kernel<<<N_HE, 128>>>(feat);

    attn_kernel<<<N_HE, 256>>>(Wh1, bh1, Wh2, bh2, Wfuse);

    ovf_kernel<<<32, 256>>>();

    p_acc_kernel<<<(nP + 7) / 8, 256>>>(nP);

    size_t smemBytes = (size_t)(64 * PAD128 + 2 * 64 * PAD256) * 4 + 64 * 2 * 4;
    cudaFuncSetAttribute(mlp2_kernel, cudaFuncAttributeMaxDynamicSharedMemorySize,
                         (int)smemBytes);
    int nBlocks = (nP + 63) / 64;
    mlp2_kernel<<<nBlocks, 256, smemBytes>>>(feat, Wself, bself, Wclu, bclu,
                                             Wf1, bf1, Wf2, bf2, Wf3, bf3,
                                             out, nP);
}

// round 5
// speedup vs baseline: 1.8112x; 1.1058x over previous
#include <cuda_runtime.h>
#include <math.h>

#define N_P   50000
#define N_HE  5000
#define D_IN  128
#define D_HID 256
#define N_HEADS 4
#define HEAD_DIM 64

#define HE_CAP 256
#define P_CAP  64
#define OVF_CAP 65536

#define PAD128 132
#define PAD256 260

// ---- scratch (no allocation allowed) ----
__device__ float g_he_feat[N_HE * D_IN];
__device__ float g_he_w[N_HE * D_IN];
__device__ float g_cluster[N_P * D_IN];
__device__ int   g_cnt_he[N_HE];
__device__ int   g_cnt_p[N_P];
__device__ float2 g_list_he[N_HE * HE_CAP];   // (pid bits, w) per hyperedge
__device__ float2 g_list_p[N_P * P_CAP];      // (hid bits, w) per protein
__device__ float4 g_ovf[OVF_CAP];             // (pid, hid, w, -) overflow
__device__ int   g_novf;

// ---------------------------------------------------------------------------
__device__ __forceinline__ void red_add_v4(float* dst, float a, float b, float c, float d) {
    asm volatile("red.global.add.v4.f32 [%0], {%1,%2,%3,%4};"
                 :: "l"(dst), "f"(a), "f"(b), "f"(c), "f"(d) : "memory");
}

// ---------------------------------------------------------------------------
__global__ void zero_kernel() {
    int i = blockIdx.x * blockDim.x + threadIdx.x;
    float4 z = make_float4(0.f, 0.f, 0.f, 0.f);
    if (i < N_P * (D_IN / 4))  ((float4*)g_cluster)[i] = z;
    if (i < N_HE * (D_IN / 4)) ((float4*)g_he_feat)[i] = z;
    if (i < N_HE)              g_cnt_he[i] = 0;
    if (i < N_P)               g_cnt_p[i] = 0;
    if (i == 0)                g_novf = 0;
}

// ---------------------------------------------------------------------------
__global__ void fill_kernel(const float* __restrict__ ew,
                            const int* __restrict__ pid,
                            const int* __restrict__ hid,
                            const float* __restrict__ feat, int nE) {
    int e = blockIdx.x * blockDim.x + threadIdx.x;
    if (e >= nE) return;
    int p = pid[e];
    int h = hid[e];
    float w = ew[e];

    int pos = atomicAdd(&g_cnt_he[h], 1);
    if (pos < HE_CAP) {
        g_list_he[(size_t)h * HE_CAP + pos] = make_float2(__int_as_float(p), w);
    } else {
        const float4* fr = (const float4*)(feat + (size_t)p * D_IN);
        for (int i = 0; i < D_IN / 4; i++) {
            float4 v = fr[i];
            red_add_v4(g_he_feat + (size_t)h * D_IN + i * 4,
                       v.x * w, v.y * w, v.z * w, v.w * w);
        }
    }

    int pos2 = atomicAdd(&g_cnt_p[p], 1);
    if (pos2 < P_CAP) {
        g_list_p[(size_t)p * P_CAP + pos2] = make_float2(__int_as_float(h), w);
    } else {
        int o = atomicAdd(&g_novf, 1);
        if (o < OVF_CAP)
            g_ovf[o] = make_float4(__int_as_float(p), __int_as_float(h), w, 0.f);
    }
}

// ---------------------------------------------------------------------------
__global__ __launch_bounds__(128) void he_acc_kernel(const float* __restrict__ feat) {
    __shared__ float2 s_list[HE_CAP];
    int b = blockIdx.x, t = threadIdx.x;
    int n = g_cnt_he[b];
    if (n > HE_CAP) n = HE_CAP;
    for (int i = t; i < n; i += 128) s_list[i] = g_list_he[(size_t)b * HE_CAP + i];
    __syncthreads();

    float acc = g_he_feat[(size_t)b * D_IN + t];
    int i = 0;
    for (; i + 4 <= n; i += 4) {
        float2 e0 = s_list[i], e1 = s_list[i + 1], e2 = s_list[i + 2], e3 = s_list[i + 3];
        float f0 = feat[(size_t)__float_as_int(e0.x) * D_IN + t];
        float f1 = feat[(size_t)__float_as_int(e1.x) * D_IN + t];
        float f2 = feat[(size_t)__float_as_int(e2.x) * D_IN + t];
        float f3 = feat[(size_t)__float_as_int(e3.x) * D_IN + t];
        acc += e0.y * f0;
        acc += e1.y * f1;
        acc += e2.y * f2;
        acc += e3.y * f3;
    }
    for (; i < n; i++) {
        float2 e0 = s_list[i];
        acc += e0.y * feat[(size_t)__float_as_int(e0.x) * D_IN + t];
    }
    g_he_feat[(size_t)b * D_IN + t] = acc;
}

// ---------------------------------------------------------------------------
// 3xTF32 MMA machinery (shared by attn + mlp)
// ---------------------------------------------------------------------------
__device__ __forceinline__ void mma_tf32(float (&c)[4], const unsigned (&a)[4],
                                         unsigned b0, unsigned b1) {
    asm volatile(
        "mma.sync.aligned.m16n8k8.row.col.f32.tf32.tf32.f32 "
        "{%0,%1,%2,%3},{%4,%5,%6,%7},{%8,%9},{%0,%1,%2,%3};\n"
        : "+f"(c[0]), "+f"(c[1]), "+f"(c[2]), "+f"(c[3])
        : "r"(a[0]), "r"(a[1]), "r"(a[2]), "r"(a[3]), "r"(b0), "r"(b1));
}

#define LDSM4(R, ADDR) \
    asm volatile("ldmatrix.sync.aligned.m8n8.x4.shared.b16 {%0,%1,%2,%3},[%4];" \
                 : "=r"((R)[0]), "=r"((R)[1]), "=r"((R)[2]), "=r"((R)[3]) : "r"(ADDR))

__device__ __forceinline__ unsigned smem_u32(const void* p) {
    return (unsigned)__cvta_generic_to_shared(p);
}

__device__ __forceinline__ void split_bits(unsigned x, unsigned& hi, unsigned& lo) {
    hi = x & 0xffffe000u;
    lo = __float_as_uint(__uint_as_float(x) - __uint_as_float(hi));
}

// KT k-tiles (depth K = KT*8), NT n-tiles of 8 cols. B element (k, c) is read
// at Wp[k*N + c] -> N doubles as the row stride of the weight matrix.
template <int KT, int NT>
__device__ __forceinline__ void gemm_stage(const unsigned (&aAddr)[4],
                                           const float* __restrict__ Wp, int N,
                                           float (&acc)[4][NT][4]) {
    unsigned a0[4][4];
    unsigned bb0[NT][2];
#pragma unroll
    for (int mt = 0; mt < 4; mt++) LDSM4(a0[mt], aAddr[mt]);
#pragma unroll
    for (int nt = 0; nt < NT; nt++) {
        bb0[nt][0] = __float_as_uint(__ldg(Wp + nt * 8));
        bb0[nt][1] = __float_as_uint(__ldg(Wp + 4 * N + nt * 8));
    }
#pragma unroll
    for (int kt = 0; kt < KT; kt++) {
        unsigned a1[4][4];
        unsigned bb1[NT][2];
        if (kt + 1 < KT) {
#pragma unroll
            for (int mt = 0; mt < 4; mt++) LDSM4(a1[mt], aAddr[mt] + (kt + 1) * 32u);
            const float* Wk = Wp + (size_t)(kt + 1) * 8 * N;
#pragma unroll
            for (int nt = 0; nt < NT; nt++) {
                bb1[nt][0] = __float_as_uint(__ldg(Wk + nt * 8));
                bb1[nt][1] = __float_as_uint(__ldg(Wk + 4 * N + nt * 8));
            }
        }
        unsigned alo[4][4];
#pragma unroll
        for (int mt = 0; mt < 4; mt++)
#pragma unroll
            for (int i = 0; i < 4; i++) split_bits(a0[mt][i], a0[mt][i], alo[mt][i]);
        unsigned blo[NT][2];
#pragma unroll
        for (int nt = 0; nt < NT; nt++) {
            split_bits(bb0[nt][0], bb0[nt][0], blo[nt][0]);
            split_bits(bb0[nt][1], bb0[nt][1], blo[nt][1]);
        }
#pragma unroll
        for (int nt = 0; nt < NT; nt++)
#pragma unroll
            for (int mt = 0; mt < 4; mt++) {
                mma_tf32(acc[mt][nt], alo[mt], bb0[nt][0], bb0[nt][1]);
                mma_tf32(acc[mt][nt], a0[mt],  blo[nt][0], blo[nt][1]);
                mma_tf32(acc[mt][nt], a0[mt],  bb0[nt][0], bb0[nt][1]);
            }
#pragma unroll
        for (int mt = 0; mt < 4; mt++)
#pragma unroll
            for (int i = 0; i < 4; i++) a0[mt][i] = a1[mt][i];
#pragma unroll
        for (int nt = 0; nt < NT; nt++) {
            bb0[nt][0] = bb1[nt][0];
            bb0[nt][1] = bb1[nt][1];
        }
    }
}

template <int NT, bool RELU>
__device__ __forceinline__ void epilogue(float* dst, int dstride, int col0,
                                         const float* __restrict__ bias,
                                         float (&acc)[4][NT][4], int lane) {
    int gid = lane >> 2, tig = lane & 3;
#pragma unroll
    for (int nt = 0; nt < NT; nt++) {
        int c = nt * 8 + tig * 2;
        float bA = __ldg(bias + c), bB = __ldg(bias + c + 1);
#pragma unroll
        for (int mt = 0; mt < 4; mt++) {
            int r = mt * 16 + gid;
            float v0 = acc[mt][nt][0] + bA, v1 = acc[mt][nt][1] + bB;
            float v2 = acc[mt][nt][2] + bA, v3 = acc[mt][nt][3] + bB;
            if (RELU) {
                v0 = fmaxf(v0, 0.f); v1 = fmaxf(v1, 0.f);
                v2 = fmaxf(v2, 0.f); v3 = fmaxf(v3, 0.f);
            }
            dst[(size_t)r * dstride + col0 + c]           = v0;
            dst[(size_t)r * dstride + col0 + c + 1]       = v1;
            dst[(size_t)(r + 8) * dstride + col0 + c]     = v2;
            dst[(size_t)(r + 8) * dstride + col0 + c + 1] = v3;
        }
    }
}

// ---------------------------------------------------------------------------
// attention as a 64-row tiled 3xTF32 GEMM (79 blocks instead of 5000):
//   H = relu(he_feat @ Wh1 + bh1)  [64 x 256 per block]
//   logit[r][h] = H[r, h*64:h*64+64] . Wh2[h] + bh2[h]
//   he_attn[r]  = sum_h sigmoid(logit) * Wfuse[h]
//   he_w[r]     = he_feat[r] * he_attn[r]
// warp w: head = w>>1, cols (w&1)*32 .. +31 within the head.
// ---------------------------------------------------------------------------
__global__ __launch_bounds__(256) void attn_gemm_kernel(
    const float* __restrict__ Wh1, const float* __restrict__ bh1,
    const float* __restrict__ Wh2, const float* __restrict__ bh2,
    const float* __restrict__ Wfuse) {
    __shared__ float s_he[64 * PAD128];
    __shared__ float s_part[64][8];
    __shared__ float s_attn[64];

    int row0 = blockIdx.x * 64;
    int t = threadIdx.x, wid = t >> 5, lane = t & 31;

    for (int i = t; i < 64 * 32; i += 256) {
        int r = i >> 5, c4 = i & 31;
        int gr = row0 + r;
        float4 v = make_float4(0.f, 0.f, 0.f, 0.f);
        if (gr < N_HE) v = ((const float4*)g_he_feat)[(size_t)gr * 32 + c4];
        *(float4*)&s_he[(size_t)r * PAD128 + c4 * 4] = v;
    }
    __syncthreads();

    int m8 = lane >> 3, rIn = lane & 7;
    int rowoff = (m8 & 1) * 8 + rIn;
    int coloff = (m8 >> 1) * 4;
    int gid = lane >> 2, tig = lane & 3;

    int head = wid >> 1;
    int colHalf = (wid & 1) * 32;

    float acc[4][4][4];
#pragma unroll
    for (int a = 0; a < 4; a++)
#pragma unroll
        for (int b = 0; b < 4; b++)
#pragma unroll
            for (int c = 0; c < 4; c++) acc[a][b][c] = 0.f;

    unsigned aAddr[4];
#pragma unroll
    for (int mt = 0; mt < 4; mt++)
        aAddr[mt] = smem_u32(s_he + (size_t)(mt * 16 + rowoff) * PAD128 + coloff);

    const float* Wp = Wh1 + (size_t)head * (D_IN * HEAD_DIM)
                    + (size_t)tig * HEAD_DIM + colHalf + gid;
    gemm_stage<16, 4>(aAddr, Wp, HEAD_DIM, acc);

    // bias + relu + dot with Wh2 -> per-row partials for this warp's 32 cols
    float p0[4] = {0.f, 0.f, 0.f, 0.f};
    float p1[4] = {0.f, 0.f, 0.f, 0.f};
#pragma unroll
    for (int nt = 0; nt < 4; nt++) {
        int c = head * HEAD_DIM + colHalf + nt * 8 + tig * 2;
        float bA = __ldg(bh1 + c),  bB = __ldg(bh1 + c + 1);
        float wA = __ldg(Wh2 + c),  wB = __ldg(Wh2 + c + 1);
#pragma unroll
        for (int mt = 0; mt < 4; mt++) {
            p0[mt] += fmaxf(acc[mt][nt][0] + bA, 0.f) * wA
                    + fmaxf(acc[mt][nt][1] + bB, 0.f) * wB;
            p1[mt] += fmaxf(acc[mt][nt][2] + bA, 0.f) * wA
                    + fmaxf(acc[mt][nt][3] + bB, 0.f) * wB;
        }
    }
    // reduce over tig (lanes differing in low 2 bits)
#pragma unroll
    for (int mt = 0; mt < 4; mt++) {
        p0[mt] += __shfl_xor_sync(0xffffffffu, p0[mt], 1);
        p0[mt] += __shfl_xor_sync(0xffffffffu, p0[mt], 2);
        p1[mt] += __shfl_xor_sync(0xffffffffu, p1[mt], 1);
        p1[mt] += __shfl_xor_sync(0xffffffffu, p1[mt], 2);
    }
    if (tig == 0) {
#pragma unroll
        for (int mt = 0; mt < 4; mt++) {
            s_part[mt * 16 + gid][wid]     = p0[mt];
            s_part[mt * 16 + gid + 8][wid] = p1[mt];
        }
    }
    __syncthreads();

    if (t < 64) {
        float a = 0.f;
#pragma unroll
        for (int h = 0; h < N_HEADS; h++) {
            float logit = s_part[t][2 * h] + s_part[t][2 * h + 1] + __ldg(bh2 + h);
            a += __ldg(Wfuse + h) / (1.f + expf(-logit));
        }
        s_attn[t] = a;
    }
    __syncthreads();

    for (int i = t; i < 64 * 32; i += 256) {
        int r = i >> 5, c4 = i & 31;
        int gr = row0 + r;
        if (gr < N_HE) {
            float4 v = *(float4*)&s_he[(size_t)r * PAD128 + c4 * 4];
            float a = s_attn[r];
            v.x *= a; v.y *= a; v.z *= a; v.w *= a;
            ((float4*)g_he_w)[(size_t)gr * 32 + c4] = v;
        }
    }
}

// ---------------------------------------------------------------------------
__global__ void ovf_kernel() {
    int novf = g_novf;
    if (novf > OVF_CAP) novf = OVF_CAP;
    int widg = (blockIdx.x * blockDim.x + threadIdx.x) >> 5;
    int lane = threadIdx.x & 31;
    int nw = (gridDim.x * blockDim.x) >> 5;
    for (int e = widg; e < novf; e += nw) {
        float4 o = g_ovf[e];
        int p = __float_as_int(o.x);
        int h = __float_as_int(o.y);
        float w = o.z;
        float4 v = ((const float4*)(g_he_w + (size_t)h * D_IN))[lane];
        red_add_v4(g_cluster + (size_t)p * D_IN + lane * 4,
                   v.x * w, v.y * w, v.z * w, v.w * w);
    }
}

// ---------------------------------------------------------------------------
__global__ __launch_bounds__(256) void p_acc_kernel(int nP) {
    __shared__ float2 s_list[8][P_CAP];
    int wid = threadIdx.x >> 5, lane = threadIdx.x & 31;
    int p = blockIdx.x * 8 + wid;
    if (p >= nP) return;
    int n = g_cnt_p[p];
    if (n > P_CAP) n = P_CAP;
    for (int i = lane; i < n; i += 32) s_list[wid][i] = g_list_p[(size_t)p * P_CAP + i];
    __syncwarp();

    float4 acc = ((const float4*)(g_cluster + (size_t)p * D_IN))[lane];
    int i = 0;
    for (; i + 2 <= n; i += 2) {
        float2 e0 = s_list[wid][i], e1 = s_list[wid][i + 1];
        float4 v0 = ((const float4*)(g_he_w + (size_t)__float_as_int(e0.x) * D_IN))[lane];
        float4 v1 = ((const float4*)(g_he_w + (size_t)__float_as_int(e1.x) * D_IN))[lane];
        acc.x += e0.y * v0.x; acc.y += e0.y * v0.y;
        acc.z += e0.y * v0.z; acc.w += e0.y * v0.w;
        acc.x += e1.y * v1.x; acc.y += e1.y * v1.y;
        acc.z += e1.y * v1.z; acc.w += e1.y * v1.w;
    }
    if (i < n) {
        float2 e0 = s_list[wid][i];
        float4 v0 = ((const float4*)(g_he_w + (size_t)__float_as_int(e0.x) * D_IN))[lane];
        acc.x += e0.y * v0.x; acc.y += e0.y * v0.y;
        acc.z += e0.y * v0.z; acc.w += e0.y * v0.w;
    }
    ((float4*)(g_cluster + (size_t)p * D_IN))[lane] = acc;
}

// ---------------------------------------------------------------------------
// 3xTF32 tensor-core fused MLP (unchanged)
// ---------------------------------------------------------------------------
__global__ __launch_bounds__(256, 1) void mlp2_kernel(
    const float* __restrict__ feat,
    const float* __restrict__ Wself, const float* __restrict__ bself,
    const float* __restrict__ Wclu,  const float* __restrict__ bclu,
    const float* __restrict__ Wf1,   const float* __restrict__ bf1,
    const float* __restrict__ Wf2,   const float* __restrict__ bf2,
    const float* __restrict__ Wf3,   const float* __restrict__ bf3,
    float* __restrict__ out, int nP) {
    extern __shared__ float sm[];
    float* s_feat = sm;
    float* s_cat  = s_feat + 64 * PAD128;
    float* s_u1   = s_cat + 64 * PAD256;
    float (*s_gate)[2] = (float (*)[2])(s_u1 + 64 * PAD256);

    int row0 = blockIdx.x * 64;
    int t = threadIdx.x;
    int wid = t >> 5, lane = t & 31;

    const float4* feat4 = (const float4*)feat;
    const float4* clu4  = (const float4*)g_cluster;
    for (int i = t; i < 64 * 32; i += 256) {
        int r = i >> 5, c4 = i & 31;
        int gr = row0 + r;
        float4 f = make_float4(0.f, 0.f, 0.f, 0.f), cl = f;
        if (gr < nP) {
            f  = feat4[(size_t)gr * 32 + c4];
            cl = clu4[(size_t)gr * 32 + c4];
        }
        *(float4*)&s_feat[(size_t)r * PAD128 + c4 * 4] = f;
        *(float4*)&s_u1[(size_t)r * PAD256 + c4 * 4]   = cl;
    }
    __syncthreads();

    int m8  = lane >> 3;
    int rIn = lane & 7;
    int rowoff = (m8 & 1) * 8 + rIn;
    int coloff = (m8 >> 1) * 4;
    int gid = lane >> 2, tig = lane & 3;

    // stage A: self_f | clu_f
    {
        float acc[4][4][4];
#pragma unroll
        for (int a = 0; a < 4; a++)
#pragma unroll
            for (int b = 0; b < 4; b++)
#pragma unroll
                for (int c = 0; c < 4; c++) acc[a][b][c] = 0.f;

        const float* aBuf   = (wid < 4) ? s_feat : s_u1;
        int          aStr   = (wid < 4) ? PAD128 : PAD256;
        const float* W      = (wid < 4) ? Wself : Wclu;
        const float* bias   = (wid < 4) ? bself : bclu;
        int ncol0           = (wid & 3) * 32;
        int outcol0         = (wid < 4) ? ncol0 : (128 + ncol0);

        unsigned aAddr[4];
#pragma unroll
        for (int mt = 0; mt < 4; mt++)
            aAddr[mt] = smem_u32(aBuf + (size_t)(mt * 16 + rowoff) * aStr + coloff);

        const float* Wp = W + (size_t)tig * 128 + ncol0 + gid;
        gemm_stage<16, 4>(aAddr, Wp, 128, acc);
        __syncthreads();
        epilogue<4, false>(s_cat, PAD256, outcol0, bias + ncol0, acc, lane);
    }
    __syncthreads();

    // stage B: x1 = relu(cat @ Wf1 + bf1)
    {
        float acc[4][4][4];
#pragma unroll
        for (int a = 0; a < 4; a++)
#pragma unroll
            for (int b = 0; b < 4; b++)
#pragma unroll
                for (int c = 0; c < 4; c++) acc[a][b][c] = 0.f;

        int ncol0 = wid * 32;
        unsigned aAddr[4];
#pragma unroll
        for (int mt = 0; mt < 4; mt++)
            aAddr[mt] = smem_u32(s_cat + (size_t)(mt * 16 + rowoff) * PAD256 + coloff);
        const float* Wp = Wf1 + (size_t)tig * 256 + ncol0 + gid;
        gemm_stage<32, 4>(aAddr, Wp, 256, acc);
        __syncthreads();
        epilogue<4, true>(s_u1, PAD256, ncol0, bf1 + ncol0, acc, lane);
    }
    __syncthreads();

    // stage C: x2 = relu(x1 @ Wf2 + bf2)
    {
        float acc[4][2][4];
#pragma unroll
        for (int a = 0; a < 4; a++)
#pragma unroll
            for (int b = 0; b < 2; b++)
#pragma unroll
                for (int c = 0; c < 4; c++) acc[a][b][c] = 0.f;

        int ncol0 = wid * 16;
        unsigned aAddr[4];
#pragma unroll
        for (int mt = 0; mt < 4; mt++)
            aAddr[mt] = smem_u32(s_u1 + (size_t)(mt * 16 + rowoff) * PAD256 + coloff);
        const float* Wp = Wf2 + (size_t)tig * 128 + ncol0 + gid;
        gemm_stage<32, 2>(aAddr, Wp, 128, acc);
        __syncthreads();
        epilogue<2, true>(s_feat, PAD128, ncol0, bf2 + ncol0, acc, lane);
    }
    __syncthreads();

    // stage D: softmax gates
    if (t < 64) {
        float a0 = __ldg(bf3 + 0), a1 = __ldg(bf3 + 1);
        const float* x = s_feat + (size_t)t * PAD128;
#pragma unroll 4
        for (int k = 0; k < 128; k++) {
            float xv = x[k];
            a0 += xv * __ldg(Wf3 + 2 * k);
            a1 += xv * __ldg(Wf3 + 2 * k + 1);
        }
        float m = fmaxf(a0, a1);
        float e0 = expf(a0 - m), e1 = expf(a1 - m);
        float inv = 1.f / (e0 + e1);
        s_gate[t][0] = e0 * inv;
        s_gate[t][1] = e1 * inv;
    }
    __syncthreads();

    // stage E: out = relu(self*g0 + clu*g1 + feat)
    for (int i = t; i < 64 * 32; i += 256) {
        int r = i >> 5, c4 = i & 31;
        int gr = row0 + r;
        if (gr < nP) {
            float4 f = feat4[(size_t)gr * 32 + c4];
            float g0 = s_gate[r][0], g1 = s_gate[r][1];
            const float* sf = s_cat + (size_t)r * PAD256 + c4 * 4;
            const float* sc = sf + 128;
            float4 o;
            o.x = fmaxf(sf[0] * g0 + sc[0] * g1 + f.x, 0.f);
            o.y = fmaxf(sf[1] * g0 + sc[1] * g1 + f.y, 0.f);
            o.z = fmaxf(sf[2] * g0 + sc[2] * g1 + f.z, 0.f);
            o.w = fmaxf(sf[3] * g0 + sc[3] * g1 + f.w, 0.f);
            ((float4*)out)[(size_t)gr * 32 + c4] = o;
        }
    }
}

// ---------------------------------------------------------------------------
extern "C" void kernel_launch(void* const* d_in, const int* in_sizes, int n_in,
                              void* d_out, int out_size) {
    const float* feat   = (const float*)d_in[0];
    const float* edge_w = (const float*)d_in[1];
    const float* Wself  = (const float*)d_in[2];
    const float* bself  = (const float*)d_in[3];
    const float* Wclu   = (const float*)d_in[4];
    const float* bclu   = (const float*)d_in[5];
    const float* Wh1    = (const float*)d_in[6];
    const float* bh1    = (const float*)d_in[7];
    const float* Wh2    = (const float*)d_in[8];
    const float* bh2    = (const float*)d_in[9];
    const float* Wfuse  = (const float*)d_in[10];
    const float* Wf1    = (const float*)d_in[11];
    const float* bf1    = (const float*)d_in[12];
    const float* Wf2    = (const float*)d_in[13];
    const float* bf2    = (const float*)d_in[14];
    const float* Wf3    = (const float*)d_in[15];
    const float* bf3    = (const float*)d_in[16];
    const int*   e_pid  = (const int*)d_in[17];
    const int*   e_hid  = (const int*)d_in[18];

    int nE = in_sizes[17];
    int nP = in_sizes[0] / D_IN;
    float* out = (float*)d_out;

    int zeroN = N_P * (D_IN / 4);
    zero_kernel<<<(zeroN + 255) / 256, 256>>>();

    fill_kernel<<<(nE + 255) / 256, 256>>>(edge_w, e_pid, e_hid, feat, nE);

    he_acc_kernel<<<N_HE, 128>>>(feat);

    attn_gemm_kernel<<<(N_HE + 63) / 64, 256>>>(Wh1, bh1, Wh2, bh2, Wfuse);

    ovf_kernel<<<32, 256>>>();

    p_acc_kernel<<<(nP + 7) / 8, 256>>>(nP);

    size_t smemBytes = (size_t)(64 * PAD128 + 2 * 64 * PAD256) * 4 + 64 * 2 * 4;
    cudaFuncSetAttribute(mlp2_kernel, cudaFuncAttributeMaxDynamicSharedMemorySize,
                         (int)smemBytes);
    int nBlocks = (nP + 63) / 64;
    mlp2_kernel<<<nBlocks, 256, smemBytes>>>(feat, Wself, bself, Wclu, bclu,
                                             Wf1, bf1, Wf2, bf2, Wf3, bf3,
                                             out, nP);
}

// round 6
// speedup vs baseline: 2.1417x; 1.1824x over previous
#include <cuda_runtime.h>
#include <math.h>

#define N_P   50000
#define N_HE  5000
#define D_IN  128
#define D_HID 256
#define N_HEADS 4
#define HEAD_DIM 64

#define HE_CAP 256
#define P_CAP  64
#define OVF_CAP 65536

#define PAD128 132
#define PAD256 260

// ---- scratch (no allocation allowed) ----
__device__ float g_he_feat[N_HE * D_IN];
__device__ float g_he_w[N_HE * D_IN];
__device__ float g_cluster[N_P * D_IN];
__device__ int   g_cnt_he[N_HE];
__device__ int   g_cnt_p[N_P];
__device__ float2 g_list_he[N_HE * HE_CAP];
__device__ float2 g_list_p[N_P * P_CAP];
__device__ float4 g_ovf[OVF_CAP];
__device__ int   g_novf;

// ---------------------------------------------------------------------------
__device__ __forceinline__ void red_add_v4(float* dst, float a, float b, float c, float d) {
    asm volatile("red.global.add.v4.f32 [%0], {%1,%2,%3,%4};"
                 :: "l"(dst), "f"(a), "f"(b), "f"(c), "f"(d) : "memory");
}

// ---------------------------------------------------------------------------
__global__ void zero_kernel() {
    int i = blockIdx.x * blockDim.x + threadIdx.x;
    float4 z = make_float4(0.f, 0.f, 0.f, 0.f);
    if (i < N_P * (D_IN / 4))  ((float4*)g_cluster)[i] = z;
    if (i < N_HE * (D_IN / 4)) ((float4*)g_he_feat)[i] = z;
    if (i < N_HE)              g_cnt_he[i] = 0;
    if (i < N_P)               g_cnt_p[i] = 0;
    if (i == 0)                g_novf = 0;
}

// ---------------------------------------------------------------------------
__global__ void fill_kernel(const float* __restrict__ ew,
                            const int* __restrict__ pid,
                            const int* __restrict__ hid,
                            const float* __restrict__ feat, int nE) {
    int e = blockIdx.x * blockDim.x + threadIdx.x;
    if (e >= nE) return;
    int p = pid[e];
    int h = hid[e];
    float w = ew[e];

    int pos = atomicAdd(&g_cnt_he[h], 1);
    if (pos < HE_CAP) {
        g_list_he[(size_t)h * HE_CAP + pos] = make_float2(__int_as_float(p), w);
    } else {
        const float4* fr = (const float4*)(feat + (size_t)p * D_IN);
        for (int i = 0; i < D_IN / 4; i++) {
            float4 v = fr[i];
            red_add_v4(g_he_feat + (size_t)h * D_IN + i * 4,
                       v.x * w, v.y * w, v.z * w, v.w * w);
        }
    }

    int pos2 = atomicAdd(&g_cnt_p[p], 1);
    if (pos2 < P_CAP) {
        g_list_p[(size_t)p * P_CAP + pos2] = make_float2(__int_as_float(h), w);
    } else {
        int o = atomicAdd(&g_novf, 1);
        if (o < OVF_CAP)
            g_ovf[o] = make_float4(__int_as_float(p), __int_as_float(h), w, 0.f);
    }
}

// ---------------------------------------------------------------------------
__global__ __launch_bounds__(128) void he_acc_kernel(const float* __restrict__ feat) {
    __shared__ float2 s_list[HE_CAP];
    int b = blockIdx.x, t = threadIdx.x;
    int n = g_cnt_he[b];
    if (n > HE_CAP) n = HE_CAP;
    for (int i = t; i < n; i += 128) s_list[i] = g_list_he[(size_t)b * HE_CAP + i];
    __syncthreads();

    float acc = g_he_feat[(size_t)b * D_IN + t];
    int i = 0;
    for (; i + 4 <= n; i += 4) {
        float2 e0 = s_list[i], e1 = s_list[i + 1], e2 = s_list[i + 2], e3 = s_list[i + 3];
        float f0 = feat[(size_t)__float_as_int(e0.x) * D_IN + t];
        float f1 = feat[(size_t)__float_as_int(e1.x) * D_IN + t];
        float f2 = feat[(size_t)__float_as_int(e2.x) * D_IN + t];
        float f3 = feat[(size_t)__float_as_int(e3.x) * D_IN + t];
        acc += e0.y * f0;
        acc += e1.y * f1;
        acc += e2.y * f2;
        acc += e3.y * f3;
    }
    for (; i < n; i++) {
        float2 e0 = s_list[i];
        acc += e0.y * feat[(size_t)__float_as_int(e0.x) * D_IN + t];
    }
    g_he_feat[(size_t)b * D_IN + t] = acc;
}

// ---------------------------------------------------------------------------
// MMA machinery
// ---------------------------------------------------------------------------
__device__ __forceinline__ void mma_tf32(float (&c)[4], const unsigned (&a)[4],
                                         unsigned b0, unsigned b1) {
    asm volatile(
        "mma.sync.aligned.m16n8k8.row.col.f32.tf32.tf32.f32 "
        "{%0,%1,%2,%3},{%4,%5,%6,%7},{%8,%9},{%0,%1,%2,%3};\n"
        : "+f"(c[0]), "+f"(c[1]), "+f"(c[2]), "+f"(c[3])
        : "r"(a[0]), "r"(a[1]), "r"(a[2]), "r"(a[3]), "r"(b0), "r"(b1));
}

#define LDSM4(R, ADDR) \
    asm volatile("ldmatrix.sync.aligned.m8n8.x4.shared.b16 {%0,%1,%2,%3},[%4];" \
                 : "=r"((R)[0]), "=r"((R)[1]), "=r"((R)[2]), "=r"((R)[3]) : "r"(ADDR))

__device__ __forceinline__ unsigned smem_u32(const void* p) {
    return (unsigned)__cvta_generic_to_shared(p);
}

__device__ __forceinline__ void split_bits(unsigned x, unsigned& hi, unsigned& lo) {
    hi = x & 0xffffe000u;
    lo = __float_as_uint(__uint_as_float(x) - __uint_as_float(hi));
}

// round-to-nearest f32 -> tf32 (for single-pass path)
__device__ __forceinline__ unsigned to_tf32(unsigned x) {
    unsigned y;
    asm("cvt.rna.tf32.f32 %0, %1;" : "=r"(y) : "f"(__uint_as_float(x)));
    return y;
}

// ---- 3xTF32 (fp32-accurate) ----
template <int KT, int NT>
__device__ __forceinline__ void gemm_stage(const unsigned (&aAddr)[4],
                                           const float* __restrict__ Wp, int N,
                                           float (&acc)[4][NT][4]) {
    unsigned a0[4][4];
    unsigned bb0[NT][2];
#pragma unroll
    for (int mt = 0; mt < 4; mt++) LDSM4(a0[mt], aAddr[mt]);
#pragma unroll
    for (int nt = 0; nt < NT; nt++) {
        bb0[nt][0] = __float_as_uint(__ldg(Wp + nt * 8));
        bb0[nt][1] = __float_as_uint(__ldg(Wp + 4 * N + nt * 8));
    }
#pragma unroll
    for (int kt = 0; kt < KT; kt++) {
        unsigned a1[4][4];
        unsigned bb1[NT][2];
        if (kt + 1 < KT) {
#pragma unroll
            for (int mt = 0; mt < 4; mt++) LDSM4(a1[mt], aAddr[mt] + (kt + 1) * 32u);
            const float* Wk = Wp + (size_t)(kt + 1) * 8 * N;
#pragma unroll
            for (int nt = 0; nt < NT; nt++) {
                bb1[nt][0] = __float_as_uint(__ldg(Wk + nt * 8));
                bb1[nt][1] = __float_as_uint(__ldg(Wk + 4 * N + nt * 8));
            }
        }
        unsigned alo[4][4];
#pragma unroll
        for (int mt = 0; mt < 4; mt++)
#pragma unroll
            for (int i = 0; i < 4; i++) split_bits(a0[mt][i], a0[mt][i], alo[mt][i]);
        unsigned blo[NT][2];
#pragma unroll
        for (int nt = 0; nt < NT; nt++) {
            split_bits(bb0[nt][0], bb0[nt][0], blo[nt][0]);
            split_bits(bb0[nt][1], bb0[nt][1], blo[nt][1]);
        }
#pragma unroll
        for (int nt = 0; nt < NT; nt++)
#pragma unroll
            for (int mt = 0; mt < 4; mt++) {
                mma_tf32(acc[mt][nt], alo[mt], bb0[nt][0], bb0[nt][1]);
                mma_tf32(acc[mt][nt], a0[mt],  blo[nt][0], blo[nt][1]);
                mma_tf32(acc[mt][nt], a0[mt],  bb0[nt][0], bb0[nt][1]);
            }
#pragma unroll
        for (int mt = 0; mt < 4; mt++)
#pragma unroll
            for (int i = 0; i < 4; i++) a0[mt][i] = a1[mt][i];
#pragma unroll
        for (int nt = 0; nt < NT; nt++) {
            bb0[nt][0] = bb1[nt][0];
            bb0[nt][1] = bb1[nt][1];
        }
    }
}

// ---- single-pass tf32 with rounded operands (gate path) ----
template <int KT, int NT>
__device__ __forceinline__ void gemm_stage1(const unsigned (&aAddr)[4],
                                            const float* __restrict__ Wp, int N,
                                            float (&acc)[4][NT][4]) {
    unsigned a0[4][4];
    unsigned bb0[NT][2];
#pragma unroll
    for (int mt = 0; mt < 4; mt++) LDSM4(a0[mt], aAddr[mt]);
#pragma unroll
    for (int nt = 0; nt < NT; nt++) {
        bb0[nt][0] = __float_as_uint(__ldg(Wp + nt * 8));
        bb0[nt][1] = __float_as_uint(__ldg(Wp + 4 * N + nt * 8));
    }
#pragma unroll
    for (int kt = 0; kt < KT; kt++) {
        unsigned a1[4][4];
        unsigned bb1[NT][2];
        if (kt + 1 < KT) {
#pragma unroll
            for (int mt = 0; mt < 4; mt++) LDSM4(a1[mt], aAddr[mt] + (kt + 1) * 32u);
            const float* Wk = Wp + (size_t)(kt + 1) * 8 * N;
#pragma unroll
            for (int nt = 0; nt < NT; nt++) {
                bb1[nt][0] = __float_as_uint(__ldg(Wk + nt * 8));
                bb1[nt][1] = __float_as_uint(__ldg(Wk + 4 * N + nt * 8));
            }
        }
#pragma unroll
        for (int mt = 0; mt < 4; mt++)
#pragma unroll
            for (int i = 0; i < 4; i++) a0[mt][i] = to_tf32(a0[mt][i]);
#pragma unroll
        for (int nt = 0; nt < NT; nt++) {
            bb0[nt][0] = to_tf32(bb0[nt][0]);
            bb0[nt][1] = to_tf32(bb0[nt][1]);
        }
#pragma unroll
        for (int nt = 0; nt < NT; nt++)
#pragma unroll
            for (int mt = 0; mt < 4; mt++)
                mma_tf32(acc[mt][nt], a0[mt], bb0[nt][0], bb0[nt][1]);
#pragma unroll
        for (int mt = 0; mt < 4; mt++)
#pragma unroll
            for (int i = 0; i < 4; i++) a0[mt][i] = a1[mt][i];
#pragma unroll
        for (int nt = 0; nt < NT; nt++) {
            bb0[nt][0] = bb1[nt][0];
            bb0[nt][1] = bb1[nt][1];
        }
    }
}

template <int NT, bool RELU>
__device__ __forceinline__ void epilogue(float* dst, int dstride, int col0,
                                         const float* __restrict__ bias,
                                         float (&acc)[4][NT][4], int lane) {
    int gid = lane >> 2, tig = lane & 3;
#pragma unroll
    for (int nt = 0; nt < NT; nt++) {
        int c = nt * 8 + tig * 2;
        float bA = __ldg(bias + c), bB = __ldg(bias + c + 1);
#pragma unroll
        for (int mt = 0; mt < 4; mt++) {
            int r = mt * 16 + gid;
            float v0 = acc[mt][nt][0] + bA, v1 = acc[mt][nt][1] + bB;
            float v2 = acc[mt][nt][2] + bA, v3 = acc[mt][nt][3] + bB;
            if (RELU) {
                v0 = fmaxf(v0, 0.f); v1 = fmaxf(v1, 0.f);
                v2 = fmaxf(v2, 0.f); v3 = fmaxf(v3, 0.f);
            }
            dst[(size_t)r * dstride + col0 + c]           = v0;
            dst[(size_t)r * dstride + col0 + c + 1]       = v1;
            dst[(size_t)(r + 8) * dstride + col0 + c]     = v2;
            dst[(size_t)(r + 8) * dstride + col0 + c + 1] = v3;
        }
    }
}

// ---------------------------------------------------------------------------
// attention as tiled 3xTF32 GEMM (direct path: keep accurate)
// ---------------------------------------------------------------------------
__global__ __launch_bounds__(256) void attn_gemm_kernel(
    const float* __restrict__ Wh1, const float* __restrict__ bh1,
    const float* __restrict__ Wh2, const float* __restrict__ bh2,
    const float* __restrict__ Wfuse) {
    __shared__ float s_he[64 * PAD128];
    __shared__ float s_part[64][8];
    __shared__ float s_attn[64];

    int row0 = blockIdx.x * 64;
    int t = threadIdx.x, wid = t >> 5, lane = t & 31;

    for (int i = t; i < 64 * 32; i += 256) {
        int r = i >> 5, c4 = i & 31;
        int gr = row0 + r;
        float4 v = make_float4(0.f, 0.f, 0.f, 0.f);
        if (gr < N_HE) v = ((const float4*)g_he_feat)[(size_t)gr * 32 + c4];
        *(float4*)&s_he[(size_t)r * PAD128 + c4 * 4] = v;
    }
    __syncthreads();

    int m8 = lane >> 3, rIn = lane & 7;
    int rowoff = (m8 & 1) * 8 + rIn;
    int coloff = (m8 >> 1) * 4;
    int gid = lane >> 2, tig = lane & 3;

    int head = wid >> 1;
    int colHalf = (wid & 1) * 32;

    float acc[4][4][4];
#pragma unroll
    for (int a = 0; a < 4; a++)
#pragma unroll
        for (int b = 0; b < 4; b++)
#pragma unroll
            for (int c = 0; c < 4; c++) acc[a][b][c] = 0.f;

    unsigned aAddr[4];
#pragma unroll
    for (int mt = 0; mt < 4; mt++)
        aAddr[mt] = smem_u32(s_he + (size_t)(mt * 16 + rowoff) * PAD128 + coloff);

    const float* Wp = Wh1 + (size_t)head * (D_IN * HEAD_DIM)
                    + (size_t)tig * HEAD_DIM + colHalf + gid;
    gemm_stage<16, 4>(aAddr, Wp, HEAD_DIM, acc);

    float p0[4] = {0.f, 0.f, 0.f, 0.f};
    float p1[4] = {0.f, 0.f, 0.f, 0.f};
#pragma unroll
    for (int nt = 0; nt < 4; nt++) {
        int c = head * HEAD_DIM + colHalf + nt * 8 + tig * 2;
        float bA = __ldg(bh1 + c),  bB = __ldg(bh1 + c + 1);
        float wA = __ldg(Wh2 + c),  wB = __ldg(Wh2 + c + 1);
#pragma unroll
        for (int mt = 0; mt < 4; mt++) {
            p0[mt] += fmaxf(acc[mt][nt][0] + bA, 0.f) * wA
                    + fmaxf(acc[mt][nt][1] + bB, 0.f) * wB;
            p1[mt] += fmaxf(acc[mt][nt][2] + bA, 0.f) * wA
                    + fmaxf(acc[mt][nt][3] + bB, 0.f) * wB;
        }
    }
#pragma unroll
    for (int mt = 0; mt < 4; mt++) {
        p0[mt] += __shfl_xor_sync(0xffffffffu, p0[mt], 1);
        p0[mt] += __shfl_xor_sync(0xffffffffu, p0[mt], 2);
        p1[mt] += __shfl_xor_sync(0xffffffffu, p1[mt], 1);
        p1[mt] += __shfl_xor_sync(0xffffffffu, p1[mt], 2);
    }
    if (tig == 0) {
#pragma unroll
        for (int mt = 0; mt < 4; mt++) {
            s_part[mt * 16 + gid][wid]     = p0[mt];
            s_part[mt * 16 + gid + 8][wid] = p1[mt];
        }
    }
    __syncthreads();

    if (t < 64) {
        float a = 0.f;
#pragma unroll
        for (int h = 0; h < N_HEADS; h++) {
            float logit = s_part[t][2 * h] + s_part[t][2 * h + 1] + __ldg(bh2 + h);
            a += __ldg(Wfuse + h) / (1.f + expf(-logit));
        }
        s_attn[t] = a;
    }
    __syncthreads();

    for (int i = t; i < 64 * 32; i += 256) {
        int r = i >> 5, c4 = i & 31;
        int gr = row0 + r;
        if (gr < N_HE) {
            float4 v = *(float4*)&s_he[(size_t)r * PAD128 + c4 * 4];
            float a = s_attn[r];
            v.x *= a; v.y *= a; v.z *= a; v.w *= a;
            ((float4*)g_he_w)[(size_t)gr * 32 + c4] = v;
        }
    }
}

// ---------------------------------------------------------------------------
__global__ void ovf_kernel() {
    int novf = g_novf;
    if (novf > OVF_CAP) novf = OVF_CAP;
    int widg = (blockIdx.x * blockDim.x + threadIdx.x) >> 5;
    int lane = threadIdx.x & 31;
    int nw = (gridDim.x * blockDim.x) >> 5;
    for (int e = widg; e < novf; e += nw) {
        float4 o = g_ovf[e];
        int p = __float_as_int(o.x);
        int h = __float_as_int(o.y);
        float w = o.z;
        float4 v = ((const float4*)(g_he_w + (size_t)h * D_IN))[lane];
        red_add_v4(g_cluster + (size_t)p * D_IN + lane * 4,
                   v.x * w, v.y * w, v.z * w, v.w * w);
    }
}

// ---------------------------------------------------------------------------
__global__ __launch_bounds__(256) void p_acc_kernel(int nP) {
    __shared__ float2 s_list[8][P_CAP];
    int wid = threadIdx.x >> 5, lane = threadIdx.x & 31;
    int p = blockIdx.x * 8 + wid;
    if (p >= nP) return;
    int n = g_cnt_p[p];
    if (n > P_CAP) n = P_CAP;
    for (int i = lane; i < n; i += 32) s_list[wid][i] = g_list_p[(size_t)p * P_CAP + i];
    __syncwarp();

    float4 acc = ((const float4*)(g_cluster + (size_t)p * D_IN))[lane];
    int i = 0;
    for (; i + 2 <= n; i += 2) {
        float2 e0 = s_list[wid][i], e1 = s_list[wid][i + 1];
        float4 v0 = ((const float4*)(g_he_w + (size_t)__float_as_int(e0.x) * D_IN))[lane];
        float4 v1 = ((const float4*)(g_he_w + (size_t)__float_as_int(e1.x) * D_IN))[lane];
        acc.x += e0.y * v0.x; acc.y += e0.y * v0.y;
        acc.z += e0.y * v0.z; acc.w += e0.y * v0.w;
        acc.x += e1.y * v1.x; acc.y += e1.y * v1.y;
        acc.z += e1.y * v1.z; acc.w += e1.y * v1.w;
    }
    if (i < n) {
        float2 e0 = s_list[wid][i];
        float4 v0 = ((const float4*)(g_he_w + (size_t)__float_as_int(e0.x) * D_IN))[lane];
        acc.x += e0.y * v0.x; acc.y += e0.y * v0.y;
        acc.z += e0.y * v0.z; acc.w += e0.y * v0.w;
    }
    ((float4*)(g_cluster + (size_t)p * D_IN))[lane] = acc;
}

// ---------------------------------------------------------------------------
// fused MLP: stage A 3xTF32 (direct path), stages B/C single tf32 (gate path)
// ---------------------------------------------------------------------------
__global__ __launch_bounds__(256, 1) void mlp2_kernel(
    const float* __restrict__ feat,
    const float* __restrict__ Wself, const float* __restrict__ bself,
    const float* __restrict__ Wclu,  const float* __restrict__ bclu,
    const float* __restrict__ Wf1,   const float* __restrict__ bf1,
    const float* __restrict__ Wf2,   const float* __restrict__ bf2,
    const float* __restrict__ Wf3,   const float* __restrict__ bf3,
    float* __restrict__ out, int nP) {
    extern __shared__ float sm[];
    float* s_feat = sm;
    float* s_cat  = s_feat + 64 * PAD128;
    float* s_u1   = s_cat + 64 * PAD256;
    float (*s_gate)[2] = (float (*)[2])(s_u1 + 64 * PAD256);

    int row0 = blockIdx.x * 64;
    int t = threadIdx.x;
    int wid = t >> 5, lane = t & 31;

    const float4* feat4 = (const float4*)feat;
    const float4* clu4  = (const float4*)g_cluster;
    for (int i = t; i < 64 * 32; i += 256) {
        int r = i >> 5, c4 = i & 31;
        int gr = row0 + r;
        float4 f = make_float4(0.f, 0.f, 0.f, 0.f), cl = f;
        if (gr < nP) {
            f  = feat4[(size_t)gr * 32 + c4];
            cl = clu4[(size_t)gr * 32 + c4];
        }
        *(float4*)&s_feat[(size_t)r * PAD128 + c4 * 4] = f;
        *(float4*)&s_u1[(size_t)r * PAD256 + c4 * 4]   = cl;
    }
    __syncthreads();

    int m8  = lane >> 3;
    int rIn = lane & 7;
    int rowoff = (m8 & 1) * 8 + rIn;
    int coloff = (m8 >> 1) * 4;
    int gid = lane >> 2, tig = lane & 3;

    // stage A: self_f | clu_f  (3xTF32, fp32-accurate)
    {
        float acc[4][4][4];
#pragma unroll
        for (int a = 0; a < 4; a++)
#pragma unroll
            for (int b = 0; b < 4; b++)
#pragma unroll
                for (int c = 0; c < 4; c++) acc[a][b][c] = 0.f;

        const float* aBuf   = (wid < 4) ? s_feat : s_u1;
        int          aStr   = (wid < 4) ? PAD128 : PAD256;
        const float* W      = (wid < 4) ? Wself : Wclu;
        const float* bias   = (wid < 4) ? bself : bclu;
        int ncol0           = (wid & 3) * 32;
        int outcol0         = (wid < 4) ? ncol0 : (128 + ncol0);

        unsigned aAddr[4];
#pragma unroll
        for (int mt = 0; mt < 4; mt++)
            aAddr[mt] = smem_u32(aBuf + (size_t)(mt * 16 + rowoff) * aStr + coloff);

        const float* Wp = W + (size_t)tig * 128 + ncol0 + gid;
        gemm_stage<16, 4>(aAddr, Wp, 128, acc);
        __syncthreads();
        epilogue<4, false>(s_cat, PAD256, outcol0, bias + ncol0, acc, lane);
    }
    __syncthreads();

    // stage B: x1 = relu(cat @ Wf1 + bf1)  (single tf32, gate path)
    {
        float acc[4][4][4];
#pragma unroll
        for (int a = 0; a < 4; a++)
#pragma unroll
            for (int b = 0; b < 4; b++)
#pragma unroll
                for (int c = 0; c < 4; c++) acc[a][b][c] = 0.f;

        int ncol0 = wid * 32;
        unsigned aAddr[4];
#pragma unroll
        for (int mt = 0; mt < 4; mt++)
            aAddr[mt] = smem_u32(s_cat + (size_t)(mt * 16 + rowoff) * PAD256 + coloff);
        const float* Wp = Wf1 + (size_t)tig * 256 + ncol0 + gid;
        gemm_stage1<32, 4>(aAddr, Wp, 256, acc);
        __syncthreads();
        epilogue<4, true>(s_u1, PAD256, ncol0, bf1 + ncol0, acc, lane);
    }
    __syncthreads();

    // stage C: x2 = relu(x1 @ Wf2 + bf2)  (single tf32, gate path)
    {
        float acc[4][2][4];
#pragma unroll
        for (int a = 0; a < 4; a++)
#pragma unroll
            for (int b = 0; b < 2; b++)
#pragma unroll
                for (int c = 0; c < 4; c++) acc[a][b][c] = 0.f;

        int ncol0 = wid * 16;
        unsigned aAddr[4];
#pragma unroll
        for (int mt = 0; mt < 4; mt++)
            aAddr[mt] = smem_u32(s_u1 + (size_t)(mt * 16 + rowoff) * PAD256 + coloff);
        const float* Wp = Wf2 + (size_t)tig * 128 + ncol0 + gid;
        gemm_stage1<32, 2>(aAddr, Wp, 128, acc);
        __syncthreads();
        epilogue<2, true>(s_feat, PAD128, ncol0, bf2 + ncol0, acc, lane);
    }
    __syncthreads();

    // stage D: logits (128 threads, 2 per row) + softmax gates
    if (t < 128) {
        int r = t >> 1, l = t & 1;
        float a = __ldg(bf3 + l);
        const float* x = s_feat + (size_t)r * PAD128;
#pragma unroll 4
        for (int k = 0; k < 128; k++)
            a += x[k] * __ldg(Wf3 + 2 * k + l);
        s_gate[r][l] = a;
    }
    __syncthreads();
    if (t < 64) {
        float a = s_gate[t][0], b = s_gate[t][1];
        float m = fmaxf(a, b);
        float e0 = expf(a - m), e1 = expf(b - m);
        float inv = 1.f / (e0 + e1);
        s_gate[t][0] = e0 * inv;
        s_gate[t][1] = e1 * inv;
    }
    __syncthreads();

    // stage E: out = relu(self*g0 + clu*g1 + feat)
    for (int i = t; i < 64 * 32; i += 256) {
        int r = i >> 5, c4 = i & 31;
        int gr = row0 + r;
        if (gr < nP) {
            float4 f = feat4[(size_t)gr * 32 + c4];
            float g0 = s_gate[r][0], g1 = s_gate[r][1];
            const float* sf = s_cat + (size_t)r * PAD256 + c4 * 4;
            const float* sc = sf + 128;
            float4 o;
            o.x = fmaxf(sf[0] * g0 + sc[0] * g1 + f.x, 0.f);
            o.y = fmaxf(sf[1] * g0 + sc[1] * g1 + f.y, 0.f);
            o.z = fmaxf(sf[2] * g0 + sc[2] * g1 + f.z, 0.f);
            o.w = fmaxf(sf[3] * g0 + sc[3] * g1 + f.w, 0.f);
            ((float4*)out)[(size_t)gr * 32 + c4] = o;
        }
    }
}

// ---------------------------------------------------------------------------
extern "C" void kernel_launch(void* const* d_in, const int* in_sizes, int n_in,
                              void* d_out, int out_size) {
    const float* feat   = (const float*)d_in[0];
    const float* edge_w = (const float*)d_in[1];
    const float* Wself  = (const float*)d_in[2];
    const float* bself  = (const float*)d_in[3];
    const float* Wclu   = (const float*)d_in[4];
    const float* bclu   = (const float*)d_in[5];
    const float* Wh1    = (const float*)d_in[6];
    const float* bh1    = (const float*)d_in[7];
    const float* Wh2    = (const float*)d_in[8];
    const float* bh2    = (const float*)d_in[9];
    const float* Wfuse  = (const float*)d_in[10];
    const float* Wf1    = (const float*)d_in[11];
    const float* bf1    = (const float*)d_in[12];
    const float* Wf2    = (const float*)d_in[13];
    const float* bf2    = (const float*)d_in[14];
    const float* Wf3    = (const float*)d_in[15];
    const float* bf3    = (const float*)d_in[16];
    const int*   e_pid  = (const int*)d_in[17];
    const int*   e_hid  = (const int*)d_in[18];

    int nE = in_sizes[17];
    int nP = in_sizes[0] / D_IN;
    float* out = (float*)d_out;

    int zeroN = N_P * (D_IN / 4);
    zero_kernel<<<(zeroN + 255) / 256, 256>>>();

    fill_kernel<<<(nE + 255) / 256, 256>>>(edge_w, e_pid, e_hid, feat, nE);

    he_acc_kernel<<<N_HE, 128>>>(feat);

    attn_gemm_kernel<<<(N_HE + 63) / 64, 256>>>(Wh1, bh1, Wh2, bh2, Wfuse);

    ovf_kernel<<<32, 256>>>();

    p_acc_kernel<<<(nP + 7) / 8, 256>>>(nP);

    size_t smemBytes = (size_t)(64 * PAD128 + 2 * 64 * PAD256) * 4 + 64 * 2 * 4;
    cudaFuncSetAttribute(mlp2_kernel, cudaFuncAttributeMaxDynamicSharedMemorySize,
                         (int)smemBytes);
    int nBlocks = (nP + 63) / 64;
    mlp2_kernel<<<nBlocks, 256, smemBytes>>>(feat, Wself, bself, Wclu, bclu,
                                             Wf1, bf1, Wf2, bf2, Wf3, bf3,
                                             out, nP);
}

// round 7
// speedup vs baseline: 2.1669x; 1.0118x over previous
#include <cuda_runtime.h>
#include <math.h>

#define N_P   50000
#define N_HE  5000
#define D_IN  128
#define D_HID 256
#define N_HEADS 4
#define HEAD_DIM 64

#define HE_CAP 256
#define P_CAP  64
#define OVF_CAP 65536

#define PAD128 132
#define PAD256 260

// ---- scratch (no allocation allowed) ----
__device__ float g_he_feat[N_HE * D_IN];
__device__ float g_he_w[N_HE * D_IN];
__device__ float g_cluster[N_P * D_IN];
__device__ int   g_cnt_he[N_HE];
__device__ int   g_cnt_p[N_P];
__device__ float2 g_list_he[N_HE * HE_CAP];
__device__ float2 g_list_p[N_P * P_CAP];
__device__ float4 g_ovf[OVF_CAP];
__device__ int   g_novf;

// ---------------------------------------------------------------------------
__device__ __forceinline__ void red_add_v4(float* dst, float a, float b, float c, float d) {
    asm volatile("red.global.add.v4.f32 [%0], {%1,%2,%3,%4};"
                 :: "l"(dst), "f"(a), "f"(b), "f"(c), "f"(d) : "memory");
}

// ---------------------------------------------------------------------------
__global__ void zero_kernel() {
    int i = blockIdx.x * blockDim.x + threadIdx.x;
    float4 z = make_float4(0.f, 0.f, 0.f, 0.f);
    if (i < N_P * (D_IN / 4))  ((float4*)g_cluster)[i] = z;
    if (i < N_HE * (D_IN / 4)) ((float4*)g_he_feat)[i] = z;
    if (i < N_HE)              g_cnt_he[i] = 0;
    if (i < N_P)               g_cnt_p[i] = 0;
    if (i == 0)                g_novf = 0;
}

// ---------------------------------------------------------------------------
__global__ void fill_kernel(const float* __restrict__ ew,
                            const int* __restrict__ pid,
                            const int* __restrict__ hid,
                            const float* __restrict__ feat, int nE) {
    int e = blockIdx.x * blockDim.x + threadIdx.x;
    if (e >= nE) return;
    int p = pid[e];
    int h = hid[e];
    float w = ew[e];

    int pos = atomicAdd(&g_cnt_he[h], 1);
    if (pos < HE_CAP) {
        g_list_he[(size_t)h * HE_CAP + pos] = make_float2(__int_as_float(p), w);
    } else {
        const float4* fr = (const float4*)(feat + (size_t)p * D_IN);
        for (int i = 0; i < D_IN / 4; i++) {
            float4 v = fr[i];
            red_add_v4(g_he_feat + (size_t)h * D_IN + i * 4,
                       v.x * w, v.y * w, v.z * w, v.w * w);
        }
    }

    int pos2 = atomicAdd(&g_cnt_p[p], 1);
    if (pos2 < P_CAP) {
        g_list_p[(size_t)p * P_CAP + pos2] = make_float2(__int_as_float(h), w);
    } else {
        int o = atomicAdd(&g_novf, 1);
        if (o < OVF_CAP)
            g_ovf[o] = make_float4(__int_as_float(p), __int_as_float(h), w, 0.f);
    }
}

// ---------------------------------------------------------------------------
__global__ __launch_bounds__(128) void he_acc_kernel(const float* __restrict__ feat) {
    __shared__ float2 s_list[HE_CAP];
    int b = blockIdx.x, t = threadIdx.x;
    int n = g_cnt_he[b];
    if (n > HE_CAP) n = HE_CAP;
    for (int i = t; i < n; i += 128) s_list[i] = g_list_he[(size_t)b * HE_CAP + i];
    __syncthreads();

    float acc = g_he_feat[(size_t)b * D_IN + t];
    int i = 0;
    for (; i + 4 <= n; i += 4) {
        float2 e0 = s_list[i], e1 = s_list[i + 1], e2 = s_list[i + 2], e3 = s_list[i + 3];
        float f0 = feat[(size_t)__float_as_int(e0.x) * D_IN + t];
        float f1 = feat[(size_t)__float_as_int(e1.x) * D_IN + t];
        float f2 = feat[(size_t)__float_as_int(e2.x) * D_IN + t];
        float f3 = feat[(size_t)__float_as_int(e3.x) * D_IN + t];
        acc += e0.y * f0;
        acc += e1.y * f1;
        acc += e2.y * f2;
        acc += e3.y * f3;
    }
    for (; i < n; i++) {
        float2 e0 = s_list[i];
        acc += e0.y * feat[(size_t)__float_as_int(e0.x) * D_IN + t];
    }
    g_he_feat[(size_t)b * D_IN + t] = acc;
}

// ---------------------------------------------------------------------------
// 3xTF32 MMA machinery (templated on M-tiles for occupancy tuning)
// ---------------------------------------------------------------------------
__device__ __forceinline__ void mma_tf32(float (&c)[4], const unsigned (&a)[4],
                                         unsigned b0, unsigned b1) {
    asm volatile(
        "mma.sync.aligned.m16n8k8.row.col.f32.tf32.tf32.f32 "
        "{%0,%1,%2,%3},{%4,%5,%6,%7},{%8,%9},{%0,%1,%2,%3};\n"
        : "+f"(c[0]), "+f"(c[1]), "+f"(c[2]), "+f"(c[3])
        : "r"(a[0]), "r"(a[1]), "r"(a[2]), "r"(a[3]), "r"(b0), "r"(b1));
}

#define LDSM4(R, ADDR) \
    asm volatile("ldmatrix.sync.aligned.m8n8.x4.shared.b16 {%0,%1,%2,%3},[%4];" \
                 : "=r"((R)[0]), "=r"((R)[1]), "=r"((R)[2]), "=r"((R)[3]) : "r"(ADDR))

__device__ __forceinline__ unsigned smem_u32(const void* p) {
    return (unsigned)__cvta_generic_to_shared(p);
}

__device__ __forceinline__ void split_bits(unsigned x, unsigned& hi, unsigned& lo) {
    hi = x & 0xffffe000u;
    lo = __float_as_uint(__uint_as_float(x) - __uint_as_float(hi));
}

// KT k-tiles (K = KT*8), NT n-tiles of 8 cols, MT m-tiles of 16 rows.
template <int KT, int NT, int MT>
__device__ __forceinline__ void gemm_stage(const unsigned (&aAddr)[MT],
                                           const float* __restrict__ Wp, int N,
                                           float (&acc)[MT][NT][4]) {
    unsigned a0[MT][4];
    unsigned bb0[NT][2];
#pragma unroll
    for (int mt = 0; mt < MT; mt++) LDSM4(a0[mt], aAddr[mt]);
#pragma unroll
    for (int nt = 0; nt < NT; nt++) {
        bb0[nt][0] = __float_as_uint(__ldg(Wp + nt * 8));
        bb0[nt][1] = __float_as_uint(__ldg(Wp + 4 * N + nt * 8));
    }
#pragma unroll
    for (int kt = 0; kt < KT; kt++) {
        unsigned a1[MT][4];
        unsigned bb1[NT][2];
        if (kt + 1 < KT) {
#pragma unroll
            for (int mt = 0; mt < MT; mt++) LDSM4(a1[mt], aAddr[mt] + (kt + 1) * 32u);
            const float* Wk = Wp + (size_t)(kt + 1) * 8 * N;
#pragma unroll
            for (int nt = 0; nt < NT; nt++) {
                bb1[nt][0] = __float_as_uint(__ldg(Wk + nt * 8));
                bb1[nt][1] = __float_as_uint(__ldg(Wk + 4 * N + nt * 8));
            }
        }
        unsigned alo[MT][4];
#pragma unroll
        for (int mt = 0; mt < MT; mt++)
#pragma unroll
            for (int i = 0; i < 4; i++) split_bits(a0[mt][i], a0[mt][i], alo[mt][i]);
        unsigned blo[NT][2];
#pragma unroll
        for (int nt = 0; nt < NT; nt++) {
            split_bits(bb0[nt][0], bb0[nt][0], blo[nt][0]);
            split_bits(bb0[nt][1], bb0[nt][1], blo[nt][1]);
        }
#pragma unroll
        for (int nt = 0; nt < NT; nt++)
#pragma unroll
            for (int mt = 0; mt < MT; mt++) {
                mma_tf32(acc[mt][nt], alo[mt], bb0[nt][0], bb0[nt][1]);
                mma_tf32(acc[mt][nt], a0[mt],  blo[nt][0], blo[nt][1]);
                mma_tf32(acc[mt][nt], a0[mt],  bb0[nt][0], bb0[nt][1]);
            }
#pragma unroll
        for (int mt = 0; mt < MT; mt++)
#pragma unroll
            for (int i = 0; i < 4; i++) a0[mt][i] = a1[mt][i];
#pragma unroll
        for (int nt = 0; nt < NT; nt++) {
            bb0[nt][0] = bb1[nt][0];
            bb0[nt][1] = bb1[nt][1];
        }
    }
}

template <int NT, int MT, bool RELU>
__device__ __forceinline__ void epilogue(float* dst, int dstride, int col0,
                                         const float* __restrict__ bias,
                                         float (&acc)[MT][NT][4], int lane) {
    int gid = lane >> 2, tig = lane & 3;
#pragma unroll
    for (int nt = 0; nt < NT; nt++) {
        int c = nt * 8 + tig * 2;
        float bA = __ldg(bias + c), bB = __ldg(bias + c + 1);
#pragma unroll
        for (int mt = 0; mt < MT; mt++) {
            int r = mt * 16 + gid;
            float v0 = acc[mt][nt][0] + bA, v1 = acc[mt][nt][1] + bB;
            float v2 = acc[mt][nt][2] + bA, v3 = acc[mt][nt][3] + bB;
            if (RELU) {
                v0 = fmaxf(v0, 0.f); v1 = fmaxf(v1, 0.f);
                v2 = fmaxf(v2, 0.f); v3 = fmaxf(v3, 0.f);
            }
            dst[(size_t)r * dstride + col0 + c]           = v0;
            dst[(size_t)r * dstride + col0 + c + 1]       = v1;
            dst[(size_t)(r + 8) * dstride + col0 + c]     = v2;
            dst[(size_t)(r + 8) * dstride + col0 + c + 1] = v3;
        }
    }
}

// ---------------------------------------------------------------------------
// attention as tiled 3xTF32 GEMM (64 rows, MT=4 — single wave, unchanged)
// ---------------------------------------------------------------------------
__global__ __launch_bounds__(256) void attn_gemm_kernel(
    const float* __restrict__ Wh1, const float* __restrict__ bh1,
    const float* __restrict__ Wh2, const float* __restrict__ bh2,
    const float* __restrict__ Wfuse) {
    __shared__ float s_he[64 * PAD128];
    __shared__ float s_part[64][8];
    __shared__ float s_attn[64];

    int row0 = blockIdx.x * 64;
    int t = threadIdx.x, wid = t >> 5, lane = t & 31;

    for (int i = t; i < 64 * 32; i += 256) {
        int r = i >> 5, c4 = i & 31;
        int gr = row0 + r;
        float4 v = make_float4(0.f, 0.f, 0.f, 0.f);
        if (gr < N_HE) v = ((const float4*)g_he_feat)[(size_t)gr * 32 + c4];
        *(float4*)&s_he[(size_t)r * PAD128 + c4 * 4] = v;
    }
    __syncthreads();

    int m8 = lane >> 3, rIn = lane & 7;
    int rowoff = (m8 & 1) * 8 + rIn;
    int coloff = (m8 >> 1) * 4;
    int gid = lane >> 2, tig = lane & 3;

    int head = wid >> 1;
    int colHalf = (wid & 1) * 32;

    float acc[4][4][4];
#pragma unroll
    for (int a = 0; a < 4; a++)
#pragma unroll
        for (int b = 0; b < 4; b++)
#pragma unroll
            for (int c = 0; c < 4; c++) acc[a][b][c] = 0.f;

    unsigned aAddr[4];
#pragma unroll
    for (int mt = 0; mt < 4; mt++)
        aAddr[mt] = smem_u32(s_he + (size_t)(mt * 16 + rowoff) * PAD128 + coloff);

    const float* Wp = Wh1 + (size_t)head * (D_IN * HEAD_DIM)
                    + (size_t)tig * HEAD_DIM + colHalf + gid;
    gemm_stage<16, 4, 4>(aAddr, Wp, HEAD_DIM, acc);

    float p0[4] = {0.f, 0.f, 0.f, 0.f};
    float p1[4] = {0.f, 0.f, 0.f, 0.f};
#pragma unroll
    for (int nt = 0; nt < 4; nt++) {
        int c = head * HEAD_DIM + colHalf + nt * 8 + tig * 2;
        float bA = __ldg(bh1 + c),  bB = __ldg(bh1 + c + 1);
        float wA = __ldg(Wh2 + c),  wB = __ldg(Wh2 + c + 1);
#pragma unroll
        for (int mt = 0; mt < 4; mt++) {
            p0[mt] += fmaxf(acc[mt][nt][0] + bA, 0.f) * wA
                    + fmaxf(acc[mt][nt][1] + bB, 0.f) * wB;
            p1[mt] += fmaxf(acc[mt][nt][2] + bA, 0.f) * wA
                    + fmaxf(acc[mt][nt][3] + bB, 0.f) * wB;
        }
    }
#pragma unroll
    for (int mt = 0; mt < 4; mt++) {
        p0[mt] += __shfl_xor_sync(0xffffffffu, p0[mt], 1);
        p0[mt] += __shfl_xor_sync(0xffffffffu, p0[mt], 2);
        p1[mt] += __shfl_xor_sync(0xffffffffu, p1[mt], 1);
        p1[mt] += __shfl_xor_sync(0xffffffffu, p1[mt], 2);
    }
    if (tig == 0) {
#pragma unroll
        for (int mt = 0; mt < 4; mt++) {
            s_part[mt * 16 + gid][wid]     = p0[mt];
            s_part[mt * 16 + gid + 8][wid] = p1[mt];
        }
    }
    __syncthreads();

    if (t < 64) {
        float a = 0.f;
#pragma unroll
        for (int h = 0; h < N_HEADS; h++) {
            float logit = s_part[t][2 * h] + s_part[t][2 * h + 1] + __ldg(bh2 + h);
            a += __ldg(Wfuse + h) / (1.f + expf(-logit));
        }
        s_attn[t] = a;
    }
    __syncthreads();

    for (int i = t; i < 64 * 32; i += 256) {
        int r = i >> 5, c4 = i & 31;
        int gr = row0 + r;
        if (gr < N_HE) {
            float4 v = *(float4*)&s_he[(size_t)r * PAD128 + c4 * 4];
            float a = s_attn[r];
            v.x *= a; v.y *= a; v.z *= a; v.w *= a;
            ((float4*)g_he_w)[(size_t)gr * 32 + c4] = v;
        }
    }
}

// ---------------------------------------------------------------------------
__global__ void ovf_kernel() {
    int novf = g_novf;
    if (novf > OVF_CAP) novf = OVF_CAP;
    int widg = (blockIdx.x * blockDim.x + threadIdx.x) >> 5;
    int lane = threadIdx.x & 31;
    int nw = (gridDim.x * blockDim.x) >> 5;
    for (int e = widg; e < novf; e += nw) {
        float4 o = g_ovf[e];
        int p = __float_as_int(o.x);
        int h = __float_as_int(o.y);
        float w = o.z;
        float4 v = ((const float4*)(g_he_w + (size_t)h * D_IN))[lane];
        red_add_v4(g_cluster + (size_t)p * D_IN + lane * 4,
                   v.x * w, v.y * w, v.z * w, v.w * w);
    }
}

// ---------------------------------------------------------------------------
__global__ __launch_bounds__(256) void p_acc_kernel(int nP) {
    __shared__ float2 s_list[8][P_CAP];
    int wid = threadIdx.x >> 5, lane = threadIdx.x & 31;
    int p = blockIdx.x * 8 + wid;
    if (p >= nP) return;
    int n = g_cnt_p[p];
    if (n > P_CAP) n = P_CAP;
    for (int i = lane; i < n; i += 32) s_list[wid][i] = g_list_p[(size_t)p * P_CAP + i];
    __syncwarp();

    float4 acc = ((const float4*)(g_cluster + (size_t)p * D_IN))[lane];
    int i = 0;
    for (; i + 2 <= n; i += 2) {
        float2 e0 = s_list[wid][i], e1 = s_list[wid][i + 1];
        float4 v0 = ((const float4*)(g_he_w + (size_t)__float_as_int(e0.x) * D_IN))[lane];
        float4 v1 = ((const float4*)(g_he_w + (size_t)__float_as_int(e1.x) * D_IN))[lane];
        acc.x += e0.y * v0.x; acc.y += e0.y * v0.y;
        acc.z += e0.y * v0.z; acc.w += e0.y * v0.w;
        acc.x += e1.y * v1.x; acc.y += e1.y * v1.y;
        acc.z += e1.y * v1.z; acc.w += e1.y * v1.w;
    }
    if (i < n) {
        float2 e0 = s_list[wid][i];
        float4 v0 = ((const float4*)(g_he_w + (size_t)__float_as_int(e0.x) * D_IN))[lane];
        acc.x += e0.y * v0.x; acc.y += e0.y * v0.y;
        acc.z += e0.y * v0.z; acc.w += e0.y * v0.w;
    }
    ((float4*)(g_cluster + (size_t)p * D_IN))[lane] = acc;
}

// ---------------------------------------------------------------------------
// fused MLP, all 3xTF32, 32 rows/block (83.7 KB smem -> 2 blocks/SM)
// ---------------------------------------------------------------------------
__global__ __launch_bounds__(256, 2) void mlp2_kernel(
    const float* __restrict__ feat,
    const float* __restrict__ Wself, const float* __restrict__ bself,
    const float* __restrict__ Wclu,  const float* __restrict__ bclu,
    const float* __restrict__ Wf1,   const float* __restrict__ bf1,
    const float* __restrict__ Wf2,   const float* __restrict__ bf2,
    const float* __restrict__ Wf3,   const float* __restrict__ bf3,
    float* __restrict__ out, int nP) {
    extern __shared__ float sm[];
    float* s_feat = sm;                            // 32 x PAD128 (later x2)
    float* s_cat  = s_feat + 32 * PAD128;          // 32 x PAD256 (self|clu)
    float* s_u1   = s_cat + 32 * PAD256;           // 32 x PAD256 (cluin, then x1)
    float (*s_gate)[2] = (float (*)[2])(s_u1 + 32 * PAD256);

    int row0 = blockIdx.x * 32;
    int t = threadIdx.x;
    int wid = t >> 5, lane = t & 31;

    const float4* feat4 = (const float4*)feat;
    const float4* clu4  = (const float4*)g_cluster;
    for (int i = t; i < 32 * 32; i += 256) {
        int r = i >> 5, c4 = i & 31;
        int gr = row0 + r;
        float4 f = make_float4(0.f, 0.f, 0.f, 0.f), cl = f;
        if (gr < nP) {
            f  = feat4[(size_t)gr * 32 + c4];
            cl = clu4[(size_t)gr * 32 + c4];
        }
        *(float4*)&s_feat[(size_t)r * PAD128 + c4 * 4] = f;
        *(float4*)&s_u1[(size_t)r * PAD256 + c4 * 4]   = cl;
    }
    __syncthreads();

    int m8  = lane >> 3;
    int rIn = lane & 7;
    int rowoff = (m8 & 1) * 8 + rIn;
    int coloff = (m8 >> 1) * 4;
    int gid = lane >> 2, tig = lane & 3;

    // stage A: self_f | clu_f
    {
        float acc[2][4][4];
#pragma unroll
        for (int a = 0; a < 2; a++)
#pragma unroll
            for (int b = 0; b < 4; b++)
#pragma unroll
                for (int c = 0; c < 4; c++) acc[a][b][c] = 0.f;

        const float* aBuf   = (wid < 4) ? s_feat : s_u1;
        int          aStr   = (wid < 4) ? PAD128 : PAD256;
        const float* W      = (wid < 4) ? Wself : Wclu;
        const float* bias   = (wid < 4) ? bself : bclu;
        int ncol0           = (wid & 3) * 32;
        int outcol0         = (wid < 4) ? ncol0 : (128 + ncol0);

        unsigned aAddr[2];
#pragma unroll
        for (int mt = 0; mt < 2; mt++)
            aAddr[mt] = smem_u32(aBuf + (size_t)(mt * 16 + rowoff) * aStr + coloff);

        const float* Wp = W + (size_t)tig * 128 + ncol0 + gid;
        gemm_stage<16, 4, 2>(aAddr, Wp, 128, acc);
        __syncthreads();
        epilogue<4, 2, false>(s_cat, PAD256, outcol0, bias + ncol0, acc, lane);
    }
    __syncthreads();

    // stage B: x1 = relu(cat @ Wf1 + bf1)
    {
        float acc[2][4][4];
#pragma unroll
        for (int a = 0; a < 2; a++)
#pragma unroll
            for (int b = 0; b < 4; b++)
#pragma unroll
                for (int c = 0; c < 4; c++) acc[a][b][c] = 0.f;

        int ncol0 = wid * 32;
        unsigned aAddr[2];
#pragma unroll
        for (int mt = 0; mt < 2; mt++)
            aAddr[mt] = smem_u32(s_cat + (size_t)(mt * 16 + rowoff) * PAD256 + coloff);
        const float* Wp = Wf1 + (size_t)tig * 256 + ncol0 + gid;
        gemm_stage<32, 4, 2>(aAddr, Wp, 256, acc);
        __syncthreads();
        epilogue<4, 2, true>(s_u1, PAD256, ncol0, bf1 + ncol0, acc, lane);
    }
    __syncthreads();

    // stage C: x2 = relu(x1 @ Wf2 + bf2)
    {
        float acc[2][2][4];
#pragma unroll
        for (int a = 0; a < 2; a++)
#pragma unroll
            for (int b = 0; b < 2; b++)
#pragma unroll
                for (int c = 0; c < 4; c++) acc[a][b][c] = 0.f;

        int ncol0 = wid * 16;
        unsigned aAddr[2];
#pragma unroll
        for (int mt = 0; mt < 2; mt++)
            aAddr[mt] = smem_u32(s_u1 + (size_t)(mt * 16 + rowoff) * PAD256 + coloff);
        const float* Wp = Wf2 + (size_t)tig * 128 + ncol0 + gid;
        gemm_stage<32, 2, 2>(aAddr, Wp, 128, acc);
        __syncthreads();
        epilogue<2, 2, true>(s_feat, PAD128, ncol0, bf2 + ncol0, acc, lane);
    }
    __syncthreads();

    // stage D: logits (64 threads, 2 per row) + softmax gates
    if (t < 64) {
        int r = t >> 1, l = t & 1;
        float a = __ldg(bf3 + l);
        const float* x = s_feat + (size_t)r * PAD128;
#pragma unroll 4
        for (int k = 0; k < 128; k++)
            a += x[k] * __ldg(Wf3 + 2 * k + l);
        s_gate[r][l] = a;
    }
    __syncthreads();
    if (t < 32) {
        float a = s_gate[t][0], b = s_gate[t][1];
        float m = fmaxf(a, b);
        float e0 = expf(a - m), e1 = expf(b - m);
        float inv = 1.f / (e0 + e1);
        s_gate[t][0] = e0 * inv;
        s_gate[t][1] = e1 * inv;
    }
    __syncthreads();

    // stage E: out = relu(self*g0 + clu*g1 + feat)
    for (int i = t; i < 32 * 32; i += 256) {
        int r = i >> 5, c4 = i & 31;
        int gr = row0 + r;
        if (gr < nP) {
            float4 f = feat4[(size_t)gr * 32 + c4];
            float g0 = s_gate[r][0], g1 = s_gate[r][1];
            const float* sf = s_cat + (size_t)r * PAD256 + c4 * 4;
            const float* sc = sf + 128;
            float4 o;
            o.x = fmaxf(sf[0] * g0 + sc[0] * g1 + f.x, 0.f);
            o.y = fmaxf(sf[1] * g0 + sc[1] * g1 + f.y, 0.f);
            o.z = fmaxf(sf[2] * g0 + sc[2] * g1 + f.z, 0.f);
            o.w = fmaxf(sf[3] * g0 + sc[3] * g1 + f.w, 0.f);
            ((float4*)out)[(size_t)gr * 32 + c4] = o;
        }
    }
}

// ---------------------------------------------------------------------------
extern "C" void kernel_launch(void* const* d_in, const int* in_sizes, int n_in,
                              void* d_out, int out_size) {
    const float* feat   = (const float*)d_in[0];
    const float* edge_w = (const float*)d_in[1];
    const float* Wself  = (const float*)d_in[2];
    const float* bself  = (const float*)d_in[3];
    const float* Wclu   = (const float*)d_in[4];
    const float* bclu   = (const float*)d_in[5];
    const float* Wh1    = (const float*)d_in[6];
    const float* bh1    = (const float*)d_in[7];
    const float* Wh2    = (const float*)d_in[8];
    const float* bh2    = (const float*)d_in[9];
    const float* Wfuse  = (const float*)d_in[10];
    const float* Wf1    = (const float*)d_in[11];
    const float* bf1    = (const float*)d_in[12];
    const float* Wf2    = (const float*)d_in[13];
    const float* bf2    = (const float*)d_in[14];
    const float* Wf3    = (const float*)d_in[15];
    const float* bf3    = (const float*)d_in[16];
    const int*   e_pid  = (const int*)d_in[17];
    const int*   e_hid  = (const int*)d_in[18];

    int nE = in_sizes[17];
    int nP = in_sizes[0] / D_IN;
    float* out = (float*)d_out;

    int zeroN = N_P * (D_IN / 4);
    zero_kernel<<<(zeroN + 255) / 256, 256>>>();

    fill_kernel<<<(nE + 255) / 256, 256>>>(edge_w, e_pid, e_hid, feat, nE);

    he_acc_kernel<<<N_HE, 128>>>(feat);

    attn_gemm_kernel<<<(N_HE + 63) / 64, 256>>>(Wh1, bh1, Wh2, bh2, Wfuse);

    ovf_kernel<<<32, 256>>>();

    p_acc_kernel<<<(nP + 7) / 8, 256>>>(nP);

    size_t smemBytes = (size_t)(32 * PAD128 + 2 * 32 * PAD256) * 4 + 32 * 2 * 4;
    cudaFuncSetAttribute(mlp2_kernel, cudaFuncAttributeMaxDynamicSharedMemorySize,
                         (int)smemBytes);
    int nBlocks = (nP + 31) / 32;
    mlp2_kernel<<<nBlocks, 256, smemBytes>>>(feat, Wself, bself, Wclu, bclu,
                                             Wf1, bf1, Wf2, bf2, Wf3, bf3,
                                             out, nP);
}

// round 8
// speedup vs baseline: 2.3035x; 1.0630x over previous
#include <cuda_runtime.h>
#include <cuda_bf16.h>
#include <math.h>

#define N_P   50000
#define N_HE  5000
#define D_IN  128
#define D_HID 256
#define N_HEADS 4
#define HEAD_DIM 64

#define HE_CAP 256
#define P_CAP  64
#define OVF_CAP 65536

// bf16 plane strides (in bf16 elems): row bytes must be odd multiple of 16
#define PB128 136   // 272B = 17*16
#define PB256 264   // 528B = 33*16

// packed-weight sections (u32 = bf16 pair along K)
#define OFF_WSELF 0
#define OFF_WCLU  8192
#define OFF_WF1   16384
#define OFF_WF2   49152
#define OFF_WH1   65536
#define PACK_TOTAL 81920

// ---- scratch (no allocation allowed) ----
__device__ float g_he_feat[N_HE * D_IN];
__device__ float g_he_w[N_HE * D_IN];
__device__ float g_cluster[N_P * D_IN];
__device__ int   g_cnt_he[N_HE];
__device__ int   g_cnt_p[N_P];
__device__ float2 g_list_he[N_HE * HE_CAP];
__device__ float2 g_list_p[N_P * P_CAP];
__device__ float4 g_ovf[OVF_CAP];
__device__ int   g_novf;
__device__ unsigned g_Whi[PACK_TOTAL];
__device__ unsigned g_Wlo[PACK_TOTAL];

// ---------------------------------------------------------------------------
__device__ __forceinline__ void red_add_v4(float* dst, float a, float b, float c, float d) {
    asm volatile("red.global.add.v4.f32 [%0], {%1,%2,%3,%4};"
                 :: "l"(dst), "f"(a), "f"(b), "f"(c), "f"(d) : "memory");
}

__device__ __forceinline__ void split_pack(float x0, float x1, unsigned& hi, unsigned& lo) {
    __nv_bfloat16 h0 = __float2bfloat16(x0);
    __nv_bfloat16 h1 = __float2bfloat16(x1);
    __nv_bfloat16 l0 = __float2bfloat16(x0 - __bfloat162float(h0));
    __nv_bfloat16 l1 = __float2bfloat16(x1 - __bfloat162float(h1));
    hi = (unsigned)__bfloat16_as_ushort(h0) | ((unsigned)__bfloat16_as_ushort(h1) << 16);
    lo = (unsigned)__bfloat16_as_ushort(l0) | ((unsigned)__bfloat16_as_ushort(l1) << 16);
}

__device__ __forceinline__ float bfu(unsigned short u) {
    return __bfloat162float(__ushort_as_bfloat16(u));
}

// ---------------------------------------------------------------------------
__global__ void zero_kernel() {
    int i = blockIdx.x * blockDim.x + threadIdx.x;
    float4 z = make_float4(0.f, 0.f, 0.f, 0.f);
    if (i < N_P * (D_IN / 4))  ((float4*)g_cluster)[i] = z;
    if (i < N_HE * (D_IN / 4)) ((float4*)g_he_feat)[i] = z;
    if (i < N_HE)              g_cnt_he[i] = 0;
    if (i < N_P)               g_cnt_p[i] = 0;
    if (i == 0)                g_novf = 0;
}

// ---------------------------------------------------------------------------
// pack weights into bf16 hi/lo pair-planes: packed[k2*N + n] = {W[2k2][n], W[2k2+1][n]}
// ---------------------------------------------------------------------------
__global__ void pack_kernel(const float* __restrict__ Wself, const float* __restrict__ Wclu,
                            const float* __restrict__ Wf1,   const float* __restrict__ Wf2,
                            const float* __restrict__ Wh1) {
    int i = blockIdx.x * blockDim.x + threadIdx.x;
    if (i >= PACK_TOTAL) return;
    const float* W;
    int N, local;
    if (i < OFF_WCLU)      { W = Wself; N = 128; local = i; }
    else if (i < OFF_WF1)  { W = Wclu;  N = 128; local = i - OFF_WCLU; }
    else if (i < OFF_WF2)  { W = Wf1;   N = 256; local = i - OFF_WF1; }
    else if (i < OFF_WH1)  { W = Wf2;   N = 128; local = i - OFF_WF2; }
    else                   { W = Wh1;   N = 64;  local = i - OFF_WH1; }
    int k2 = local / N, n = local % N;
    float w0 = W[(size_t)(2 * k2) * N + n];
    float w1 = W[(size_t)(2 * k2 + 1) * N + n];
    unsigned hi, lo;
    split_pack(w0, w1, hi, lo);
    g_Whi[i] = hi;
    g_Wlo[i] = lo;
}

// ---------------------------------------------------------------------------
__global__ void fill_kernel(const float* __restrict__ ew,
                            const int* __restrict__ pid,
                            const int* __restrict__ hid,
                            const float* __restrict__ feat, int nE) {
    int e = blockIdx.x * blockDim.x + threadIdx.x;
    if (e >= nE) return;
    int p = pid[e];
    int h = hid[e];
    float w = ew[e];

    int pos = atomicAdd(&g_cnt_he[h], 1);
    if (pos < HE_CAP) {
        g_list_he[(size_t)h * HE_CAP + pos] = make_float2(__int_as_float(p), w);
    } else {
        const float4* fr = (const float4*)(feat + (size_t)p * D_IN);
        for (int i = 0; i < D_IN / 4; i++) {
            float4 v = fr[i];
            red_add_v4(g_he_feat + (size_t)h * D_IN + i * 4,
                       v.x * w, v.y * w, v.z * w, v.w * w);
        }
    }

    int pos2 = atomicAdd(&g_cnt_p[p], 1);
    if (pos2 < P_CAP) {
        g_list_p[(size_t)p * P_CAP + pos2] = make_float2(__int_as_float(h), w);
    } else {
        int o = atomicAdd(&g_novf, 1);
        if (o < OVF_CAP)
            g_ovf[o] = make_float4(__int_as_float(p), __int_as_float(h), w, 0.f);
    }
}

// ---------------------------------------------------------------------------
__global__ __launch_bounds__(128) void he_acc_kernel(const float* __restrict__ feat) {
    __shared__ float2 s_list[HE_CAP];
    int b = blockIdx.x, t = threadIdx.x;
    int n = g_cnt_he[b];
    if (n > HE_CAP) n = HE_CAP;
    for (int i = t; i < n; i += 128) s_list[i] = g_list_he[(size_t)b * HE_CAP + i];
    __syncthreads();

    float acc = g_he_feat[(size_t)b * D_IN + t];
    int i = 0;
    for (; i + 4 <= n; i += 4) {
        float2 e0 = s_list[i], e1 = s_list[i + 1], e2 = s_list[i + 2], e3 = s_list[i + 3];
        float f0 = feat[(size_t)__float_as_int(e0.x) * D_IN + t];
        float f1 = feat[(size_t)__float_as_int(e1.x) * D_IN + t];
        float f2 = feat[(size_t)__float_as_int(e2.x) * D_IN + t];
        float f3 = feat[(size_t)__float_as_int(e3.x) * D_IN + t];
        acc += e0.y * f0;
        acc += e1.y * f1;
        acc += e2.y * f2;
        acc += e3.y * f3;
    }
    for (; i < n; i++) {
        float2 e0 = s_list[i];
        acc += e0.y * feat[(size_t)__float_as_int(e0.x) * D_IN + t];
    }
    g_he_feat[(size_t)b * D_IN + t] = acc;
}

// ---------------------------------------------------------------------------
// bf16 MMA machinery (2-way split: ahi*bhi + ahi*blo + alo*bhi)
// ---------------------------------------------------------------------------
__device__ __forceinline__ void mma_bf16(float (&c)[4], const unsigned (&a)[4],
                                         unsigned b0, unsigned b1) {
    asm volatile(
        "mma.sync.aligned.m16n8k16.row.col.f32.bf16.bf16.f32 "
        "{%0,%1,%2,%3},{%4,%5,%6,%7},{%8,%9},{%0,%1,%2,%3};\n"
        : "+f"(c[0]), "+f"(c[1]), "+f"(c[2]), "+f"(c[3])
        : "r"(a[0]), "r"(a[1]), "r"(a[2]), "r"(a[3]), "r"(b0), "r"(b1));
}

#define LDSM4(R, ADDR) \
    asm volatile("ldmatrix.sync.aligned.m8n8.x4.shared.b16 {%0,%1,%2,%3},[%4];" \
                 : "=r"((R)[0]), "=r"((R)[1]), "=r"((R)[2]), "=r"((R)[3]) : "r"(ADDR))

__device__ __forceinline__ unsigned smem_u32(const void* p) {
    return (unsigned)__cvta_generic_to_shared(p);
}

// KT k16-tiles, NT n-tiles of 8 cols, MT m-tiles of 16 rows.
// aAddr: per-lane ldmatrix addresses into HI plane; lo plane at +loOffBytes.
// Whi/Wlo: packed pair arrays, pre-offset per warp; row stride N u32 per k2.
template <int KT, int NT, int MT>
__device__ __forceinline__ void gemm_bf16(const unsigned (&aAddr)[MT], unsigned loOffBytes,
                                          const unsigned* __restrict__ Whi,
                                          const unsigned* __restrict__ Wlo, int N,
                                          float (&acc)[MT][NT][4]) {
    unsigned ah0[MT][4], al0[MT][4];
    unsigned bh0[NT][2], bl0[NT][2];
#pragma unroll
    for (int mt = 0; mt < MT; mt++) {
        LDSM4(ah0[mt], aAddr[mt]);
        LDSM4(al0[mt], aAddr[mt] + loOffBytes);
    }
#pragma unroll
    for (int nt = 0; nt < NT; nt++) {
        bh0[nt][0] = __ldg(Whi + nt * 8);
        bh0[nt][1] = __ldg(Whi + 4 * N + nt * 8);
        bl0[nt][0] = __ldg(Wlo + nt * 8);
        bl0[nt][1] = __ldg(Wlo + 4 * N + nt * 8);
    }
#pragma unroll
    for (int kt = 0; kt < KT; kt++) {
        unsigned ah1[MT][4], al1[MT][4];
        unsigned bh1[NT][2], bl1[NT][2];
        if (kt + 1 < KT) {
#pragma unroll
            for (int mt = 0; mt < MT; mt++) {
                LDSM4(ah1[mt], aAddr[mt] + (kt + 1) * 32u);
                LDSM4(al1[mt], aAddr[mt] + loOffBytes + (kt + 1) * 32u);
            }
            const unsigned* Whik = Whi + (size_t)(kt + 1) * 8 * N;
            const unsigned* Wlok = Wlo + (size_t)(kt + 1) * 8 * N;
#pragma unroll
            for (int nt = 0; nt < NT; nt++) {
                bh1[nt][0] = __ldg(Whik + nt * 8);
                bh1[nt][1] = __ldg(Whik + 4 * N + nt * 8);
                bl1[nt][0] = __ldg(Wlok + nt * 8);
                bl1[nt][1] = __ldg(Wlok + 4 * N + nt * 8);
            }
        }
#pragma unroll
        for (int nt = 0; nt < NT; nt++)
#pragma unroll
            for (int mt = 0; mt < MT; mt++) {
                mma_bf16(acc[mt][nt], al0[mt], bh0[nt][0], bh0[nt][1]);
                mma_bf16(acc[mt][nt], ah0[mt], bl0[nt][0], bl0[nt][1]);
                mma_bf16(acc[mt][nt], ah0[mt], bh0[nt][0], bh0[nt][1]);
            }
#pragma unroll
        for (int mt = 0; mt < MT; mt++)
#pragma unroll
            for (int i = 0; i < 4; i++) { ah0[mt][i] = ah1[mt][i]; al0[mt][i] = al1[mt][i]; }
#pragma unroll
        for (int nt = 0; nt < NT; nt++) {
            bh0[nt][0] = bh1[nt][0]; bh0[nt][1] = bh1[nt][1];
            bl0[nt][0] = bl1[nt][0]; bl0[nt][1] = bl1[nt][1];
        }
    }
}

// fp32 epilogue (stage C writes fp32 x2)
template <int NT, int MT, bool RELU>
__device__ __forceinline__ void epilogue_f32(float* dst, int dstride, int col0,
                                             const float* __restrict__ bias,
                                             float (&acc)[MT][NT][4], int lane) {
    int gid = lane >> 2, tig = lane & 3;
#pragma unroll
    for (int nt = 0; nt < NT; nt++) {
        int c = nt * 8 + tig * 2;
        float bA = __ldg(bias + c), bB = __ldg(bias + c + 1);
#pragma unroll
        for (int mt = 0; mt < MT; mt++) {
            int r = mt * 16 + gid;
            float v0 = acc[mt][nt][0] + bA, v1 = acc[mt][nt][1] + bB;
            float v2 = acc[mt][nt][2] + bA, v3 = acc[mt][nt][3] + bB;
            if (RELU) {
                v0 = fmaxf(v0, 0.f); v1 = fmaxf(v1, 0.f);
                v2 = fmaxf(v2, 0.f); v3 = fmaxf(v3, 0.f);
            }
            dst[(size_t)r * dstride + col0 + c]           = v0;
            dst[(size_t)r * dstride + col0 + c + 1]       = v1;
            dst[(size_t)(r + 8) * dstride + col0 + c]     = v2;
            dst[(size_t)(r + 8) * dstride + col0 + c + 1] = v3;
        }
    }
}

// bf16-plane epilogue: +bias, optional relu, write hi/lo planes (packed u32 pairs)
template <int NT, int MT, bool RELU>
__device__ __forceinline__ void epilogue_bf16(unsigned short* hiBase, int strideElems,
                                              int loOffElems, int col0,
                                              const float* __restrict__ bias,
                                              float (&acc)[MT][NT][4], int lane) {
    int gid = lane >> 2, tig = lane & 3;
#pragma unroll
    for (int nt = 0; nt < NT; nt++) {
        int c = nt * 8 + tig * 2;
        float bA = __ldg(bias + c), bB = __ldg(bias + c + 1);
#pragma unroll
        for (int mt = 0; mt < MT; mt++) {
            int r = mt * 16 + gid;
            float v0 = acc[mt][nt][0] + bA, v1 = acc[mt][nt][1] + bB;
            float v2 = acc[mt][nt][2] + bA, v3 = acc[mt][nt][3] + bB;
            if (RELU) {
                v0 = fmaxf(v0, 0.f); v1 = fmaxf(v1, 0.f);
                v2 = fmaxf(v2, 0.f); v3 = fmaxf(v3, 0.f);
            }
            unsigned h01, l01, h23, l23;
            split_pack(v0, v1, h01, l01);
            split_pack(v2, v3, h23, l23);
            int i0 = r * strideElems + col0 + c;
            int i1 = (r + 8) * strideElems + col0 + c;
            *(unsigned*)&hiBase[i0]               = h01;
            *(unsigned*)&hiBase[loOffElems + i0]  = l01;
            *(unsigned*)&hiBase[i1]               = h23;
            *(unsigned*)&hiBase[loOffElems + i1]  = l23;
        }
    }
}

// load a 32-row x 128-col fp32 tile from gmem into bf16 hi/lo planes
__device__ __forceinline__ void load_tile_planes(unsigned short* plane, int strideElems,
                                                 int loOffElems, const float4* src,
                                                 int row0, int rowMax, int t) {
    for (int i = t; i < 32 * 32; i += 256) {
        int r = i >> 5, c4 = i & 31;
        int gr = row0 + r;
        float4 v = make_float4(0.f, 0.f, 0.f, 0.f);
        if (gr < rowMax) v = src[(size_t)gr * 32 + c4];
        unsigned h01, l01, h23, l23;
        split_pack(v.x, v.y, h01, l01);
        split_pack(v.z, v.w, h23, l23);
        int base = r * strideElems + c4 * 4;
        *(unsigned*)&plane[base]                   = h01;
        *(unsigned*)&plane[base + 2]               = h23;
        *(unsigned*)&plane[loOffElems + base]      = l01;
        *(unsigned*)&plane[loOffElems + base + 2]  = l23;
    }
}

// ---------------------------------------------------------------------------
// attention: 32-row tiles, bf16-split GEMM vs packed Wh1
// ---------------------------------------------------------------------------
__global__ __launch_bounds__(256) void attn_gemm_kernel(
    const float* __restrict__ bh1, const float* __restrict__ Wh2,
    const float* __restrict__ bh2, const float* __restrict__ Wfuse) {
    __shared__ unsigned short s_he[2 * 32 * PB128];
    __shared__ float s_part[32][8];
    __shared__ float s_attn[32];

    int row0 = blockIdx.x * 32;
    int t = threadIdx.x, wid = t >> 5, lane = t & 31;

    load_tile_planes(s_he, PB128, 32 * PB128, (const float4*)g_he_feat, row0, N_HE, t);
    __syncthreads();

    int m8 = lane >> 3, rIn = lane & 7;
    int rowoff = (m8 & 1) * 8 + rIn;
    int colByte = (m8 >> 1) * 16;
    int gid = lane >> 2, tig = lane & 3;

    int head = wid >> 1;
    int colHalf = (wid & 1) * 32;

    float acc[2][4][4];
#pragma unroll
    for (int a = 0; a < 2; a++)
#pragma unroll
        for (int b = 0; b < 4; b++)
#pragma unroll
            for (int c = 0; c < 4; c++) acc[a][b][c] = 0.f;

    unsigned aAddr[2];
#pragma unroll
    for (int mt = 0; mt < 2; mt++)
        aAddr[mt] = smem_u32(s_he + (mt * 16 + rowoff) * PB128) + colByte;

    const unsigned* Whi = g_Whi + OFF_WH1 + head * 4096 + tig * 64 + colHalf + gid;
    const unsigned* Wlo = g_Wlo + OFF_WH1 + head * 4096 + tig * 64 + colHalf + gid;
    gemm_bf16<8, 4, 2>(aAddr, 32 * PB128 * 2, Whi, Wlo, HEAD_DIM, acc);

    float p0[2] = {0.f, 0.f};
    float p1[2] = {0.f, 0.f};
#pragma unroll
    for (int nt = 0; nt < 4; nt++) {
        int c = head * HEAD_DIM + colHalf + nt * 8 + tig * 2;
        float bA = __ldg(bh1 + c),  bB = __ldg(bh1 + c + 1);
        float wA = __ldg(Wh2 + c),  wB = __ldg(Wh2 + c + 1);
#pragma unroll
        for (int mt = 0; mt < 2; mt++) {
            p0[mt] += fmaxf(acc[mt][nt][0] + bA, 0.f) * wA
                    + fmaxf(acc[mt][nt][1] + bB, 0.f) * wB;
            p1[mt] += fmaxf(acc[mt][nt][2] + bA, 0.f) * wA
                    + fmaxf(acc[mt][nt][3] + bB, 0.f) * wB;
        }
    }
#pragma unroll
    for (int mt = 0; mt < 2; mt++) {
        p0[mt] += __shfl_xor_sync(0xffffffffu, p0[mt], 1);
        p0[mt] += __shfl_xor_sync(0xffffffffu, p0[mt], 2);
        p1[mt] += __shfl_xor_sync(0xffffffffu, p1[mt], 1);
        p1[mt] += __shfl_xor_sync(0xffffffffu, p1[mt], 2);
    }
    if (tig == 0) {
#pragma unroll
        for (int mt = 0; mt < 2; mt++) {
            s_part[mt * 16 + gid][wid]     = p0[mt];
            s_part[mt * 16 + gid + 8][wid] = p1[mt];
        }
    }
    __syncthreads();

    if (t < 32) {
        float a = 0.f;
#pragma unroll
        for (int h = 0; h < N_HEADS; h++) {
            float logit = s_part[t][2 * h] + s_part[t][2 * h + 1] + __ldg(bh2 + h);
            a += __ldg(Wfuse + h) / (1.f + expf(-logit));
        }
        s_attn[t] = a;
    }
    __syncthreads();

    for (int i = t; i < 32 * 32; i += 256) {
        int r = i >> 5, c4 = i & 31;
        int gr = row0 + r;
        if (gr < N_HE) {
            float4 v = ((const float4*)g_he_feat)[(size_t)gr * 32 + c4];
            float a = s_attn[r];
            v.x *= a; v.y *= a; v.z *= a; v.w *= a;
            ((float4*)g_he_w)[(size_t)gr * 32 + c4] = v;
        }
    }
}

// ---------------------------------------------------------------------------
__global__ void ovf_kernel() {
    int novf = g_novf;
    if (novf > OVF_CAP) novf = OVF_CAP;
    int widg = (blockIdx.x * blockDim.x + threadIdx.x) >> 5;
    int lane = threadIdx.x & 31;
    int nw = (gridDim.x * blockDim.x) >> 5;
    for (int e = widg; e < novf; e += nw) {
        float4 o = g_ovf[e];
        int p = __float_as_int(o.x);
        int h = __float_as_int(o.y);
        float w = o.z;
        float4 v = ((const float4*)(g_he_w + (size_t)h * D_IN))[lane];
        red_add_v4(g_cluster + (size_t)p * D_IN + lane * 4,
                   v.x * w, v.y * w, v.z * w, v.w * w);
    }
}

// ---------------------------------------------------------------------------
__global__ __launch_bounds__(256) void p_acc_kernel(int nP) {
    __shared__ float2 s_list[8][P_CAP];
    int wid = threadIdx.x >> 5, lane = threadIdx.x & 31;
    int p = blockIdx.x * 8 + wid;
    if (p >= nP) return;
    int n = g_cnt_p[p];
    if (n > P_CAP) n = P_CAP;
    for (int i = lane; i < n; i += 32) s_list[wid][i] = g_list_p[(size_t)p * P_CAP + i];
    __syncwarp();

    float4 acc = ((const float4*)(g_cluster + (size_t)p * D_IN))[lane];
    int i = 0;
    for (; i + 2 <= n; i += 2) {
        float2 e0 = s_list[wid][i], e1 = s_list[wid][i + 1];
        float4 v0 = ((const float4*)(g_he_w + (size_t)__float_as_int(e0.x) * D_IN))[lane];
        float4 v1 = ((const float4*)(g_he_w + (size_t)__float_as_int(e1.x) * D_IN))[lane];
        acc.x += e0.y * v0.x; acc.y += e0.y * v0.y;
        acc.z += e0.y * v0.z; acc.w += e0.y * v0.w;
        acc.x += e1.y * v1.x; acc.y += e1.y * v1.y;
        acc.z += e1.y * v1.z; acc.w += e1.y * v1.w;
    }
    if (i < n) {
        float2 e0 = s_list[wid][i];
        float4 v0 = ((const float4*)(g_he_w + (size_t)__float_as_int(e0.x) * D_IN))[lane];
        acc.x += e0.y * v0.x; acc.y += e0.y * v0.y;
        acc.z += e0.y * v0.z; acc.w += e0.y * v0.w;
    }
    ((float4*)(g_cluster + (size_t)p * D_IN))[lane] = acc;
}

// ---------------------------------------------------------------------------
// fused MLP, all bf16-split, 32 rows/block, ~85 KB smem -> 2 blocks/SM
// smem regions (u16 elems):
//   r1 @0:      2 planes 32xPB128  (feat; stage-C fp32 x2 NOT here)
//   r2 @8704:   2 planes 32xPB256  (cluin -> x1; fp32 x2 overlays after)
//   r3 @25600:  2 planes 32xPB256  (cat = self|clu)
//   gate @42496 (float[32][2])
// ---------------------------------------------------------------------------
#define R1OFF 0
#define R2OFF 8704
#define R3OFF 25600
#define GATEOFF 42496
#define LO128 (32 * PB128)
#define LO256 (32 * PB256)

__global__ __launch_bounds__(256, 2) void mlp2_kernel(
    const float* __restrict__ feat,
    const float* __restrict__ bself, const float* __restrict__ bclu,
    const float* __restrict__ bf1,   const float* __restrict__ bf2,
    const float* __restrict__ Wf3,   const float* __restrict__ bf3,
    float* __restrict__ out, int nP) {
    extern __shared__ unsigned short s16[];
    unsigned short* r1 = s16 + R1OFF;
    unsigned short* r2 = s16 + R2OFF;
    unsigned short* r3 = s16 + R3OFF;
    float (*s_gate)[2] = (float (*)[2])(s16 + GATEOFF);
    float* s_x2 = (float*)r2;   // stage C fp32 output, stride 132

    int row0 = blockIdx.x * 32;
    int t = threadIdx.x;
    int wid = t >> 5, lane = t & 31;

    load_tile_planes(r1, PB128, LO128, (const float4*)feat, row0, nP, t);
    load_tile_planes(r2, PB256, LO256, (const float4*)g_cluster, row0, nP, t);
    __syncthreads();

    int m8 = lane >> 3, rIn = lane & 7;
    int rowoff = (m8 & 1) * 8 + rIn;
    int colByte = (m8 >> 1) * 16;
    int gid = lane >> 2, tig = lane & 3;

    // stage A: self_f | clu_f
    {
        float acc[2][4][4];
#pragma unroll
        for (int a = 0; a < 2; a++)
#pragma unroll
            for (int b = 0; b < 4; b++)
#pragma unroll
                for (int c = 0; c < 4; c++) acc[a][b][c] = 0.f;

        unsigned short* aBuf = (wid < 4) ? r1 : r2;
        int aStr             = (wid < 4) ? PB128 : PB256;
        unsigned loOff       = (wid < 4) ? (LO128 * 2) : (LO256 * 2);
        int wOff             = (wid < 4) ? OFF_WSELF : OFF_WCLU;
        const float* bias    = (wid < 4) ? bself : bclu;
        int ncol0            = (wid & 3) * 32;
        int outcol0          = (wid < 4) ? ncol0 : (128 + ncol0);

        unsigned aAddr[2];
#pragma unroll
        for (int mt = 0; mt < 2; mt++)
            aAddr[mt] = smem_u32(aBuf + (mt * 16 + rowoff) * aStr) + colByte;

        const unsigned* Whi = g_Whi + wOff + tig * 128 + ncol0 + gid;
        const unsigned* Wlo = g_Wlo + wOff + tig * 128 + ncol0 + gid;
        gemm_bf16<8, 4, 2>(aAddr, loOff, Whi, Wlo, 128, acc);
        __syncthreads();
        epilogue_bf16<4, 2, false>(r3, PB256, LO256, outcol0, bias + ncol0, acc, lane);
    }
    __syncthreads();

    // stage B: x1 = relu(cat @ Wf1 + bf1) -> r2 planes
    {
        float acc[2][4][4];
#pragma unroll
        for (int a = 0; a < 2; a++)
#pragma unroll
            for (int b = 0; b < 4; b++)
#pragma unroll
                for (int c = 0; c < 4; c++) acc[a][b][c] = 0.f;

        int ncol0 = wid * 32;
        unsigned aAddr[2];
#pragma unroll
        for (int mt = 0; mt < 2; mt++)
            aAddr[mt] = smem_u32(r3 + (mt * 16 + rowoff) * PB256) + colByte;
        const unsigned* Whi = g_Whi + OFF_WF1 + tig * 256 + ncol0 + gid;
        const unsigned* Wlo = g_Wlo + OFF_WF1 + tig * 256 + ncol0 + gid;
        gemm_bf16<16, 4, 2>(aAddr, LO256 * 2, Whi, Wlo, 256, acc);
        __syncthreads();
        epilogue_bf16<4, 2, true>(r2, PB256, LO256, ncol0, bf1 + ncol0, acc, lane);
    }
    __syncthreads();

    // stage C: x2 = relu(x1 @ Wf2 + bf2) -> fp32 overlay on r2
    {
        float acc[2][2][4];
#pragma unroll
        for (int a = 0; a < 2; a++)
#pragma unroll
            for (int b = 0; b < 2; b++)
#pragma unroll
                for (int c = 0; c < 4; c++) acc[a][b][c] = 0.f;

        int ncol0 = wid * 16;
        unsigned aAddr[2];
#pragma unroll
        for (int mt = 0; mt < 2; mt++)
            aAddr[mt] = smem_u32(r2 + (mt * 16 + rowoff) * PB256) + colByte;
        const unsigned* Whi = g_Whi + OFF_WF2 + tig * 128 + ncol0 + gid;
        const unsigned* Wlo = g_Wlo + OFF_WF2 + tig * 128 + ncol0 + gid;
        gemm_bf16<16, 2, 2>(aAddr, LO256 * 2, Whi, Wlo, 128, acc);
        __syncthreads();   // all x1 reads done before fp32 overlay
        epilogue_f32<2, 2, true>(s_x2, 132, ncol0, bf2 + ncol0, acc, lane);
    }
    __syncthreads();

    // stage D: logits + softmax gates
    if (t < 64) {
        int r = t >> 1, l = t & 1;
        float a = __ldg(bf3 + l);
        const float* x = s_x2 + (size_t)r * 132;
#pragma unroll 4
        for (int k = 0; k < 128; k++)
            a += x[k] * __ldg(Wf3 + 2 * k + l);
        s_gate[r][l] = a;
    }
    __syncthreads();
    if (t < 32) {
        float a = s_gate[t][0], b = s_gate[t][1];
        float m = fmaxf(a, b);
        float e0 = expf(a - m), e1 = expf(b - m);
        float inv = 1.f / (e0 + e1);
        s_gate[t][0] = e0 * inv;
        s_gate[t][1] = e1 * inv;
    }
    __syncthreads();

    // stage E: out = relu(self*g0 + clu*g1 + feat); self/clu = hi+lo from r3
    const float4* feat4 = (const float4*)feat;
    for (int i = t; i < 32 * 32; i += 256) {
        int r = i >> 5, c4 = i & 31;
        int gr = row0 + r;
        if (gr < nP) {
            float4 f = feat4[(size_t)gr * 32 + c4];
            float g0 = s_gate[r][0], g1 = s_gate[r][1];
            int c0 = c4 * 4;
            ushort4 hs = *(const ushort4*)&r3[r * PB256 + c0];
            ushort4 ls = *(const ushort4*)&r3[LO256 + r * PB256 + c0];
            ushort4 hc = *(const ushort4*)&r3[r * PB256 + c0 + 128];
            ushort4 lc = *(const ushort4*)&r3[LO256 + r * PB256 + c0 + 128];
            float4 o;
            o.x = fmaxf((bfu(hs.x) + bfu(ls.x)) * g0 + (bfu(hc.x) + bfu(lc.x)) * g1 + f.x, 0.f);
            o.y = fmaxf((bfu(hs.y) + bfu(ls.y)) * g0 + (bfu(hc.y) + bfu(lc.y)) * g1 + f.y, 0.f);
            o.z = fmaxf((bfu(hs.z) + bfu(ls.z)) * g0 + (bfu(hc.z) + bfu(lc.z)) * g1 + f.z, 0.f);
            o.w = fmaxf((bfu(hs.w) + bfu(ls.w)) * g0 + (bfu(hc.w) + bfu(lc.w)) * g1 + f.w, 0.f);
            ((float4*)out)[(size_t)gr * 32 + c4] = o;
        }
    }
}

// ---------------------------------------------------------------------------
extern "C" void kernel_launch(void* const* d_in, const int* in_sizes, int n_in,
                              void* d_out, int out_size) {
    const float* feat   = (const float*)d_in[0];
    const float* edge_w = (const float*)d_in[1];
    const float* Wself  = (const float*)d_in[2];
    const float* bself  = (const float*)d_in[3];
    const float* Wclu   = (const float*)d_in[4];
    const float* bclu   = (const float*)d_in[5];
    const float* Wh1    = (const float*)d_in[6];
    const float* bh1    = (const float*)d_in[7];
    const float* Wh2    = (const float*)d_in[8];
    const float* bh2    = (const float*)d_in[9];
    const float* Wfuse  = (const float*)d_in[10];
    const float* Wf1    = (const float*)d_in[11];
    const float* bf1    = (const float*)d_in[12];
    const float* Wf2    = (const float*)d_in[13];
    const float* bf2    = (const float*)d_in[14];
    const float* Wf3    = (const float*)d_in[15];
    const float* bf3    = (const float*)d_in[16];
    const int*   e_pid  = (const int*)d_in[17];
    const int*   e_hid  = (const int*)d_in[18];

    int nE = in_sizes[17];
    int nP = in_sizes[0] / D_IN;
    float* out = (float*)d_out;

    int zeroN = N_P * (D_IN / 4);
    zero_kernel<<<(zeroN + 255) / 256, 256>>>();

    pack_kernel<<<(PACK_TOTAL + 255) / 256, 256>>>(Wself, Wclu, Wf1, Wf2, Wh1);

    fill_kernel<<<(nE + 255) / 256, 256>>>(edge_w, e_pid, e_hid, feat, nE);

    he_acc_kernel<<<N_HE, 128>>>(feat);

    attn_gemm_kernel<<<(N_HE + 31) / 32, 256>>>(bh1, Wh2, bh2, Wfuse);

    ovf_kernel<<<32, 256>>>();

    p_acc_kernel<<<(nP + 7) / 8, 256>>>(nP);

    size_t smemBytes = (size_t)GATEOFF * 2 + 32 * 2 * sizeof(float);
    cudaFuncSetAttribute(mlp2_kernel, cudaFuncAttributeMaxDynamicSharedMemorySize,
                         (int)smemBytes);
    int nBlocks = (nP + 31) / 32;
    mlp2_kernel<<<nBlocks, 256, smemBytes>>>(feat, bself, bclu, bf1, bf2,
                                             Wf3, bf3, out, nP);
}

// round 10
// speedup vs baseline: 2.3782x; 1.0324x over previous
#include <cuda_runtime.h>
#include <cuda_bf16.h>
#include <math.h>

#define N_P   50000
#define N_HE  5000
#define D_IN  128
#define D_HID 256
#define N_HEADS 4
#define HEAD_DIM 64

#define HE_CAP 256
#define P_CAP  64
#define OVF_CAP 65536

// bf16 plane strides (in bf16 elems): row bytes odd multiple of 16
#define PB128 136
#define PB256 264

// packed-weight sections (u32 = bf16 pair along K)
#define OFF_WSELF 0
#define OFF_WCLU  8192
#define OFF_WF1   16384
#define OFF_WF2   49152
#define OFF_WH1   65536
#define PACK_TOTAL 81920

// ---- scratch (no allocation allowed) ----
__device__ float g_he_feat[N_HE * D_IN];
__device__ float g_he_w[N_HE * D_IN];
__device__ float g_cluster[N_P * D_IN];
__device__ int   g_cnt_he[N_HE];
__device__ int   g_cnt_p[N_P];
__device__ float2 g_list_he[N_HE * HE_CAP];
__device__ float2 g_list_p[N_P * P_CAP];
__device__ float4 g_ovf[OVF_CAP];
__device__ int   g_novf;
__device__ unsigned g_Whi[PACK_TOTAL];
__device__ unsigned g_Wlo[PACK_TOTAL];

// ---------------------------------------------------------------------------
__device__ __forceinline__ void red_add_v4(float* dst, float a, float b, float c, float d) {
    asm volatile("red.global.add.v4.f32 [%0], {%1,%2,%3,%4};"
                 :: "l"(dst), "f"(a), "f"(b), "f"(c), "f"(d) : "memory");
}

__device__ __forceinline__ void split_pack(float x0, float x1, unsigned& hi, unsigned& lo) {
    __nv_bfloat16 h0 = __float2bfloat16(x0);
    __nv_bfloat16 h1 = __float2bfloat16(x1);
    __nv_bfloat16 l0 = __float2bfloat16(x0 - __bfloat162float(h0));
    __nv_bfloat16 l1 = __float2bfloat16(x1 - __bfloat162float(h1));
    hi = (unsigned)__bfloat16_as_ushort(h0) | ((unsigned)__bfloat16_as_ushort(h1) << 16);
    lo = (unsigned)__bfloat16_as_ushort(l0) | ((unsigned)__bfloat16_as_ushort(l1) << 16);
}

__device__ __forceinline__ float bfu(unsigned short u) {
    return __bfloat162float(__ushort_as_bfloat16(u));
}

// ---------------------------------------------------------------------------
// zero (he_feat + counters only) fused with weight packing
// ---------------------------------------------------------------------------
__global__ void zero_pack_kernel(const float* __restrict__ Wself, const float* __restrict__ Wclu,
                                 const float* __restrict__ Wf1,   const float* __restrict__ Wf2,
                                 const float* __restrict__ Wh1) {
    int i = blockIdx.x * blockDim.x + threadIdx.x;
    if (i < N_HE * (D_IN / 4))
        ((float4*)g_he_feat)[i] = make_float4(0.f, 0.f, 0.f, 0.f);
    if (i < N_HE) g_cnt_he[i] = 0;
    if (i < N_P)  g_cnt_p[i] = 0;
    if (i == 0)   g_novf = 0;
    if (i < PACK_TOTAL) {
        const float* W;
        int N, local;
        if (i < OFF_WCLU)      { W = Wself; N = 128; local = i; }
        else if (i < OFF_WF1)  { W = Wclu;  N = 128; local = i - OFF_WCLU; }
        else if (i < OFF_WF2)  { W = Wf1;   N = 256; local = i - OFF_WF1; }
        else if (i < OFF_WH1)  { W = Wf2;   N = 128; local = i - OFF_WF2; }
        else                   { W = Wh1;   N = 64;  local = i - OFF_WH1; }
        int k2 = local / N, n = local % N;
        unsigned hi, lo;
        split_pack(W[(size_t)(2 * k2) * N + n], W[(size_t)(2 * k2 + 1) * N + n], hi, lo);
        g_Whi[i] = hi;
        g_Wlo[i] = lo;
    }
}

// ---------------------------------------------------------------------------
__global__ void fill_kernel(const float* __restrict__ ew,
                            const int* __restrict__ pid,
                            const int* __restrict__ hid,
                            const float* __restrict__ feat, int nE) {
    int e = blockIdx.x * blockDim.x + threadIdx.x;
    if (e >= nE) return;
    int p = pid[e];
    int h = hid[e];
    float w = ew[e];

    int pos = atomicAdd(&g_cnt_he[h], 1);
    if (pos < HE_CAP) {
        g_list_he[(size_t)h * HE_CAP + pos] = make_float2(__int_as_float(p), w);
    } else {
        const float4* fr = (const float4*)(feat + (size_t)p * D_IN);
        for (int i = 0; i < D_IN / 4; i++) {
            float4 v = fr[i];
            red_add_v4(g_he_feat + (size_t)h * D_IN + i * 4,
                       v.x * w, v.y * w, v.z * w, v.w * w);
        }
    }

    int pos2 = atomicAdd(&g_cnt_p[p], 1);
    if (pos2 < P_CAP) {
        g_list_p[(size_t)p * P_CAP + pos2] = make_float2(__int_as_float(h), w);
    } else {
        int o = atomicAdd(&g_novf, 1);
        if (o < OVF_CAP)
            g_ovf[o] = make_float4(__int_as_float(p), __int_as_float(h), w, 0.f);
    }
}

// ---------------------------------------------------------------------------
// conditional cluster zero: only needed when overflow path will RED into it
// ---------------------------------------------------------------------------
__global__ void zero_cluster_kernel() {
    if (g_novf == 0) return;
    int i = blockIdx.x * blockDim.x + threadIdx.x;
    if (i < N_P * (D_IN / 4))
        ((float4*)g_cluster)[i] = make_float4(0.f, 0.f, 0.f, 0.f);
}

// ---------------------------------------------------------------------------
// he_acc: warp per hyperedge, float4 row loads (one LDG.128 per edge)
// ---------------------------------------------------------------------------
__global__ __launch_bounds__(256) void he_acc_kernel(const float* __restrict__ feat) {
    __shared__ float2 s_list[8][HE_CAP];
    int wid = threadIdx.x >> 5, lane = threadIdx.x & 31;
    int he = blockIdx.x * 8 + wid;
    if (he >= N_HE) return;
    int n_raw = g_cnt_he[he];
    int n = n_raw < HE_CAP ? n_raw : HE_CAP;
    for (int i = lane; i < n; i += 32) s_list[wid][i] = g_list_he[(size_t)he * HE_CAP + i];
    __syncwarp();

    float4 acc = make_float4(0.f, 0.f, 0.f, 0.f);
    if (n_raw > HE_CAP)   // overflow remainder was RED'd into the base row
        acc = ((const float4*)(g_he_feat + (size_t)he * D_IN))[lane];

    const float4* feat4 = (const float4*)feat;
    int i = 0;
    for (; i + 4 <= n; i += 4) {
        float2 e0 = s_list[wid][i],     e1 = s_list[wid][i + 1];
        float2 e2 = s_list[wid][i + 2], e3 = s_list[wid][i + 3];
        float4 v0 = feat4[(size_t)__float_as_int(e0.x) * 32 + lane];
        float4 v1 = feat4[(size_t)__float_as_int(e1.x) * 32 + lane];
        float4 v2 = feat4[(size_t)__float_as_int(e2.x) * 32 + lane];
        float4 v3 = feat4[(size_t)__float_as_int(e3.x) * 32 + lane];
        acc.x += e0.y * v0.x; acc.y += e0.y * v0.y; acc.z += e0.y * v0.z; acc.w += e0.y * v0.w;
        acc.x += e1.y * v1.x; acc.y += e1.y * v1.y; acc.z += e1.y * v1.z; acc.w += e1.y * v1.w;
        acc.x += e2.y * v2.x; acc.y += e2.y * v2.y; acc.z += e2.y * v2.z; acc.w += e2.y * v2.w;
        acc.x += e3.y * v3.x; acc.y += e3.y * v3.y; acc.z += e3.y * v3.z; acc.w += e3.y * v3.w;
    }
    for (; i < n; i++) {
        float2 e0 = s_list[wid][i];
        float4 v0 = feat4[(size_t)__float_as_int(e0.x) * 32 + lane];
        acc.x += e0.y * v0.x; acc.y += e0.y * v0.y; acc.z += e0.y * v0.z; acc.w += e0.y * v0.w;
    }
    ((float4*)(g_he_feat + (size_t)he * D_IN))[lane] = acc;
}

// ---------------------------------------------------------------------------
// bf16 MMA machinery (2-way split: ahi*bhi + ahi*blo + alo*bhi)
// ---------------------------------------------------------------------------
__device__ __forceinline__ void mma_bf16(float (&c)[4], const unsigned (&a)[4],
                                         unsigned b0, unsigned b1) {
    asm volatile(
        "mma.sync.aligned.m16n8k16.row.col.f32.bf16.bf16.f32 "
        "{%0,%1,%2,%3},{%4,%5,%6,%7},{%8,%9},{%0,%1,%2,%3};\n"
        : "+f"(c[0]), "+f"(c[1]), "+f"(c[2]), "+f"(c[3])
        : "r"(a[0]), "r"(a[1]), "r"(a[2]), "r"(a[3]), "r"(b0), "r"(b1));
}

#define LDSM4(R, ADDR) \
    asm volatile("ldmatrix.sync.aligned.m8n8.x4.shared.b16 {%0,%1,%2,%3},[%4];" \
                 : "=r"((R)[0]), "=r"((R)[1]), "=r"((R)[2]), "=r"((R)[3]) : "r"(ADDR))

__device__ __forceinline__ unsigned smem_u32(const void* p) {
    return (unsigned)__cvta_generic_to_shared(p);
}

template <int KT, int NT, int MT>
__device__ __forceinline__ void gemm_bf16(const unsigned (&aAddr)[MT], unsigned loOffBytes,
                                          const unsigned* __restrict__ Whi,
                                          const unsigned* __restrict__ Wlo, int N,
                                          float (&acc)[MT][NT][4]) {
    unsigned ah0[MT][4], al0[MT][4];
    unsigned bh0[NT][2], bl0[NT][2];
#pragma unroll
    for (int mt = 0; mt < MT; mt++) {
        LDSM4(ah0[mt], aAddr[mt]);
        LDSM4(al0[mt], aAddr[mt] + loOffBytes);
    }
#pragma unroll
    for (int nt = 0; nt < NT; nt++) {
        bh0[nt][0] = __ldg(Whi + nt * 8);
        bh0[nt][1] = __ldg(Whi + 4 * N + nt * 8);
        bl0[nt][0] = __ldg(Wlo + nt * 8);
        bl0[nt][1] = __ldg(Wlo + 4 * N + nt * 8);
    }
#pragma unroll
    for (int kt = 0; kt < KT; kt++) {
        unsigned ah1[MT][4], al1[MT][4];
        unsigned bh1[NT][2], bl1[NT][2];
        if (kt + 1 < KT) {
#pragma unroll
            for (int mt = 0; mt < MT; mt++) {
                LDSM4(ah1[mt], aAddr[mt] + (kt + 1) * 32u);
                LDSM4(al1[mt], aAddr[mt] + loOffBytes + (kt + 1) * 32u);
            }
            const unsigned* Whik = Whi + (size_t)(kt + 1) * 8 * N;
            const unsigned* Wlok = Wlo + (size_t)(kt + 1) * 8 * N;
#pragma unroll
            for (int nt = 0; nt < NT; nt++) {
                bh1[nt][0] = __ldg(Whik + nt * 8);
                bh1[nt][1] = __ldg(Whik + 4 * N + nt * 8);
                bl1[nt][0] = __ldg(Wlok + nt * 8);
                bl1[nt][1] = __ldg(Wlok + 4 * N + nt * 8);
            }
        }
#pragma unroll
        for (int nt = 0; nt < NT; nt++)
#pragma unroll
            for (int mt = 0; mt < MT; mt++) {
                mma_bf16(acc[mt][nt], al0[mt], bh0[nt][0], bh0[nt][1]);
                mma_bf16(acc[mt][nt], ah0[mt], bl0[nt][0], bl0[nt][1]);
                mma_bf16(acc[mt][nt], ah0[mt], bh0[nt][0], bh0[nt][1]);
            }
#pragma unroll
        for (int mt = 0; mt < MT; mt++)
#pragma unroll
            for (int i = 0; i < 4; i++) { ah0[mt][i] = ah1[mt][i]; al0[mt][i] = al1[mt][i]; }
#pragma unroll
        for (int nt = 0; nt < NT; nt++) {
            bh0[nt][0] = bh1[nt][0]; bh0[nt][1] = bh1[nt][1];
            bl0[nt][0] = bl1[nt][0]; bl0[nt][1] = bl1[nt][1];
        }
    }
}

template <int NT, int MT, bool RELU>
__device__ __forceinline__ void epilogue_f32(float* dst, int dstride, int col0,
                                             const float* __restrict__ bias,
                                             float (&acc)[MT][NT][4], int lane) {
    int gid = lane >> 2, tig = lane & 3;
#pragma unroll
    for (int nt = 0; nt < NT; nt++) {
        int c = nt * 8 + tig * 2;
        float bA = __ldg(bias + c), bB = __ldg(bias + c + 1);
#pragma unroll
        for (int mt = 0; mt < MT; mt++) {
            int r = mt * 16 + gid;
            float v0 = acc[mt][nt][0] + bA, v1 = acc[mt][nt][1] + bB;
            float v2 = acc[mt][nt][2] + bA, v3 = acc[mt][nt][3] + bB;
            if (RELU) {
                v0 = fmaxf(v0, 0.f); v1 = fmaxf(v1, 0.f);
                v2 = fmaxf(v2, 0.f); v3 = fmaxf(v3, 0.f);
            }
            dst[(size_t)r * dstride + col0 + c]           = v0;
            dst[(size_t)r * dstride + col0 + c + 1]       = v1;
            dst[(size_t)(r + 8) * dstride + col0 + c]     = v2;
            dst[(size_t)(r + 8) * dstride + col0 + c + 1] = v3;
        }
    }
}

template <int NT, int MT, bool RELU>
__device__ __forceinline__ void epilogue_bf16(unsigned short* hiBase, int strideElems,
                                              int loOffElems, int col0,
                                              const float* __restrict__ bias,
                                              float (&acc)[MT][NT][4], int lane) {
    int gid = lane >> 2, tig = lane & 3;
#pragma unroll
    for (int nt = 0; nt < NT; nt++) {
        int c = nt * 8 + tig * 2;
        float bA = __ldg(bias + c), bB = __ldg(bias + c + 1);
#pragma unroll
        for (int mt = 0; mt < MT; mt++) {
            int r = mt * 16 + gid;
            float v0 = acc[mt][nt][0] + bA, v1 = acc[mt][nt][1] + bB;
            float v2 = acc[mt][nt][2] + bA, v3 = acc[mt][nt][3] + bB;
            if (RELU) {
                v0 = fmaxf(v0, 0.f); v1 = fmaxf(v1, 0.f);
                v2 = fmaxf(v2, 0.f); v3 = fmaxf(v3, 0.f);
            }
            unsigned h01, l01, h23, l23;
            split_pack(v0, v1, h01, l01);
            split_pack(v2, v3, h23, l23);
            int i0 = r * strideElems + col0 + c;
            int i1 = (r + 8) * strideElems + col0 + c;
            *(unsigned*)&hiBase[i0]               = h01;
            *(unsigned*)&hiBase[loOffElems + i0]  = l01;
            *(unsigned*)&hiBase[i1]               = h23;
            *(unsigned*)&hiBase[loOffElems + i1]  = l23;
        }
    }
}

__device__ __forceinline__ void load_tile_planes(unsigned short* plane, int strideElems,
                                                 int loOffElems, const float4* src,
                                                 int row0, int rowMax, int t) {
    for (int i = t; i < 32 * 32; i += 256) {
        int r = i >> 5, c4 = i & 31;
        int gr = row0 + r;
        float4 v = make_float4(0.f, 0.f, 0.f, 0.f);
        if (gr < rowMax) v = src[(size_t)gr * 32 + c4];
        unsigned h01, l01, h23, l23;
        split_pack(v.x, v.y, h01, l01);
        split_pack(v.z, v.w, h23, l23);
        int base = r * strideElems + c4 * 4;
        *(unsigned*)&plane[base]                   = h01;
        *(unsigned*)&plane[base + 2]               = h23;
        *(unsigned*)&plane[loOffElems + base]      = l01;
        *(unsigned*)&plane[loOffElems + base + 2]  = l23;
    }
}

// ---------------------------------------------------------------------------
// attention: 32-row tiles, bf16-split GEMM vs packed Wh1
// ---------------------------------------------------------------------------
__global__ __launch_bounds__(256) void attn_gemm_kernel(
    const float* __restrict__ bh1, const float* __restrict__ Wh2,
    const float* __restrict__ bh2, const float* __restrict__ Wfuse) {
    __shared__ unsigned short s_he[2 * 32 * PB128];
    __shared__ float s_part[32][8];
    __shared__ float s_attn[32];

    int row0 = blockIdx.x * 32;
    int t = threadIdx.x, wid = t >> 5, lane = t & 31;

    load_tile_planes(s_he, PB128, 32 * PB128, (const float4*)g_he_feat, row0, N_HE, t);
    __syncthreads();

    int m8 = lane >> 3, rIn = lane & 7;
    int rowoff = (m8 & 1) * 8 + rIn;
    int colByte = (m8 >> 1) * 16;
    int gid = lane >> 2, tig = lane & 3;

    int head = wid >> 1;
    int colHalf = (wid & 1) * 32;

    float acc[2][4][4];
#pragma unroll
    for (int a = 0; a < 2; a++)
#pragma unroll
        for (int b = 0; b < 4; b++)
#pragma unroll
            for (int c = 0; c < 4; c++) acc[a][b][c] = 0.f;

    unsigned aAddr[2];
#pragma unroll
    for (int mt = 0; mt < 2; mt++)
        aAddr[mt] = smem_u32(s_he + (mt * 16 + rowoff) * PB128) + colByte;

    const unsigned* Whi = g_Whi + OFF_WH1 + head * 4096 + tig * 64 + colHalf + gid;
    const unsigned* Wlo = g_Wlo + OFF_WH1 + head * 4096 + tig * 64 + colHalf + gid;
    gemm_bf16<8, 4, 2>(aAddr, 32 * PB128 * 2, Whi, Wlo, HEAD_DIM, acc);

    float p0[2] = {0.f, 0.f};
    float p1[2] = {0.f, 0.f};
#pragma unroll
    for (int nt = 0; nt < 4; nt++) {
        int c = head * HEAD_DIM + colHalf + nt * 8 + tig * 2;
        float bA = __ldg(bh1 + c),  bB = __ldg(bh1 + c + 1);
        float wA = __ldg(Wh2 + c),  wB = __ldg(Wh2 + c + 1);
#pragma unroll
        for (int mt = 0; mt < 2; mt++) {
            p0[mt] += fmaxf(acc[mt][nt][0] + bA, 0.f) * wA
                    + fmaxf(acc[mt][nt][1] + bB, 0.f) * wB;
            p1[mt] += fmaxf(acc[mt][nt][2] + bA, 0.f) * wA
                    + fmaxf(acc[mt][nt][3] + bB, 0.f) * wB;
        }
    }
#pragma unroll
    for (int mt = 0; mt < 2; mt++) {
        p0[mt] += __shfl_xor_sync(0xffffffffu, p0[mt], 1);
        p0[mt] += __shfl_xor_sync(0xffffffffu, p0[mt], 2);
        p1[mt] += __shfl_xor_sync(0xffffffffu, p1[mt], 1);
        p1[mt] += __shfl_xor_sync(0xffffffffu, p1[mt], 2);
    }
    if (tig == 0) {
#pragma unroll
        for (int mt = 0; mt < 2; mt++) {
            s_part[mt * 16 + gid][wid]     = p0[mt];
            s_part[mt * 16 + gid + 8][wid] = p1[mt];
        }
    }
    __syncthreads();

    if (t < 32) {
        float a = 0.f;
#pragma unroll
        for (int h = 0; h < N_HEADS; h++) {
            float logit = s_part[t][2 * h] + s_part[t][2 * h + 1] + __ldg(bh2 + h);
            a += __ldg(Wfuse + h) / (1.f + expf(-logit));
        }
        s_attn[t] = a;
    }
    __syncthreads();

    for (int i = t; i < 32 * 32; i += 256) {
        int r = i >> 5, c4 = i & 31;
        int gr = row0 + r;
        if (gr < N_HE) {
            float4 v = ((const float4*)g_he_feat)[(size_t)gr * 32 + c4];
            float a = s_attn[r];
            v.x *= a; v.y *= a; v.z *= a; v.w *= a;
            ((float4*)g_he_w)[(size_t)gr * 32 + c4] = v;
        }
    }
}

// ---------------------------------------------------------------------------
__global__ void ovf_kernel() {
    int novf = g_novf;
    if (novf > OVF_CAP) novf = OVF_CAP;
    int widg = (blockIdx.x * blockDim.x + threadIdx.x) >> 5;
    int lane = threadIdx.x & 31;
    int nw = (gridDim.x * blockDim.x) >> 5;
    for (int e = widg; e < novf; e += nw) {
        float4 o = g_ovf[e];
        int p = __float_as_int(o.x);
        int h = __float_as_int(o.y);
        float w = o.z;
        float4 v = ((const float4*)(g_he_w + (size_t)h * D_IN))[lane];
        red_add_v4(g_cluster + (size_t)p * D_IN + lane * 4,
                   v.x * w, v.y * w, v.z * w, v.w * w);
    }
}

// ---------------------------------------------------------------------------
__global__ __launch_bounds__(256) void p_acc_kernel(int nP) {
    __shared__ float2 s_list[8][P_CAP];
    int wid = threadIdx.x >> 5, lane = threadIdx.x & 31;
    int p = blockIdx.x * 8 + wid;
    if (p >= nP) return;
    int n = g_cnt_p[p];
    if (n > P_CAP) n = P_CAP;
    for (int i = lane; i < n; i += 32) s_list[wid][i] = g_list_p[(size_t)p * P_CAP + i];
    __syncwarp();

    float4 acc = make_float4(0.f, 0.f, 0.f, 0.f);
    if (g_novf > 0)   // overflow REDs landed in the (then-zeroed) base
        acc = ((const float4*)(g_cluster + (size_t)p * D_IN))[lane];

    int i = 0;
    for (; i + 2 <= n; i += 2) {
        float2 e0 = s_list[wid][i], e1 = s_list[wid][i + 1];
        float4 v0 = ((const float4*)(g_he_w + (size_t)__float_as_int(e0.x) * D_IN))[lane];
        float4 v1 = ((const float4*)(g_he_w + (size_t)__float_as_int(e1.x) * D_IN))[lane];
        acc.x += e0.y * v0.x; acc.y += e0.y * v0.y;
        acc.z += e0.y * v0.z; acc.w += e0.y * v0.w;
        acc.x += e1.y * v1.x; acc.y += e1.y * v1.y;
        acc.z += e1.y * v1.z; acc.w += e1.y * v1.w;
    }
    if (i < n) {
        float2 e0 = s_list[wid][i];
        float4 v0 = ((const float4*)(g_he_w + (size_t)__float_as_int(e0.x) * D_IN))[lane];
        acc.x += e0.y * v0.x; acc.y += e0.y * v0.y;
        acc.z += e0.y * v0.z; acc.w += e0.y * v0.w;
    }
    ((float4*)(g_cluster + (size_t)p * D_IN))[lane] = acc;
}

// ---------------------------------------------------------------------------
// fused MLP, bf16-split, 32 rows/block
// ---------------------------------------------------------------------------
#define R1OFF 0
#define R2OFF 8704
#define R3OFF 25600
#define GATEOFF 42496
#define LO128 (32 * PB128)
#define LO256 (32 * PB256)

__global__ __launch_bounds__(256, 2) void mlp2_kernel(
    const float* __restrict__ feat,
    const float* __restrict__ bself, const float* __restrict__ bclu,
    const float* __restrict__ bf1,   const float* __restrict__ bf2,
    const float* __restrict__ Wf3,   const float* __restrict__ bf3,
    float* __restrict__ out, int nP) {
    extern __shared__ unsigned short s16[];
    unsigned short* r1 = s16 + R1OFF;
    unsigned short* r2 = s16 + R2OFF;
    unsigned short* r3 = s16 + R3OFF;
    float (*s_gate)[2] = (float (*)[2])(s16 + GATEOFF);
    float* s_x2 = (float*)r2;

    int row0 = blockIdx.x * 32;
    int t = threadIdx.x;
    int wid = t >> 5, lane = t & 31;

    load_tile_planes(r1, PB128, LO128, (const float4*)feat, row0, nP, t);
    load_tile_planes(r2, PB256, LO256, (const float4*)g_cluster, row0, nP, t);
    __syncthreads();

    int m8 = lane >> 3, rIn = lane & 7;
    int rowoff = (m8 & 1) * 8 + rIn;
    int colByte = (m8 >> 1) * 16;
    int gid = lane >> 2, tig = lane & 3;

    // stage A
    {
        float acc[2][4][4];
#pragma unroll
        for (int a = 0; a < 2; a++)
#pragma unroll
            for (int b = 0; b < 4; b++)
#pragma unroll
                for (int c = 0; c < 4; c++) acc[a][b][c] = 0.f;

        unsigned short* aBuf = (wid < 4) ? r1 : r2;
        int aStr             = (wid < 4) ? PB128 : PB256;
        unsigned loOff       = (wid < 4) ? (LO128 * 2) : (LO256 * 2);
        int wOff             = (wid < 4) ? OFF_WSELF : OFF_WCLU;
        const float* bias    = (wid < 4) ? bself : bclu;
        int ncol0            = (wid & 3) * 32;
        int outcol0          = (wid < 4) ? ncol0 : (128 + ncol0);

        unsigned aAddr[2];
#pragma unroll
        for (int mt = 0; mt < 2; mt++)
            aAddr[mt] = smem_u32(aBuf + (mt * 16 + rowoff) * aStr) + colByte;

        const unsigned* Whi = g_Whi + wOff + tig * 128 + ncol0 + gid;
        const unsigned* Wlo = g_Wlo + wOff + tig * 128 + ncol0 + gid;
        gemm_bf16<8, 4, 2>(aAddr, loOff, Whi, Wlo, 128, acc);
        __syncthreads();
        epilogue_bf16<4, 2, false>(r3, PB256, LO256, outcol0, bias + ncol0, acc, lane);
    }
    __syncthreads();

    // stage B
    {
        float acc[2][4][4];
#pragma unroll
        for (int a = 0; a < 2; a++)
#pragma unroll
            for (int b = 0; b < 4; b++)
#pragma unroll
                for (int c = 0; c < 4; c++) acc[a][b][c] = 0.f;

        int ncol0 = wid * 32;
        unsigned aAddr[2];
#pragma unroll
        for (int mt = 0; mt < 2; mt++)
            aAddr[mt] = smem_u32(r3 + (mt * 16 + rowoff) * PB256) + colByte;
        const unsigned* Whi = g_Whi + OFF_WF1 + tig * 256 + ncol0 + gid;
        const unsigned* Wlo = g_Wlo + OFF_WF1 + tig * 256 + ncol0 + gid;
        gemm_bf16<16, 4, 2>(aAddr, LO256 * 2, Whi, Wlo, 256, acc);
        __syncthreads();
        epilogue_bf16<4, 2, true>(r2, PB256, LO256, ncol0, bf1 + ncol0, acc, lane);
    }
    __syncthreads();

    // stage C
    {
        float acc[2][2][4];
#pragma unroll
        for (int a = 0; a < 2; a++)
#pragma unroll
            for (int b = 0; b < 2; b++)
#pragma unroll
                for (int c = 0; c < 4; c++) acc[a][b][c] = 0.f;

        int ncol0 = wid * 16;
        unsigned aAddr[2];
#pragma unroll
        for (int mt = 0; mt < 2; mt++)
            aAddr[mt] = smem_u32(r2 + (mt * 16 + rowoff) * PB256) + colByte;
        const unsigned* Whi = g_Whi + OFF_WF2 + tig * 128 + ncol0 + gid;
        const unsigned* Wlo = g_Wlo + OFF_WF2 + tig * 128 + ncol0 + gid;
        gemm_bf16<16, 2, 2>(aAddr, LO256 * 2, Whi, Wlo, 128, acc);
        __syncthreads();
        epilogue_f32<2, 2, true>(s_x2, 132, ncol0, bf2 + ncol0, acc, lane);
    }
    __syncthreads();

    // stage D
    if (t < 64) {
        int r = t >> 1, l = t & 1;
        float a = __ldg(bf3 + l);
        const float* x = s_x2 + (size_t)r * 132;
#pragma unroll 4
        for (int k = 0; k < 128; k++)
            a += x[k] * __ldg(Wf3 + 2 * k + l);
        s_gate[r][l] = a;
    }
    __syncthreads();
    if (t < 32) {
        float a = s_gate[t][0], b = s_gate[t][1];
        float m = fmaxf(a, b);
        float e0 = expf(a - m), e1 = expf(b - m);
        float inv = 1.f / (e0 + e1);
        s_gate[t][0] = e0 * inv;
        s_gate[t][1] = e1 * inv;
    }
    __syncthreads();

    // stage E
    const float4* feat4 = (const float4*)feat;
    for (int i = t; i < 32 * 32; i += 256) {
        int r = i >> 5, c4 = i & 31;
        int gr = row0 + r;
        if (gr < nP) {
            float4 f = feat4[(size_t)gr * 32 + c4];
            float g0 = s_gate[r][0], g1 = s_gate[r][1];
            int c0 = c4 * 4;
            ushort4 hs = *(const ushort4*)&r3[r * PB256 + c0];
            ushort4 ls = *(const ushort4*)&r3[LO256 + r * PB256 + c0];
            ushort4 hc = *(const ushort4*)&r3[r * PB256 + c0 + 128];
            ushort4 lc = *(const ushort4*)&r3[LO256 + r * PB256 + c0 + 128];
            float4 o;
            o.x = fmaxf((bfu(hs.x) + bfu(ls.x)) * g0 + (bfu(hc.x) + bfu(lc.x)) * g1 + f.x, 0.f);
            o.y = fmaxf((bfu(hs.y) + bfu(ls.y)) * g0 + (bfu(hc.y) + bfu(lc.y)) * g1 + f.y, 0.f);
            o.z = fmaxf((bfu(hs.z) + bfu(ls.z)) * g0 + (bfu(hc.z) + bfu(lc.z)) * g1 + f.z, 0.f);
            o.w = fmaxf((bfu(hs.w) + bfu(ls.w)) * g0 + (bfu(hc.w) + bfu(lc.w)) * g1 + f.w, 0.f);
            ((float4*)out)[(size_t)gr * 32 + c4] = o;
        }
    }
}

// ---------------------------------------------------------------------------
extern "C" void kernel_launch(void* const* d_in, const int* in_sizes, int n_in,
                              void* d_out, int out_size) {
    const float* feat   = (const float*)d_in[0];
    const float* edge_w = (const float*)d_in[1];
    const float* Wself  = (const float*)d_in[2];
    const float* bself  = (const float*)d_in[3];
    const float* Wclu   = (const float*)d_in[4];
    const float* bclu   = (const float*)d_in[5];
    const float* Wh1    = (const float*)d_in[6];
    const float* bh1    = (const float*)d_in[7];
    const float* Wh2    = (const float*)d_in[8];
    const float* bh2    = (const float*)d_in[9];
    const float* Wfuse  = (const float*)d_in[10];
    const float* Wf1    = (const float*)d_in[11];
    const float* bf1    = (const float*)d_in[12];
    const float* Wf2    = (const float*)d_in[13];
    const float* bf2    = (const float*)d_in[14];
    const float* Wf3    = (const float*)d_in[15];
    const float* bf3    = (const float*)d_in[16];
    const int*   e_pid  = (const int*)d_in[17];
    const int*   e_hid  = (const int*)d_in[18];

    int nE = in_sizes[17];
    int nP = in_sizes[0] / D_IN;
    float* out = (float*)d_out;

    // zero (he_feat + counters) fused with weight packing
    int zpN = N_HE * (D_IN / 4);   // 160000 covers PACK_TOTAL and counters
    zero_pack_kernel<<<(zpN + 255) / 256, 256>>>(Wself, Wclu, Wf1, Wf2, Wh1);

    fill_kernel<<<(nE + 255) / 256, 256>>>(edge_w, e_pid, e_hid, feat, nE);

    zero_cluster_kernel<<<(N_P * (D_IN / 4) + 255) / 256, 256>>>();

    he_acc_kernel<<<(N_HE + 7) / 8, 256>>>(feat);

    attn_gemm_kernel<<<(N_HE + 31) / 32, 256>>>(bh1, Wh2, bh2, Wfuse);

    ovf_kernel<<<32, 256>>>();

    p_acc_kernel<<<(nP + 7) / 8, 256>>>(nP);

    size_t smemBytes = (size_t)GATEOFF * 2 + 32 * 2 * sizeof(float);
    cudaFuncSetAttribute(mlp2_kernel, cudaFuncAttributeMaxDynamicSharedMemorySize,
                         (int)smemBytes);
    int nBlocks = (nP + 31) / 32;
    mlp2_kernel<<<nBlocks, 256, smemBytes>>>(feat, bself, bclu, bf1, bf2,
                                             Wf3, bf3, out, nP);
}

// round 11
// speedup vs baseline: 2.8441x; 1.1959x over previous
#include <cuda_runtime.h>
#include <cuda_bf16.h>
#include <math.h>

#define N_P   50000
#define N_HE  5000
#define D_IN  128
#define D_HID 256
#define N_HEADS 4
#define HEAD_DIM 64

#define HE_CAP 256
#define P_CAP  64
#define OVF_CAP 65536

// bf16 plane strides (in bf16 elems): row bytes odd multiple of 16
#define PB128 136
#define PB256 264

// packed-weight sections (u32), fragment-order layout (see pack kernel)
#define OFF_WSELF 0
#define OFF_WCLU  8192
#define OFF_WF1   16384
#define OFF_WF2   49152
#define OFF_WH1   65536
#define PACK_TOTAL 81920

// ---- scratch (no allocation allowed) ----
__device__ float g_he_feat[N_HE * D_IN];
__device__ float g_he_w[N_HE * D_IN];
__device__ float g_cluster[N_P * D_IN];
__device__ int   g_cnt_he[N_HE];
__device__ int   g_cnt_p[N_P];
__device__ float2 g_list_he[N_HE * HE_CAP];
__device__ float2 g_list_p[N_P * P_CAP];
__device__ float4 g_ovf[OVF_CAP];
__device__ int   g_novf;
__device__ __align__(16) unsigned g_Whi[PACK_TOTAL];
__device__ __align__(16) unsigned g_Wlo[PACK_TOTAL];

// ---------------------------------------------------------------------------
__device__ __forceinline__ void red_add_v4(float* dst, float a, float b, float c, float d) {
    asm volatile("red.global.add.v4.f32 [%0], {%1,%2,%3,%4};"
                 :: "l"(dst), "f"(a), "f"(b), "f"(c), "f"(d) : "memory");
}

__device__ __forceinline__ void split_pack(float x0, float x1, unsigned& hi, unsigned& lo) {
    __nv_bfloat16 h0 = __float2bfloat16(x0);
    __nv_bfloat16 h1 = __float2bfloat16(x1);
    __nv_bfloat16 l0 = __float2bfloat16(x0 - __bfloat162float(h0));
    __nv_bfloat16 l1 = __float2bfloat16(x1 - __bfloat162float(h1));
    hi = (unsigned)__bfloat16_as_ushort(h0) | ((unsigned)__bfloat16_as_ushort(h1) << 16);
    lo = (unsigned)__bfloat16_as_ushort(l0) | ((unsigned)__bfloat16_as_ushort(l1) << 16);
}

__device__ __forceinline__ float bfu(unsigned short u) {
    return __bfloat162float(__ushort_as_bfloat16(u));
}

// ---------------------------------------------------------------------------
// zero (he_feat + counters) fused with FRAGMENT-ORDER weight packing.
// Packed u32 index within a section:
//   i = ((wb*KT + kt)*32 + lane)*2NT + j
//   j<NT:  b0[nt=j]     -> k2 = kt*8 + tig,     n = wb*NT*8 + j*8 + gid
//   j>=NT: b1[nt=j-NT]  -> k2 = kt*8 + 4 + tig, n = wb*NT*8 + (j-NT)*8 + gid
// where lane = gid*4+tig, u32 = bf16 pair {W[2k2][n], W[2k2+1][n]}.
// A warp then loads its whole per-kt B fragment with NT/2 coalesced LDG.128s.
// ---------------------------------------------------------------------------
__global__ void zero_pack_kernel(const float* __restrict__ Wself, const float* __restrict__ Wclu,
                                 const float* __restrict__ Wf1,   const float* __restrict__ Wf2,
                                 const float* __restrict__ Wh1) {
    int i = blockIdx.x * blockDim.x + threadIdx.x;
    if (i < N_HE * (D_IN / 4))
        ((float4*)g_he_feat)[i] = make_float4(0.f, 0.f, 0.f, 0.f);
    if (i < N_HE) g_cnt_he[i] = 0;
    if (i < N_P)  g_cnt_p[i] = 0;
    if (i == 0)   g_novf = 0;
    if (i < PACK_TOTAL) {
        const float* W;
        int N, K, NT, local;
        if (i < OFF_WCLU)      { W = Wself; N = 128; K = 128; NT = 4; local = i; }
        else if (i < OFF_WF1)  { W = Wclu;  N = 128; K = 128; NT = 4; local = i - OFF_WCLU; }
        else if (i < OFF_WF2)  { W = Wf1;   N = 256; K = 256; NT = 4; local = i - OFF_WF1; }
        else if (i < OFF_WH1)  { W = Wf2;   N = 128; K = 256; NT = 2; local = i - OFF_WF2; }
        else {
            local = i - OFF_WH1;
            int head = local / 4096; local -= head * 4096;
            W = Wh1 + (size_t)head * 128 * 64; N = 64; K = 128; NT = 4;
        }
        int KT = K / 16;
        int twoNT = 2 * NT;
        int j = local % twoNT;  int r = local / twoNT;
        int lane = r % 32;      r /= 32;
        int kt = r % KT;        int wb = r / KT;
        int tig = lane & 3, gid = lane >> 2;
        int nt = (j < NT) ? j : j - NT;
        int k2 = kt * 8 + ((j < NT) ? 0 : 4) + tig;
        int n  = wb * NT * 8 + nt * 8 + gid;
        unsigned hi, lo;
        split_pack(W[(size_t)(2 * k2) * N + n], W[(size_t)(2 * k2 + 1) * N + n], hi, lo);
        g_Whi[i] = hi;
        g_Wlo[i] = lo;
    }
}

// ---------------------------------------------------------------------------
__global__ void fill_kernel(const float* __restrict__ ew,
                            const int* __restrict__ pid,
                            const int* __restrict__ hid,
                            const float* __restrict__ feat, int nE) {
    int e = blockIdx.x * blockDim.x + threadIdx.x;
    if (e >= nE) return;
    int p = pid[e];
    int h = hid[e];
    float w = ew[e];

    int pos = atomicAdd(&g_cnt_he[h], 1);
    if (pos < HE_CAP) {
        g_list_he[(size_t)h * HE_CAP + pos] = make_float2(__int_as_float(p), w);
    } else {
        const float4* fr = (const float4*)(feat + (size_t)p * D_IN);
        for (int i = 0; i < D_IN / 4; i++) {
            float4 v = fr[i];
            red_add_v4(g_he_feat + (size_t)h * D_IN + i * 4,
                       v.x * w, v.y * w, v.z * w, v.w * w);
        }
    }

    int pos2 = atomicAdd(&g_cnt_p[p], 1);
    if (pos2 < P_CAP) {
        g_list_p[(size_t)p * P_CAP + pos2] = make_float2(__int_as_float(h), w);
    } else {
        int o = atomicAdd(&g_novf, 1);
        if (o < OVF_CAP)
            g_ovf[o] = make_float4(__int_as_float(p), __int_as_float(h), w, 0.f);
    }
}

// ---------------------------------------------------------------------------
__global__ void zero_cluster_kernel() {
    if (g_novf == 0) return;
    int i = blockIdx.x * blockDim.x + threadIdx.x;
    if (i < N_P * (D_IN / 4))
        ((float4*)g_cluster)[i] = make_float4(0.f, 0.f, 0.f, 0.f);
}

// ---------------------------------------------------------------------------
// he_acc: 2 warps per hyperedge (even/odd edges), smem pair-combine.
// N_HE = 5000 divisible by 4 -> 1250 full blocks, no guards needed.
// ---------------------------------------------------------------------------
__global__ __launch_bounds__(256) void he_acc_kernel(const float* __restrict__ feat) {
    __shared__ float2 s_list[4][HE_CAP];
    __shared__ float4 s_part[4][32];
    int wid = threadIdx.x >> 5, lane = threadIdx.x & 31;
    int pair = wid >> 1;      // 0..3: hyperedge slot in block
    int half = wid & 1;       // 0/1: which warp of the pair
    int he = blockIdx.x * 4 + pair;

    int n_raw = g_cnt_he[he];
    int n = n_raw < HE_CAP ? n_raw : HE_CAP;
    for (int i = half * 32 + lane; i < n; i += 64)
        s_list[pair][i] = g_list_he[(size_t)he * HE_CAP + i];
    __syncthreads();

    float4 acc = make_float4(0.f, 0.f, 0.f, 0.f);
    if (half == 1 && n_raw > HE_CAP)   // overflow remainder RED'd into base row
        acc = ((const float4*)(g_he_feat + (size_t)he * D_IN))[lane];

    const float4* feat4 = (const float4*)feat;
    int i = half;
    for (; i + 6 < n; i += 8) {
        float2 e0 = s_list[pair][i],     e1 = s_list[pair][i + 2];
        float2 e2 = s_list[pair][i + 4], e3 = s_list[pair][i + 6];
        float4 v0 = feat4[(size_t)__float_as_int(e0.x) * 32 + lane];
        float4 v1 = feat4[(size_t)__float_as_int(e1.x) * 32 + lane];
        float4 v2 = feat4[(size_t)__float_as_int(e2.x) * 32 + lane];
        float4 v3 = feat4[(size_t)__float_as_int(e3.x) * 32 + lane];
        acc.x += e0.y * v0.x; acc.y += e0.y * v0.y; acc.z += e0.y * v0.z; acc.w += e0.y * v0.w;
        acc.x += e1.y * v1.x; acc.y += e1.y * v1.y; acc.z += e1.y * v1.z; acc.w += e1.y * v1.w;
        acc.x += e2.y * v2.x; acc.y += e2.y * v2.y; acc.z += e2.y * v2.z; acc.w += e2.y * v2.w;
        acc.x += e3.y * v3.x; acc.y += e3.y * v3.y; acc.z += e3.y * v3.z; acc.w += e3.y * v3.w;
    }
    for (; i < n; i += 2) {
        float2 e0 = s_list[pair][i];
        float4 v0 = feat4[(size_t)__float_as_int(e0.x) * 32 + lane];
        acc.x += e0.y * v0.x; acc.y += e0.y * v0.y; acc.z += e0.y * v0.z; acc.w += e0.y * v0.w;
    }

    if (half == 1) s_part[pair][lane] = acc;
    __syncthreads();
    if (half == 0) {
        float4 o = s_part[pair][lane];
        acc.x += o.x; acc.y += o.y; acc.z += o.z; acc.w += o.w;
        ((float4*)(g_he_feat + (size_t)he * D_IN))[lane] = acc;
    }
}

// ---------------------------------------------------------------------------
// bf16 MMA machinery; B operands come from fragment-packed arrays via LDG.128
// ---------------------------------------------------------------------------
__device__ __forceinline__ void mma_bf16(float (&c)[4], const unsigned (&a)[4],
                                         unsigned b0, unsigned b1) {
    asm volatile(
        "mma.sync.aligned.m16n8k16.row.col.f32.bf16.bf16.f32 "
        "{%0,%1,%2,%3},{%4,%5,%6,%7},{%8,%9},{%0,%1,%2,%3};\n"
        : "+f"(c[0]), "+f"(c[1]), "+f"(c[2]), "+f"(c[3])
        : "r"(a[0]), "r"(a[1]), "r"(a[2]), "r"(a[3]), "r"(b0), "r"(b1));
}

#define LDSM4(R, ADDR) \
    asm volatile("ldmatrix.sync.aligned.m8n8.x4.shared.b16 {%0,%1,%2,%3},[%4];" \
                 : "=r"((R)[0]), "=r"((R)[1]), "=r"((R)[2]), "=r"((R)[3]) : "r"(ADDR))

__device__ __forceinline__ unsigned smem_u32(const void* p) {
    return (unsigned)__cvta_generic_to_shared(p);
}

// Bhi/Blo: pre-offset per (warp-block, lane) into fragment-packed arrays,
// in uint4 units. Per kt the warp consumes 32*NB4 uint4 (NB4 = NT/2 per lane).
template <int KT, int NT, int MT>
__device__ __forceinline__ void gemm_bf16(const unsigned (&aAddr)[MT], unsigned loOffBytes,
                                          const uint4* __restrict__ Bhi,
                                          const uint4* __restrict__ Blo,
                                          float (&acc)[MT][NT][4]) {
    constexpr int NB4 = NT / 2;
    unsigned ah0[MT][4], al0[MT][4];
    unsigned bh0[2 * NT], bl0[2 * NT];
#pragma unroll
    for (int mt = 0; mt < MT; mt++) {
        LDSM4(ah0[mt], aAddr[mt]);
        LDSM4(al0[mt], aAddr[mt] + loOffBytes);
    }
#pragma unroll
    for (int q = 0; q < NB4; q++) {
        uint4 vh = __ldg(Bhi + q), vl = __ldg(Blo + q);
        bh0[4 * q + 0] = vh.x; bh0[4 * q + 1] = vh.y; bh0[4 * q + 2] = vh.z; bh0[4 * q + 3] = vh.w;
        bl0[4 * q + 0] = vl.x; bl0[4 * q + 1] = vl.y; bl0[4 * q + 2] = vl.z; bl0[4 * q + 3] = vl.w;
    }
#pragma unroll
    for (int kt = 0; kt < KT; kt++) {
        unsigned ah1[MT][4], al1[MT][4];
        unsigned bh1[2 * NT], bl1[2 * NT];
        if (kt + 1 < KT) {
#pragma unroll
            for (int mt = 0; mt < MT; mt++) {
                LDSM4(ah1[mt], aAddr[mt] + (kt + 1) * 32u);
                LDSM4(al1[mt], aAddr[mt] + loOffBytes + (kt + 1) * 32u);
            }
#pragma unroll
            for (int q = 0; q < NB4; q++) {
                uint4 vh = __ldg(Bhi + (size_t)(kt + 1) * 32 * NB4 + q);
                uint4 vl = __ldg(Blo + (size_t)(kt + 1) * 32 * NB4 + q);
                bh1[4 * q + 0] = vh.x; bh1[4 * q + 1] = vh.y; bh1[4 * q + 2] = vh.z; bh1[4 * q + 3] = vh.w;
                bl1[4 * q + 0] = vl.x; bl1[4 * q + 1] = vl.y; bl1[4 * q + 2] = vl.z; bl1[4 * q + 3] = vl.w;
            }
        }
#pragma unroll
        for (int nt = 0; nt < NT; nt++)
#pragma unroll
            for (int mt = 0; mt < MT; mt++) {
                mma_bf16(acc[mt][nt], al0[mt], bh0[nt], bh0[NT + nt]);
                mma_bf16(acc[mt][nt], ah0[mt], bl0[nt], bl0[NT + nt]);
                mma_bf16(acc[mt][nt], ah0[mt], bh0[nt], bh0[NT + nt]);
            }
#pragma unroll
        for (int mt = 0; mt < MT; mt++)
#pragma unroll
            for (int i = 0; i < 4; i++) { ah0[mt][i] = ah1[mt][i]; al0[mt][i] = al1[mt][i]; }
#pragma unroll
        for (int j = 0; j < 2 * NT; j++) { bh0[j] = bh1[j]; bl0[j] = bl1[j]; }
    }
}

template <int NT, int MT, bool RELU>
__device__ __forceinline__ void epilogue_f32(float* dst, int dstride, int col0,
                                             const float* __restrict__ bias,
                                             float (&acc)[MT][NT][4], int lane) {
    int gid = lane >> 2, tig = lane & 3;
#pragma unroll
    for (int nt = 0; nt < NT; nt++) {
        int c = nt * 8 + tig * 2;
        float bA = __ldg(bias + c), bB = __ldg(bias + c + 1);
#pragma unroll
        for (int mt = 0; mt < MT; mt++) {
            int r = mt * 16 + gid;
            float v0 = acc[mt][nt][0] + bA, v1 = acc[mt][nt][1] + bB;
            float v2 = acc[mt][nt][2] + bA, v3 = acc[mt][nt][3] + bB;
            if (RELU) {
                v0 = fmaxf(v0, 0.f); v1 = fmaxf(v1, 0.f);
                v2 = fmaxf(v2, 0.f); v3 = fmaxf(v3, 0.f);
            }
            dst[(size_t)r * dstride + col0 + c]           = v0;
            dst[(size_t)r * dstride + col0 + c + 1]       = v1;
            dst[(size_t)(r + 8) * dstride + col0 + c]     = v2;
            dst[(size_t)(r + 8) * dstride + col0 + c + 1] = v3;
        }
    }
}

template <int NT, int MT, bool RELU>
__device__ __forceinline__ void epilogue_bf16(unsigned short* hiBase, int strideElems,
                                              int loOffElems, int col0,
                                              const float* __restrict__ bias,
                                              float (&acc)[MT][NT][4], int lane) {
    int gid = lane >> 2, tig = lane & 3;
#pragma unroll
    for (int nt = 0; nt < NT; nt++) {
        int c = nt * 8 + tig * 2;
        float bA = __ldg(bias + c), bB = __ldg(bias + c + 1);
#pragma unroll
        for (int mt = 0; mt < MT; mt++) {
            int r = mt * 16 + gid;
            float v0 = acc[mt][nt][0] + bA, v1 = acc[mt][nt][1] + bB;
            float v2 = acc[mt][nt][2] + bA, v3 = acc[mt][nt][3] + bB;
            if (RELU) {
                v0 = fmaxf(v0, 0.f); v1 = fmaxf(v1, 0.f);
                v2 = fmaxf(v2, 0.f); v3 = fmaxf(v3, 0.f);
            }
            unsigned h01, l01, h23, l23;
            split_pack(v0, v1, h01, l01);
            split_pack(v2, v3, h23, l23);
            int i0 = r * strideElems + col0 + c;
            int i1 = (r + 8) * strideElems + col0 + c;
            *(unsigned*)&hiBase[i0]               = h01;
            *(unsigned*)&hiBase[loOffElems + i0]  = l01;
            *(unsigned*)&hiBase[i1]               = h23;
            *(unsigned*)&hiBase[loOffElems + i1]  = l23;
        }
    }
}

__device__ __forceinline__ void load_tile_planes(unsigned short* plane, int strideElems,
                                                 int loOffElems, const float4* src,
                                                 int row0, int rowMax, int t) {
    for (int i = t; i < 32 * 32; i += 256) {
        int r = i >> 5, c4 = i & 31;
        int gr = row0 + r;
        float4 v = make_float4(0.f, 0.f, 0.f, 0.f);
        if (gr < rowMax) v = src[(size_t)gr * 32 + c4];
        unsigned h01, l01, h23, l23;
        split_pack(v.x, v.y, h01, l01);
        split_pack(v.z, v.w, h23, l23);
        int base = r * strideElems + c4 * 4;
        *(unsigned*)&plane[base]                   = h01;
        *(unsigned*)&plane[base + 2]               = h23;
        *(unsigned*)&plane[loOffElems + base]      = l01;
        *(unsigned*)&plane[loOffElems + base + 2]  = l23;
    }
}

// ---------------------------------------------------------------------------
// attention: 32-row tiles, bf16-split GEMM vs fragment-packed Wh1
// ---------------------------------------------------------------------------
__global__ __launch_bounds__(256) void attn_gemm_kernel(
    const float* __restrict__ bh1, const float* __restrict__ Wh2,
    const float* __restrict__ bh2, const float* __restrict__ Wfuse) {
    __shared__ unsigned short s_he[2 * 32 * PB128];
    __shared__ float s_part[32][8];
    __shared__ float s_attn[32];

    int row0 = blockIdx.x * 32;
    int t = threadIdx.x, wid = t >> 5, lane = t & 31;

    load_tile_planes(s_he, PB128, 32 * PB128, (const float4*)g_he_feat, row0, N_HE, t);
    __syncthreads();

    int m8 = lane >> 3, rIn = lane & 7;
    int rowoff = (m8 & 1) * 8 + rIn;
    int colByte = (m8 >> 1) * 16;
    int gid = lane >> 2, tig = lane & 3;

    int head = wid >> 1;
    int colHalf = (wid & 1) * 32;

    float acc[2][4][4];
#pragma unroll
    for (int a = 0; a < 2; a++)
#pragma unroll
        for (int b = 0; b < 4; b++)
#pragma unroll
            for (int c = 0; c < 4; c++) acc[a][b][c] = 0.f;

    unsigned aAddr[2];
#pragma unroll
    for (int mt = 0; mt < 2; mt++)
        aAddr[mt] = smem_u32(s_he + (mt * 16 + rowoff) * PB128) + colByte;

    // fragment-packed: section off = OFF_WH1 + head*4096; wb = wid&1, KT=8, NT=4
    size_t fidx = ((size_t)((wid & 1) * 8) * 32 + lane) * 2;
    const uint4* Bhi = (const uint4*)(g_Whi + OFF_WH1 + head * 4096) + fidx;
    const uint4* Blo = (const uint4*)(g_Wlo + OFF_WH1 + head * 4096) + fidx;
    gemm_bf16<8, 4, 2>(aAddr, 32 * PB128 * 2, Bhi, Blo, acc);

    float p0[2] = {0.f, 0.f};
    float p1[2] = {0.f, 0.f};
#pragma unroll
    for (int nt = 0; nt < 4; nt++) {
        int c = head * HEAD_DIM + colHalf + nt * 8 + tig * 2;
        float bA = __ldg(bh1 + c),  bB = __ldg(bh1 + c + 1);
        float wA = __ldg(Wh2 + c),  wB = __ldg(Wh2 + c + 1);
#pragma unroll
        for (int mt = 0; mt < 2; mt++) {
            p0[mt] += fmaxf(acc[mt][nt][0] + bA, 0.f) * wA
                    + fmaxf(acc[mt][nt][1] + bB, 0.f) * wB;
            p1[mt] += fmaxf(acc[mt][nt][2] + bA, 0.f) * wA
                    + fmaxf(acc[mt][nt][3] + bB, 0.f) * wB;
        }
    }
#pragma unroll
    for (int mt = 0; mt < 2; mt++) {
        p0[mt] += __shfl_xor_sync(0xffffffffu, p0[mt], 1);
        p0[mt] += __shfl_xor_sync(0xffffffffu, p0[mt], 2);
        p1[mt] += __shfl_xor_sync(0xffffffffu, p1[mt], 1);
        p1[mt] += __shfl_xor_sync(0xffffffffu, p1[mt], 2);
    }
    if (tig == 0) {
#pragma unroll
        for (int mt = 0; mt < 2; mt++) {
            s_part[mt * 16 + gid][wid]     = p0[mt];
            s_part[mt * 16 + gid + 8][wid] = p1[mt];
        }
    }
    __syncthreads();

    if (t < 32) {
        float a = 0.f;
#pragma unroll
        for (int h = 0; h < N_HEADS; h++) {
            float logit = s_part[t][2 * h] + s_part[t][2 * h + 1] + __ldg(bh2 + h);
            a += __ldg(Wfuse + h) / (1.f + expf(-logit));
        }
        s_attn[t] = a;
    }
    __syncthreads();

    for (int i = t; i < 32 * 32; i += 256) {
        int r = i >> 5, c4 = i & 31;
        int gr = row0 + r;
        if (gr < N_HE) {
            float4 v = ((const float4*)g_he_feat)[(size_t)gr * 32 + c4];
            float a = s_attn[r];
            v.x *= a; v.y *= a; v.z *= a; v.w *= a;
            ((float4*)g_he_w)[(size_t)gr * 32 + c4] = v;
        }
    }
}

// ---------------------------------------------------------------------------
__global__ void ovf_kernel() {
    int novf = g_novf;
    if (novf > OVF_CAP) novf = OVF_CAP;
    int widg = (blockIdx.x * blockDim.x + threadIdx.x) >> 5;
    int lane = threadIdx.x & 31;
    int nw = (gridDim.x * blockDim.x) >> 5;
    for (int e = widg; e < novf; e += nw) {
        float4 o = g_ovf[e];
        int p = __float_as_int(o.x);
        int h = __float_as_int(o.y);
        float w = o.z;
        float4 v = ((const float4*)(g_he_w + (size_t)h * D_IN))[lane];
        red_add_v4(g_cluster + (size_t)p * D_IN + lane * 4,
                   v.x * w, v.y * w, v.z * w, v.w * w);
    }
}

// ---------------------------------------------------------------------------
__global__ __launch_bounds__(256) void p_acc_kernel(int nP) {
    __shared__ float2 s_list[8][P_CAP];
    int wid = threadIdx.x >> 5, lane = threadIdx.x & 31;
    int p = blockIdx.x * 8 + wid;
    if (p >= nP) return;
    int n = g_cnt_p[p];
    if (n > P_CAP) n = P_CAP;
    for (int i = lane; i < n; i += 32) s_list[wid][i] = g_list_p[(size_t)p * P_CAP + i];
    __syncwarp();

    float4 acc = make_float4(0.f, 0.f, 0.f, 0.f);
    if (g_novf > 0)
        acc = ((const float4*)(g_cluster + (size_t)p * D_IN))[lane];

    const float4* hw4 = (const float4*)g_he_w;
    int i = 0;
    for (; i + 4 <= n; i += 4) {
        float2 e0 = s_list[wid][i],     e1 = s_list[wid][i + 1];
        float2 e2 = s_list[wid][i + 2], e3 = s_list[wid][i + 3];
        float4 v0 = hw4[(size_t)__float_as_int(e0.x) * 32 + lane];
        float4 v1 = hw4[(size_t)__float_as_int(e1.x) * 32 + lane];
        float4 v2 = hw4[(size_t)__float_as_int(e2.x) * 32 + lane];
        float4 v3 = hw4[(size_t)__float_as_int(e3.x) * 32 + lane];
        acc.x += e0.y * v0.x; acc.y += e0.y * v0.y; acc.z += e0.y * v0.z; acc.w += e0.y * v0.w;
        acc.x += e1.y * v1.x; acc.y += e1.y * v1.y; acc.z += e1.y * v1.z; acc.w += e1.y * v1.w;
        acc.x += e2.y * v2.x; acc.y += e2.y * v2.y; acc.z += e2.y * v2.z; acc.w += e2.y * v2.w;
        acc.x += e3.y * v3.x; acc.y += e3.y * v3.y; acc.z += e3.y * v3.z; acc.w += e3.y * v3.w;
    }
    for (; i < n; i++) {
        float2 e0 = s_list[wid][i];
        float4 v0 = hw4[(size_t)__float_as_int(e0.x) * 32 + lane];
        acc.x += e0.y * v0.x; acc.y += e0.y * v0.y; acc.z += e0.y * v0.z; acc.w += e0.y * v0.w;
    }
    ((float4*)(g_cluster + (size_t)p * D_IN))[lane] = acc;
}

// ---------------------------------------------------------------------------
// fused MLP, bf16-split, 32 rows/block, fragment-packed B operands
// ---------------------------------------------------------------------------
#define R1OFF 0
#define R2OFF 8704
#define R3OFF 25600
#define GATEOFF 42496
#define LO128 (32 * PB128)
#define LO256 (32 * PB256)

__global__ __launch_bounds__(256, 2) void mlp2_kernel(
    const float* __restrict__ feat,
    const float* __restrict__ bself, const float* __restrict__ bclu,
    const float* __restrict__ bf1,   const float* __restrict__ bf2,
    const float* __restrict__ Wf3,   const float* __restrict__ bf3,
    float* __restrict__ out, int nP) {
    extern __shared__ unsigned short s16[];
    unsigned short* r1 = s16 + R1OFF;
    unsigned short* r2 = s16 + R2OFF;
    unsigned short* r3 = s16 + R3OFF;
    float (*s_gate)[2] = (float (*)[2])(s16 + GATEOFF);
    float* s_x2 = (float*)r2;

    int row0 = blockIdx.x * 32;
    int t = threadIdx.x;
    int wid = t >> 5, lane = t & 31;

    load_tile_planes(r1, PB128, LO128, (const float4*)feat, row0, nP, t);
    load_tile_planes(r2, PB256, LO256, (const float4*)g_cluster, row0, nP, t);
    __syncthreads();

    int m8 = lane >> 3, rIn = lane & 7;
    int rowoff = (m8 & 1) * 8 + rIn;
    int colByte = (m8 >> 1) * 16;
    int gid = lane >> 2, tig = lane & 3;

    // stage A: self_f | clu_f  (wb = wid&3, KT=8, NT=4)
    {
        float acc[2][4][4];
#pragma unroll
        for (int a = 0; a < 2; a++)
#pragma unroll
            for (int b = 0; b < 4; b++)
#pragma unroll
                for (int c = 0; c < 4; c++) acc[a][b][c] = 0.f;

        unsigned short* aBuf = (wid < 4) ? r1 : r2;
        int aStr             = (wid < 4) ? PB128 : PB256;
        unsigned loOff       = (wid < 4) ? (LO128 * 2) : (LO256 * 2);
        int wOff             = (wid < 4) ? OFF_WSELF : OFF_WCLU;
        const float* bias    = (wid < 4) ? bself : bclu;
        int ncol0            = (wid & 3) * 32;
        int outcol0          = (wid < 4) ? ncol0 : (128 + ncol0);

        unsigned aAddr[2];
#pragma unroll
        for (int mt = 0; mt < 2; mt++)
            aAddr[mt] = smem_u32(aBuf + (mt * 16 + rowoff) * aStr) + colByte;

        size_t fidx = ((size_t)((wid & 3) * 8) * 32 + lane) * 2;
        const uint4* Bhi = (const uint4*)(g_Whi + wOff) + fidx;
        const uint4* Blo = (const uint4*)(g_Wlo + wOff) + fidx;
        gemm_bf16<8, 4, 2>(aAddr, loOff, Bhi, Blo, acc);
        __syncthreads();
        epilogue_bf16<4, 2, false>(r3, PB256, LO256, outcol0, bias + ncol0, acc, lane);
    }
    __syncthreads();

    // stage B: x1 = relu(cat @ Wf1 + bf1)  (wb = wid, KT=16, NT=4)
    {
        float acc[2][4][4];
#pragma unroll
        for (int a = 0; a < 2; a++)
#pragma unroll
            for (int b = 0; b < 4; b++)
#pragma unroll
                for (int c = 0; c < 4; c++) acc[a][b][c] = 0.f;

        int ncol0 = wid * 32;
        unsigned aAddr[2];
#pragma unroll
        for (int mt = 0; mt < 2; mt++)
            aAddr[mt] = smem_u32(r3 + (mt * 16 + rowoff) * PB256) + colByte;
        size_t fidx = ((size_t)(wid * 16) * 32 + lane) * 2;
        const uint4* Bhi = (const uint4*)(g_Whi + OFF_WF1) + fidx;
        const uint4* Blo = (const uint4*)(g_Wlo + OFF_WF1) + fidx;
        gemm_bf16<16, 4, 2>(aAddr, LO256 * 2, Bhi, Blo, acc);
        __syncthreads();
        epilogue_bf16<4, 2, true>(r2, PB256, LO256, ncol0, bf1 + ncol0, acc, lane);
    }
    __syncthreads();

    // stage C: x2 = relu(x1 @ Wf2 + bf2)  (wb = wid, KT=16, NT=2)
    {
        float acc[2][2][4];
#pragma unroll
        for (int a = 0; a < 2; a++)
#pragma unroll
            for (int b = 0; b < 2; b++)
#pragma unroll
                for (int c = 0; c < 4; c++) acc[a][b][c] = 0.f;

        int ncol0 = wid * 16;
        unsigned aAddr[2];
#pragma unroll
        for (int mt = 0; mt < 2; mt++)
            aAddr[mt] = smem_u32(r2 + (mt * 16 + rowoff) * PB256) + colByte;
        size_t fidx = ((size_t)(wid * 16) * 32 + lane) * 1;
        const uint4* Bhi = (const uint4*)(g_Whi + OFF_WF2) + fidx;
        const uint4* Blo = (const uint4*)(g_Wlo + OFF_WF2) + fidx;
        gemm_bf16<16, 2, 2>(aAddr, LO256 * 2, Bhi, Blo, acc);
        __syncthreads();
        epilogue_f32<2, 2, true>(s_x2, 132, ncol0, bf2 + ncol0, acc, lane);
    }
    __syncthreads();

    // stage D: logits + softmax gates
    if (t < 64) {
        int r = t >> 1, l = t & 1;
        float a = __ldg(bf3 + l);
        const float* x = s_x2 + (size_t)r * 132;
#pragma unroll 4
        for (int k = 0; k < 128; k++)
            a += x[k] * __ldg(Wf3 + 2 * k + l);
        s_gate[r][l] = a;
    }
    __syncthreads();
    if (t < 32) {
        float a = s_gate[t][0], b = s_gate[t][1];
        float m = fmaxf(a, b);
        float e0 = expf(a - m), e1 = expf(b - m);
        float inv = 1.f / (e0 + e1);
        s_gate[t][0] = e0 * inv;
        s_gate[t][1] = e1 * inv;
    }
    __syncthreads();

    // stage E
    const float4* feat4 = (const float4*)feat;
    for (int i = t; i < 32 * 32; i += 256) {
        int r = i >> 5, c4 = i & 31;
        int gr = row0 + r;
        if (gr < nP) {
            float4 f = feat4[(size_t)gr * 32 + c4];
            float g0 = s_gate[r][0], g1 = s_gate[r][1];
            int c0 = c4 * 4;
            ushort4 hs = *(const ushort4*)&r3[r * PB256 + c0];
            ushort4 ls = *(const ushort4*)&r3[LO256 + r * PB256 + c0];
            ushort4 hc = *(const ushort4*)&r3[r * PB256 + c0 + 128];
            ushort4 lc = *(const ushort4*)&r3[LO256 + r * PB256 + c0 + 128];
            float4 o;
            o.x = fmaxf((bfu(hs.x) + bfu(ls.x)) * g0 + (bfu(hc.x) + bfu(lc.x)) * g1 + f.x, 0.f);
            o.y = fmaxf((bfu(hs.y) + bfu(ls.y)) * g0 + (bfu(hc.y) + bfu(lc.y)) * g1 + f.y, 0.f);
            o.z = fmaxf((bfu(hs.z) + bfu(ls.z)) * g0 + (bfu(hc.z) + bfu(lc.z)) * g1 + f.z, 0.f);
            o.w = fmaxf((bfu(hs.w) + bfu(ls.w)) * g0 + (bfu(hc.w) + bfu(lc.w)) * g1 + f.w, 0.f);
            ((float4*)out)[(size_t)gr * 32 + c4] = o;
        }
    }
}

// ---------------------------------------------------------------------------
extern "C" void kernel_launch(void* const* d_in, const int* in_sizes, int n_in,
                              void* d_out, int out_size) {
    const float* feat   = (const float*)d_in[0];
    const float* edge_w = (const float*)d_in[1];
    const float* Wself  = (const float*)d_in[2];
    const float* bself  = (const float*)d_in[3];
    const float* Wclu   = (const float*)d_in[4];
    const float* bclu   = (const float*)d_in[5];
    const float* Wh1    = (const float*)d_in[6];
    const float* bh1    = (const float*)d_in[7];
    const float* Wh2    = (const float*)d_in[8];
    const float* bh2    = (const float*)d_in[9];
    const float* Wfuse  = (const float*)d_in[10];
    const float* Wf1    = (const float*)d_in[11];
    const float* bf1    = (const float*)d_in[12];
    const float* Wf2    = (const float*)d_in[13];
    const float* bf2    = (const float*)d_in[14];
    const float* Wf3    = (const float*)d_in[15];
    const float* bf3    = (const float*)d_in[16];
    const int*   e_pid  = (const int*)d_in[17];
    const int*   e_hid  = (const int*)d_in[18];

    int nE = in_sizes[17];
    int nP = in_sizes[0] / D_IN;
    float* out = (float*)d_out;

    int zpN = N_HE * (D_IN / 4);   // 160000 covers PACK_TOTAL and counters
    zero_pack_kernel<<<(zpN + 255) / 256, 256>>>(Wself, Wclu, Wf1, Wf2, Wh1);

    fill_kernel<<<(nE + 255) / 256, 256>>>(edge_w, e_pid, e_hid, feat, nE);

    zero_cluster_kernel<<<(N_P * (D_IN / 4) + 255) / 256, 256>>>();

    he_acc_kernel<<<N_HE / 4, 256>>>(feat);

    attn_gemm_kernel<<<(N_HE + 31) / 32, 256>>>(bh1, Wh2, bh2, Wfuse);

    ovf_kernel<<<32, 256>>>();

    p_acc_kernel<<<(nP + 7) / 8, 256>>>(nP);

    size_t smemBytes = (size_t)GATEOFF * 2 + 32 * 2 * sizeof(float);
    cudaFuncSetAttribute(mlp2_kernel, cudaFuncAttributeMaxDynamicSharedMemorySize,
                         (int)smemBytes);
    int nBlocks = (nP + 31) / 32;
    mlp2_kernel<<<nBlocks, 256, smemBytes>>>(feat, bself, bclu, bf1, bf2,
                                             Wf3, bf3, out, nP);
}